// round 3
// baseline (speedup 1.0000x reference)
#include <cuda_runtime.h>
#include <cuda_bf16.h>
#include <cstdint>
#include <cstddef>

#define D_MODEL 1024
#define N_HEADS 16
#define DKH     64
#define D_FF    4096
#define BB      2
#define TT      2048
#define MROWS   (BB * TT)   // 4096

// ---------------- scratch (device globals; no runtime allocation) -----------
__device__ float g_Q   [MROWS * D_MODEL];
__device__ float g_K   [MROWS * D_MODEL];
__device__ float g_V   [MROWS * D_MODEL];
__device__ float g_attn[MROWS * D_MODEL];
__device__ float g_x1  [MROWS * D_MODEL];
__device__ float g_x2  [MROWS * D_MODEL];
__device__ float g_tmp [MROWS * D_MODEL];
__device__ float g_ffn [MROWS * D_FF];

// ---------------- SGEMM: C[M,N] = A[M,K] @ B[K,N] + bias[N] -----------------
// HEADB: B is stored as [H, K, 64] (per-head stacked weights); logical column
//        j maps to element B[(j>>6)*K*64 + k*64 + (j&63)].
// RELU : apply max(0, x) in epilogue.
#define BM 128
#define BN 128
#define BKK 8

template<bool HEADB, bool RELU>
__global__ __launch_bounds__(256) void sgemm_kernel(
    int M, int N, int K,
    const float* __restrict__ A, const float* __restrict__ B,
    const float* __restrict__ bias, float* __restrict__ C)
{
    __shared__ float As[BKK][BM];
    __shared__ float Bs[BKK][BN];

    const int tid = threadIdx.x;
    const int tx  = tid & 15;    // 0..15
    const int ty  = tid >> 4;    // 0..15
    const int blockRow = blockIdx.y * BM;
    const int blockCol = blockIdx.x * BN;

    // cooperative load indices
    const int aRow = tid >> 1;          // 0..127
    const int aCol = (tid & 1) * 4;     // 0 or 4
    const int bRow = tid >> 5;          // 0..7
    const int bCol = (tid & 31) * 4;    // 0..124

    const float* Aptr = A + (size_t)(blockRow + aRow) * K;

    float acc[8][8];
#pragma unroll
    for (int i = 0; i < 8; i++)
#pragma unroll
        for (int j = 0; j < 8; j++) acc[i][j] = 0.f;

    for (int k0 = 0; k0 < K; k0 += BKK) {
        // load A tile (transposed into As[k][m])
        float4 a4 = *(const float4*)(Aptr + k0 + aCol);
        As[aCol + 0][aRow] = a4.x;
        As[aCol + 1][aRow] = a4.y;
        As[aCol + 2][aRow] = a4.z;
        As[aCol + 3][aRow] = a4.w;

        // load B tile
        const int j = blockCol + bCol;
        float4 b4;
        if (HEADB) {
            const size_t off = (size_t)(j >> 6) * ((size_t)K * 64)
                             + (size_t)(k0 + bRow) * 64 + (j & 63);
            b4 = *(const float4*)(B + off);
        } else {
            b4 = *(const float4*)(B + (size_t)(k0 + bRow) * N + j);
        }
        *(float4*)&Bs[bRow][bCol] = b4;
        __syncthreads();

#pragma unroll
        for (int kk = 0; kk < BKK; kk++) {
            float4 a0 = *(const float4*)&As[kk][ty * 4];
            float4 a1 = *(const float4*)&As[kk][ty * 4 + 64];
            float4 b0 = *(const float4*)&Bs[kk][tx * 4];
            float4 b1 = *(const float4*)&Bs[kk][tx * 4 + 64];
            float ra[8] = {a0.x, a0.y, a0.z, a0.w, a1.x, a1.y, a1.z, a1.w};
            float rb[8] = {b0.x, b0.y, b0.z, b0.w, b1.x, b1.y, b1.z, b1.w};
#pragma unroll
            for (int i = 0; i < 8; i++)
#pragma unroll
                for (int jj = 0; jj < 8; jj++)
                    acc[i][jj] = fmaf(ra[i], rb[jj], acc[i][jj]);
        }
        __syncthreads();
    }

    // epilogue: +bias, optional relu, float4 stores
    float4 bia0 = *(const float4*)(bias + blockCol + tx * 4);
    float4 bia1 = *(const float4*)(bias + blockCol + tx * 4 + 64);
#pragma unroll
    for (int i = 0; i < 8; i++) {
        const int r = blockRow + ((i < 4) ? (ty * 4 + i) : (64 + ty * 4 + (i - 4)));
        float4 o0, o1;
        o0.x = acc[i][0] + bia0.x; o0.y = acc[i][1] + bia0.y;
        o0.z = acc[i][2] + bia0.z; o0.w = acc[i][3] + bia0.w;
        o1.x = acc[i][4] + bia1.x; o1.y = acc[i][5] + bia1.y;
        o1.z = acc[i][6] + bia1.z; o1.w = acc[i][7] + bia1.w;
        if (RELU) {
            o0.x = fmaxf(o0.x, 0.f); o0.y = fmaxf(o0.y, 0.f);
            o0.z = fmaxf(o0.z, 0.f); o0.w = fmaxf(o0.w, 0.f);
            o1.x = fmaxf(o1.x, 0.f); o1.y = fmaxf(o1.y, 0.f);
            o1.z = fmaxf(o1.z, 0.f); o1.w = fmaxf(o1.w, 0.f);
        }
        float* crow = C + (size_t)r * N + blockCol + tx * 4;
        *(float4*)crow        = o0;
        *(float4*)(crow + 64) = o1;
    }
}

// ---------------- attention (flash-style, one thread per query row) ---------
// Q,K,V,O layouts: [B, T, H*64] row-major (head h occupies cols h*64..h*64+63).
// grid: (T/128, H, B); block: 128 threads; K/V streamed in 64-row SMEM tiles.
template<bool CAUSAL>
__global__ __launch_bounds__(128) void attn_kernel(
    const float* __restrict__ Q, const float* __restrict__ K,
    const float* __restrict__ V, float* __restrict__ O, int T)
{
    __shared__ float4 Ks[64][16];
    __shared__ float4 Vs[64][16];

    const int h = blockIdx.y;
    const int b = blockIdx.z;
    const int t = blockIdx.x * 128 + threadIdx.x;

    const float* qp = Q + ((size_t)(b * T + t) * N_HEADS + h) * DKH;
    float4 q[16];
#pragma unroll
    for (int i = 0; i < 16; i++) q[i] = ((const float4*)qp)[i];

    float4 acc[16];
#pragma unroll
    for (int i = 0; i < 16; i++) acc[i] = make_float4(0.f, 0.f, 0.f, 0.f);
    float mval = -1e30f, lsum = 0.f;

    const int sEnd = CAUSAL ? (blockIdx.x * 128 + 128) : T;  // tile cap
    for (int s0 = 0; s0 < sEnd; s0 += 64) {
        // cooperatively load 64x64 K and V tiles
        for (int i = threadIdx.x; i < 64 * 16; i += 128) {
            const int r = i >> 4, c = i & 15;
            const size_t g = ((size_t)(b * T + s0 + r) * N_HEADS + h) * DKH;
            Ks[r][c] = ((const float4*)(K + g))[c];
            Vs[r][c] = ((const float4*)(V + g))[c];
        }
        __syncthreads();

        const int sMax = CAUSAL ? min(64, t - s0 + 1) : 64;
        for (int s = 0; s < sMax; s++) {
            float sc = 0.f;
#pragma unroll
            for (int i = 0; i < 16; i++) {
                float4 kk = Ks[s][i];
                sc = fmaf(q[i].x, kk.x, sc);
                sc = fmaf(q[i].y, kk.y, sc);
                sc = fmaf(q[i].z, kk.z, sc);
                sc = fmaf(q[i].w, kk.w, sc);
            }
            sc *= 0.125f;  // 1/sqrt(64)
            if (sc > mval) {
                const float cr = __expf(mval - sc);
                mval = sc;
                lsum *= cr;
#pragma unroll
                for (int i = 0; i < 16; i++) {
                    acc[i].x *= cr; acc[i].y *= cr;
                    acc[i].z *= cr; acc[i].w *= cr;
                }
            }
            const float p = __expf(sc - mval);
            lsum += p;
#pragma unroll
            for (int i = 0; i < 16; i++) {
                float4 vv = Vs[s][i];
                acc[i].x = fmaf(p, vv.x, acc[i].x);
                acc[i].y = fmaf(p, vv.y, acc[i].y);
                acc[i].z = fmaf(p, vv.z, acc[i].z);
                acc[i].w = fmaf(p, vv.w, acc[i].w);
            }
        }
        __syncthreads();
    }

    const float inv = 1.f / lsum;
    float4* op = (float4*)(O + ((size_t)(b * T + t) * N_HEADS + h) * DKH);
#pragma unroll
    for (int i = 0; i < 16; i++) {
        float4 o;
        o.x = acc[i].x * inv; o.y = acc[i].y * inv;
        o.z = acc[i].z * inv; o.w = acc[i].w * inv;
        op[i] = o;
    }
}

// ---------------- residual add + LayerNorm (row-wise, D=1024) ---------------
__inline__ __device__ float warpSum(float v) {
#pragma unroll
    for (int o = 16; o > 0; o >>= 1) v += __shfl_xor_sync(0xffffffffu, v, o);
    return v;
}

__global__ __launch_bounds__(256) void add_ln_kernel(
    const float* __restrict__ res, const float* __restrict__ y,
    const float* __restrict__ gamma, const float* __restrict__ beta,
    float* __restrict__ out)
{
    const int row = blockIdx.x;
    const int i = threadIdx.x;  // each thread owns one float4 (1024/256*4)
    const float4 a  = ((const float4*)(res + (size_t)row * D_MODEL))[i];
    const float4 b4 = ((const float4*)(y   + (size_t)row * D_MODEL))[i];
    const float x0 = a.x + b4.x, x1 = a.y + b4.y, x2 = a.z + b4.z, x3 = a.w + b4.w;

    float s  = x0 + x1 + x2 + x3;
    float sq = x0 * x0 + x1 * x1 + x2 * x2 + x3 * x3;
    s = warpSum(s); sq = warpSum(sq);

    __shared__ float sh[2][8];
    const int w = threadIdx.x >> 5, l = threadIdx.x & 31;
    if (l == 0) { sh[0][w] = s; sh[1][w] = sq; }
    __syncthreads();
    if (threadIdx.x < 32) {
        float aa = (l < 8) ? sh[0][l] : 0.f;
        float bb = (l < 8) ? sh[1][l] : 0.f;
        aa = warpSum(aa); bb = warpSum(bb);
        if (l == 0) { sh[0][0] = aa; sh[1][0] = bb; }
    }
    __syncthreads();
    const float mean = sh[0][0] * (1.f / D_MODEL);
    const float var  = sh[1][0] * (1.f / D_MODEL) - mean * mean;
    const float rinv = rsqrtf(var + 1e-5f);

    const float4 g  = ((const float4*)gamma)[i];
    const float4 be = ((const float4*)beta)[i];
    float4 o;
    o.x = (x0 - mean) * rinv * g.x + be.x;
    o.y = (x1 - mean) * rinv * g.y + be.y;
    o.z = (x2 - mean) * rinv * g.z + be.z;
    o.w = (x3 - mean) * rinv * g.w + be.w;
    ((float4*)(out + (size_t)row * D_MODEL))[i] = o;
}

// ---------------- launch --------------------------------------------------
extern "C" void kernel_launch(void* const* d_in, const int* in_sizes, int n_in,
                              void* d_out, int out_size)
{
    const float* dec  = (const float*)d_in[0];
    const float* enc  = (const float*)d_in[1];
    const float* Wq_s = (const float*)d_in[2];
    const float* bq_s = (const float*)d_in[3];
    const float* Wk_s = (const float*)d_in[4];
    const float* bk_s = (const float*)d_in[5];
    const float* Wv_s = (const float*)d_in[6];
    const float* bv_s = (const float*)d_in[7];
    const float* Wo_s = (const float*)d_in[8];
    const float* bo_s = (const float*)d_in[9];
    const float* Wq_c = (const float*)d_in[10];
    const float* bq_c = (const float*)d_in[11];
    const float* Wk_c = (const float*)d_in[12];
    const float* bk_c = (const float*)d_in[13];
    const float* Wv_c = (const float*)d_in[14];
    const float* bv_c = (const float*)d_in[15];
    const float* Wo_c = (const float*)d_in[16];
    const float* bo_c = (const float*)d_in[17];
    const float* W1   = (const float*)d_in[18];
    const float* b1   = (const float*)d_in[19];
    const float* W2   = (const float*)d_in[20];
    const float* b2   = (const float*)d_in[21];
    const float* g1   = (const float*)d_in[22];
    const float* be1  = (const float*)d_in[23];
    const float* g2   = (const float*)d_in[24];
    const float* be2  = (const float*)d_in[25];
    const float* g3   = (const float*)d_in[26];
    const float* be3  = (const float*)d_in[27];

    float *Qb, *Kb, *Vb, *At, *X1, *X2, *Tm, *Ff;
    cudaGetSymbolAddress((void**)&Qb, g_Q);
    cudaGetSymbolAddress((void**)&Kb, g_K);
    cudaGetSymbolAddress((void**)&Vb, g_V);
    cudaGetSymbolAddress((void**)&At, g_attn);
    cudaGetSymbolAddress((void**)&X1, g_x1);
    cudaGetSymbolAddress((void**)&X2, g_x2);
    cudaGetSymbolAddress((void**)&Tm, g_tmp);
    cudaGetSymbolAddress((void**)&Ff, g_ffn);

    const dim3 gD(D_MODEL / BN, MROWS / BM);   // (8, 32)
    const dim3 gF(D_FF / BN,   MROWS / BM);    // (32, 32)
    const dim3 gA(TT / 128, N_HEADS, BB);      // (16, 16, 2)

    // ---- self-attention block ----
    sgemm_kernel<true,  false><<<gD, 256>>>(MROWS, D_MODEL, D_MODEL, dec, Wq_s, bq_s, Qb);
    sgemm_kernel<true,  false><<<gD, 256>>>(MROWS, D_MODEL, D_MODEL, dec, Wk_s, bk_s, Kb);
    sgemm_kernel<true,  false><<<gD, 256>>>(MROWS, D_MODEL, D_MODEL, dec, Wv_s, bv_s, Vb);
    attn_kernel<true><<<gA, 128>>>(Qb, Kb, Vb, At, TT);
    sgemm_kernel<false, false><<<gD, 256>>>(MROWS, D_MODEL, D_MODEL, At, Wo_s, bo_s, Tm);
    add_ln_kernel<<<MROWS, 256>>>(dec, Tm, g1, be1, X1);

    // ---- cross-attention block ----
    sgemm_kernel<true,  false><<<gD, 256>>>(MROWS, D_MODEL, D_MODEL, X1,  Wq_c, bq_c, Qb);
    sgemm_kernel<true,  false><<<gD, 256>>>(MROWS, D_MODEL, D_MODEL, enc, Wk_c, bk_c, Kb);
    sgemm_kernel<true,  false><<<gD, 256>>>(MROWS, D_MODEL, D_MODEL, enc, Wv_c, bv_c, Vb);
    attn_kernel<false><<<gA, 128>>>(Qb, Kb, Vb, At, TT);
    sgemm_kernel<false, false><<<gD, 256>>>(MROWS, D_MODEL, D_MODEL, At, Wo_c, bo_c, Tm);
    add_ln_kernel<<<MROWS, 256>>>(X1, Tm, g2, be2, X2);

    // ---- FFN block ----
    sgemm_kernel<false, true ><<<gF, 256>>>(MROWS, D_FF,    D_MODEL, X2, W1, b1, Ff);
    sgemm_kernel<false, false><<<gD, 256>>>(MROWS, D_MODEL, D_FF,    Ff, W2, b2, Tm);
    add_ln_kernel<<<MROWS, 256>>>(X2, Tm, g3, be3, (float*)d_out);
}

// round 4
// speedup vs baseline: 1.0032x; 1.0032x over previous
#include <cuda_runtime.h>
#include <cuda_bf16.h>
#include <cstdint>
#include <cstddef>

#define D_MODEL 1024
#define N_HEADS 16
#define DKH     64
#define D_FF    4096
#define BB      2
#define TT      2048
#define MROWS   (BB * TT)   // 4096

// ---------------- scratch (device globals; no runtime allocation) -----------
__device__ float g_Q   [MROWS * D_MODEL];
__device__ float g_K   [MROWS * D_MODEL];
__device__ float g_V   [MROWS * D_MODEL];
__device__ float g_attn[MROWS * D_MODEL];
__device__ float g_x1  [MROWS * D_MODEL];
__device__ float g_x2  [MROWS * D_MODEL];
__device__ float g_tmp [MROWS * D_MODEL];
__device__ float g_ffn [MROWS * D_FF];

// ---------------- SGEMM: C[M,N] = A[M,K] @ B[K,N] + bias[N] -----------------
// HEADB: B is stored as [H, K, 64] (per-head stacked weights); logical column
//        j maps to element B[(j>>6)*K*64 + k*64 + (j&63)].
// RELU : apply max(0, x) in epilogue.
#define BM 128
#define BN 128
#define BKK 8

template<bool HEADB, bool RELU>
__global__ __launch_bounds__(256) void sgemm_kernel(
    int M, int N, int K,
    const float* __restrict__ A, const float* __restrict__ B,
    const float* __restrict__ bias, float* __restrict__ C)
{
    __shared__ float As[BKK][BM];
    __shared__ float Bs[BKK][BN];

    const int tid = threadIdx.x;
    const int tx  = tid & 15;    // 0..15
    const int ty  = tid >> 4;    // 0..15
    const int blockRow = blockIdx.y * BM;
    const int blockCol = blockIdx.x * BN;

    // cooperative load indices
    const int aRow = tid >> 1;          // 0..127
    const int aCol = (tid & 1) * 4;     // 0 or 4
    const int bRow = tid >> 5;          // 0..7
    const int bCol = (tid & 31) * 4;    // 0..124

    const float* Aptr = A + (size_t)(blockRow + aRow) * K;

    float acc[8][8];
#pragma unroll
    for (int i = 0; i < 8; i++)
#pragma unroll
        for (int j = 0; j < 8; j++) acc[i][j] = 0.f;

    for (int k0 = 0; k0 < K; k0 += BKK) {
        // load A tile (transposed into As[k][m])
        float4 a4 = *(const float4*)(Aptr + k0 + aCol);
        As[aCol + 0][aRow] = a4.x;
        As[aCol + 1][aRow] = a4.y;
        As[aCol + 2][aRow] = a4.z;
        As[aCol + 3][aRow] = a4.w;

        // load B tile
        const int j = blockCol + bCol;
        float4 b4;
        if (HEADB) {
            const size_t off = (size_t)(j >> 6) * ((size_t)K * 64)
                             + (size_t)(k0 + bRow) * 64 + (j & 63);
            b4 = *(const float4*)(B + off);
        } else {
            b4 = *(const float4*)(B + (size_t)(k0 + bRow) * N + j);
        }
        *(float4*)&Bs[bRow][bCol] = b4;
        __syncthreads();

#pragma unroll
        for (int kk = 0; kk < BKK; kk++) {
            float4 a0 = *(const float4*)&As[kk][ty * 4];
            float4 a1 = *(const float4*)&As[kk][ty * 4 + 64];
            float4 b0 = *(const float4*)&Bs[kk][tx * 4];
            float4 b1 = *(const float4*)&Bs[kk][tx * 4 + 64];
            float ra[8] = {a0.x, a0.y, a0.z, a0.w, a1.x, a1.y, a1.z, a1.w};
            float rb[8] = {b0.x, b0.y, b0.z, b0.w, b1.x, b1.y, b1.z, b1.w};
#pragma unroll
            for (int i = 0; i < 8; i++)
#pragma unroll
                for (int jj = 0; jj < 8; jj++)
                    acc[i][jj] = fmaf(ra[i], rb[jj], acc[i][jj]);
        }
        __syncthreads();
    }

    // epilogue: +bias, optional relu, float4 stores
    float4 bia0 = *(const float4*)(bias + blockCol + tx * 4);
    float4 bia1 = *(const float4*)(bias + blockCol + tx * 4 + 64);
#pragma unroll
    for (int i = 0; i < 8; i++) {
        const int r = blockRow + ((i < 4) ? (ty * 4 + i) : (64 + ty * 4 + (i - 4)));
        float4 o0, o1;
        o0.x = acc[i][0] + bia0.x; o0.y = acc[i][1] + bia0.y;
        o0.z = acc[i][2] + bia0.z; o0.w = acc[i][3] + bia0.w;
        o1.x = acc[i][4] + bia1.x; o1.y = acc[i][5] + bia1.y;
        o1.z = acc[i][6] + bia1.z; o1.w = acc[i][7] + bia1.w;
        if (RELU) {
            o0.x = fmaxf(o0.x, 0.f); o0.y = fmaxf(o0.y, 0.f);
            o0.z = fmaxf(o0.z, 0.f); o0.w = fmaxf(o0.w, 0.f);
            o1.x = fmaxf(o1.x, 0.f); o1.y = fmaxf(o1.y, 0.f);
            o1.z = fmaxf(o1.z, 0.f); o1.w = fmaxf(o1.w, 0.f);
        }
        float* crow = C + (size_t)r * N + blockCol + tx * 4;
        *(float4*)crow        = o0;
        *(float4*)(crow + 64) = o1;
    }
}

// ---------------- attention (flash-style, one thread per query row) ---------
// Q,K,V,O layouts: [B, T, H*64] row-major (head h occupies cols h*64..h*64+63).
// grid: (T/128, H, B); block: 128 threads; K/V streamed in 64-row SMEM tiles.
template<bool CAUSAL>
__global__ __launch_bounds__(128) void attn_kernel(
    const float* __restrict__ Q, const float* __restrict__ K,
    const float* __restrict__ V, float* __restrict__ O, int T)
{
    __shared__ float4 Ks[64][16];
    __shared__ float4 Vs[64][16];

    const int h = blockIdx.y;
    const int b = blockIdx.z;
    const int t = blockIdx.x * 128 + threadIdx.x;

    const float* qp = Q + ((size_t)(b * T + t) * N_HEADS + h) * DKH;
    float4 q[16];
#pragma unroll
    for (int i = 0; i < 16; i++) q[i] = ((const float4*)qp)[i];

    float4 acc[16];
#pragma unroll
    for (int i = 0; i < 16; i++) acc[i] = make_float4(0.f, 0.f, 0.f, 0.f);
    float mval = -1e30f, lsum = 0.f;

    const int sEnd = CAUSAL ? (blockIdx.x * 128 + 128) : T;  // tile cap
    for (int s0 = 0; s0 < sEnd; s0 += 64) {
        // cooperatively load 64x64 K and V tiles
        for (int i = threadIdx.x; i < 64 * 16; i += 128) {
            const int r = i >> 4, c = i & 15;
            const size_t g = ((size_t)(b * T + s0 + r) * N_HEADS + h) * DKH;
            Ks[r][c] = ((const float4*)(K + g))[c];
            Vs[r][c] = ((const float4*)(V + g))[c];
        }
        __syncthreads();

        const int sMax = CAUSAL ? min(64, t - s0 + 1) : 64;
        for (int s = 0; s < sMax; s++) {
            float sc = 0.f;
#pragma unroll
            for (int i = 0; i < 16; i++) {
                float4 kk = Ks[s][i];
                sc = fmaf(q[i].x, kk.x, sc);
                sc = fmaf(q[i].y, kk.y, sc);
                sc = fmaf(q[i].z, kk.z, sc);
                sc = fmaf(q[i].w, kk.w, sc);
            }
            sc *= 0.125f;  // 1/sqrt(64)
            if (sc > mval) {
                const float cr = __expf(mval - sc);
                mval = sc;
                lsum *= cr;
#pragma unroll
                for (int i = 0; i < 16; i++) {
                    acc[i].x *= cr; acc[i].y *= cr;
                    acc[i].z *= cr; acc[i].w *= cr;
                }
            }
            const float p = __expf(sc - mval);
            lsum += p;
#pragma unroll
            for (int i = 0; i < 16; i++) {
                float4 vv = Vs[s][i];
                acc[i].x = fmaf(p, vv.x, acc[i].x);
                acc[i].y = fmaf(p, vv.y, acc[i].y);
                acc[i].z = fmaf(p, vv.z, acc[i].z);
                acc[i].w = fmaf(p, vv.w, acc[i].w);
            }
        }
        __syncthreads();
    }

    const float inv = 1.f / lsum;
    float4* op = (float4*)(O + ((size_t)(b * T + t) * N_HEADS + h) * DKH);
#pragma unroll
    for (int i = 0; i < 16; i++) {
        float4 o;
        o.x = acc[i].x * inv; o.y = acc[i].y * inv;
        o.z = acc[i].z * inv; o.w = acc[i].w * inv;
        op[i] = o;
    }
}

// ---------------- residual add + LayerNorm (row-wise, D=1024) ---------------
__inline__ __device__ float warpSum(float v) {
#pragma unroll
    for (int o = 16; o > 0; o >>= 1) v += __shfl_xor_sync(0xffffffffu, v, o);
    return v;
}

__global__ __launch_bounds__(256) void add_ln_kernel(
    const float* __restrict__ res, const float* __restrict__ y,
    const float* __restrict__ gamma, const float* __restrict__ beta,
    float* __restrict__ out)
{
    const int row = blockIdx.x;
    const int i = threadIdx.x;  // each thread owns one float4 (1024/256*4)
    const float4 a  = ((const float4*)(res + (size_t)row * D_MODEL))[i];
    const float4 b4 = ((const float4*)(y   + (size_t)row * D_MODEL))[i];
    const float x0 = a.x + b4.x, x1 = a.y + b4.y, x2 = a.z + b4.z, x3 = a.w + b4.w;

    float s  = x0 + x1 + x2 + x3;
    float sq = x0 * x0 + x1 * x1 + x2 * x2 + x3 * x3;
    s = warpSum(s); sq = warpSum(sq);

    __shared__ float sh[2][8];
    const int w = threadIdx.x >> 5, l = threadIdx.x & 31;
    if (l == 0) { sh[0][w] = s; sh[1][w] = sq; }
    __syncthreads();
    if (threadIdx.x < 32) {
        float aa = (l < 8) ? sh[0][l] : 0.f;
        float bb = (l < 8) ? sh[1][l] : 0.f;
        aa = warpSum(aa); bb = warpSum(bb);
        if (l == 0) { sh[0][0] = aa; sh[1][0] = bb; }
    }
    __syncthreads();
    const float mean = sh[0][0] * (1.f / D_MODEL);
    const float var  = sh[1][0] * (1.f / D_MODEL) - mean * mean;
    const float rinv = rsqrtf(var + 1e-5f);

    const float4 g  = ((const float4*)gamma)[i];
    const float4 be = ((const float4*)beta)[i];
    float4 o;
    o.x = (x0 - mean) * rinv * g.x + be.x;
    o.y = (x1 - mean) * rinv * g.y + be.y;
    o.z = (x2 - mean) * rinv * g.z + be.z;
    o.w = (x3 - mean) * rinv * g.w + be.w;
    ((float4*)(out + (size_t)row * D_MODEL))[i] = o;
}

// ---------------- launch --------------------------------------------------
extern "C" void kernel_launch(void* const* d_in, const int* in_sizes, int n_in,
                              void* d_out, int out_size)
{
    const float* dec  = (const float*)d_in[0];
    const float* enc  = (const float*)d_in[1];
    const float* Wq_s = (const float*)d_in[2];
    const float* bq_s = (const float*)d_in[3];
    const float* Wk_s = (const float*)d_in[4];
    const float* bk_s = (const float*)d_in[5];
    const float* Wv_s = (const float*)d_in[6];
    const float* bv_s = (const float*)d_in[7];
    const float* Wo_s = (const float*)d_in[8];
    const float* bo_s = (const float*)d_in[9];
    const float* Wq_c = (const float*)d_in[10];
    const float* bq_c = (const float*)d_in[11];
    const float* Wk_c = (const float*)d_in[12];
    const float* bk_c = (const float*)d_in[13];
    const float* Wv_c = (const float*)d_in[14];
    const float* bv_c = (const float*)d_in[15];
    const float* Wo_c = (const float*)d_in[16];
    const float* bo_c = (const float*)d_in[17];
    const float* W1   = (const float*)d_in[18];
    const float* b1   = (const float*)d_in[19];
    const float* W2   = (const float*)d_in[20];
    const float* b2   = (const float*)d_in[21];
    const float* g1   = (const float*)d_in[22];
    const float* be1  = (const float*)d_in[23];
    const float* g2   = (const float*)d_in[24];
    const float* be2  = (const float*)d_in[25];
    const float* g3   = (const float*)d_in[26];
    const float* be3  = (const float*)d_in[27];

    float *Qb, *Kb, *Vb, *At, *X1, *X2, *Tm, *Ff;
    cudaGetSymbolAddress((void**)&Qb, g_Q);
    cudaGetSymbolAddress((void**)&Kb, g_K);
    cudaGetSymbolAddress((void**)&Vb, g_V);
    cudaGetSymbolAddress((void**)&At, g_attn);
    cudaGetSymbolAddress((void**)&X1, g_x1);
    cudaGetSymbolAddress((void**)&X2, g_x2);
    cudaGetSymbolAddress((void**)&Tm, g_tmp);
    cudaGetSymbolAddress((void**)&Ff, g_ffn);

    const dim3 gD(D_MODEL / BN, MROWS / BM);   // (8, 32)
    const dim3 gF(D_FF / BN,   MROWS / BM);    // (32, 32)
    const dim3 gA(TT / 128, N_HEADS, BB);      // (16, 16, 2)

    // ---- self-attention block ----
    sgemm_kernel<true,  false><<<gD, 256>>>(MROWS, D_MODEL, D_MODEL, dec, Wq_s, bq_s, Qb);
    sgemm_kernel<true,  false><<<gD, 256>>>(MROWS, D_MODEL, D_MODEL, dec, Wk_s, bk_s, Kb);
    sgemm_kernel<true,  false><<<gD, 256>>>(MROWS, D_MODEL, D_MODEL, dec, Wv_s, bv_s, Vb);
    attn_kernel<true><<<gA, 128>>>(Qb, Kb, Vb, At, TT);
    sgemm_kernel<false, false><<<gD, 256>>>(MROWS, D_MODEL, D_MODEL, At, Wo_s, bo_s, Tm);
    add_ln_kernel<<<MROWS, 256>>>(dec, Tm, g1, be1, X1);

    // ---- cross-attention block ----
    sgemm_kernel<true,  false><<<gD, 256>>>(MROWS, D_MODEL, D_MODEL, X1,  Wq_c, bq_c, Qb);
    sgemm_kernel<true,  false><<<gD, 256>>>(MROWS, D_MODEL, D_MODEL, enc, Wk_c, bk_c, Kb);
    sgemm_kernel<true,  false><<<gD, 256>>>(MROWS, D_MODEL, D_MODEL, enc, Wv_c, bv_c, Vb);
    attn_kernel<false><<<gA, 128>>>(Qb, Kb, Vb, At, TT);
    sgemm_kernel<false, false><<<gD, 256>>>(MROWS, D_MODEL, D_MODEL, At, Wo_c, bo_c, Tm);
    add_ln_kernel<<<MROWS, 256>>>(X1, Tm, g2, be2, X2);

    // ---- FFN block ----
    sgemm_kernel<false, true ><<<gF, 256>>>(MROWS, D_FF,    D_MODEL, X2, W1, b1, Ff);
    sgemm_kernel<false, false><<<gD, 256>>>(MROWS, D_MODEL, D_FF,    Ff, W2, b2, Tm);
    add_ln_kernel<<<MROWS, 256>>>(X2, Tm, g3, be3, (float*)d_out);
}

// round 6
// speedup vs baseline: 1.0509x; 1.0475x over previous
#include <cuda_runtime.h>
#include <cuda_bf16.h>
#include <cstdint>
#include <cstddef>

#define D_MODEL 1024
#define N_HEADS 16
#define DKH     64
#define D_FF    4096
#define BB      2
#define TT      2048
#define MROWS   (BB * TT)   // 4096

// ---------------- scratch (device globals; no runtime allocation) -----------
__device__ float g_Q   [MROWS * D_MODEL];
__device__ float g_K   [MROWS * D_MODEL];
__device__ float g_V   [MROWS * D_MODEL];
__device__ float g_attn[MROWS * D_MODEL];
__device__ float g_x1  [MROWS * D_MODEL];
__device__ float g_x2  [MROWS * D_MODEL];
__device__ float g_tmp [MROWS * D_MODEL];
__device__ float g_ffn [MROWS * D_FF];     // also holds rounded dec/enc early
__device__ float g_Wt  [D_FF * D_MODEL];   // transposed (K-major) weights

// ======================= helpers ============================================
__device__ __forceinline__ float rna_tf32(float x) {
    uint32_t u;
    asm("cvt.rna.tf32.f32 %0, %1;" : "=r"(u) : "f"(x));
    return __uint_as_float(u);
}

__device__ __forceinline__ void cpa8(uint32_t dst, const void* src) {
    asm volatile("cp.async.ca.shared.global [%0], [%1], 8;\n"
                 :: "r"(dst), "l"(src) : "memory");
}
#define CP_COMMIT() asm volatile("cp.async.commit_group;\n" ::: "memory")
#define CP_WAIT(n)  asm volatile("cp.async.wait_group %0;\n" :: "n"(n) : "memory")

__device__ __forceinline__ uint32_t smem_u32(const void* p) {
    uint32_t a;
    asm("{ .reg .u64 t; cvta.to.shared.u64 t, %1; cvt.u32.u64 %0, t; }"
        : "=r"(a) : "l"(p));
    return a;
}

__device__ __forceinline__ void mma8(float* c, const uint32_t* a,
                                     uint32_t b0, uint32_t b1) {
    asm volatile(
        "mma.sync.aligned.m16n8k8.row.col.f32.tf32.tf32.f32 "
        "{%0,%1,%2,%3}, {%4,%5,%6,%7}, {%8,%9}, {%0,%1,%2,%3};"
        : "+f"(c[0]), "+f"(c[1]), "+f"(c[2]), "+f"(c[3])
        : "r"(a[0]), "r"(a[1]), "r"(a[2]), "r"(a[3]), "r"(b0), "r"(b1));
}

// =============== tf32 mma.sync GEMM: C = A[M,K] @ Wt^T + bias ===============
// Wt is K-major: Wt[n][k] = W[k][n]. All GEMM inputs are pre-rounded to tf32.
// Block tile 128x128, 4 warps (2x2), warp tile 64x64, BK=16, 3-stage cp.async.
#define ROWSTR 20                         // floats per SMEM row (conflict-free)
#define STAGEF (2 * 128 * ROWSTR)         // floats per stage (A tile + B tile)
#define NSTAGE 3
#define GSMEMB (NSTAGE * STAGEF * 4)      // 61440 bytes

__global__ __launch_bounds__(128, 1)
void gemm_tc(int M, int N, int K,
             const float* __restrict__ A, const float* __restrict__ Wt,
             const float* __restrict__ bias, float* __restrict__ C,
             int relu, int rnd)
{
    extern __shared__ float sm[];
    const uint32_t* smu = (const uint32_t*)sm;
    const uint32_t sb = smem_u32(sm);

    const int tid = threadIdx.x;
    const int wid = tid >> 5, lid = tid & 31;
    const int g = lid >> 2, tg = lid & 3;
    const int wm = wid >> 1, wn = wid & 1;

    const int bRow = blockIdx.y * 128, bCol = blockIdx.x * 128;
    const float* Ap = A  + (size_t)(bRow + tid) * K;
    const float* Bp = Wt + (size_t)(bCol + tid) * K;
    const int NT = K >> 4;

    float acc[4][8][4];
#pragma unroll
    for (int m = 0; m < 4; m++)
#pragma unroll
        for (int n = 0; n < 8; n++)
#pragma unroll
            for (int x = 0; x < 4; x++) acc[m][n][x] = 0.f;

    // stage loader: tile it -> buffer s
    auto load_stage = [&](int it, int s) {
        const uint32_t ad = sb + (s * STAGEF + tid * ROWSTR) * 4;
        const uint32_t bd = ad + 128 * ROWSTR * 4;
        const float* as = Ap + it * 16;
        const float* bs = Bp + it * 16;
#pragma unroll
        for (int j = 0; j < 8; j++) {
            cpa8(ad + j * 8, as + j * 2);
            cpa8(bd + j * 8, bs + j * 2);
        }
    };

    load_stage(0, 0); CP_COMMIT();
    load_stage(1, 1); CP_COMMIT();

    for (int i = 0; i < NT; i++) {
        CP_WAIT(1);
        __syncthreads();
        const int pre = i + 2;
        if (pre < NT) load_stage(pre, pre % NSTAGE);
        CP_COMMIT();

        const int buf = (i % NSTAGE) * STAGEF;
#pragma unroll
        for (int ks = 0; ks < 2; ks++) {
            const int k0 = ks * 8;
            uint32_t a[4][4];
#pragma unroll
            for (int mt = 0; mt < 4; mt++) {
                const int ad = buf + (wm * 64 + mt * 16 + g) * ROWSTR + k0 + tg;
                a[mt][0] = smu[ad];
                a[mt][1] = smu[ad + 8 * ROWSTR];
                a[mt][2] = smu[ad + 4];
                a[mt][3] = smu[ad + 8 * ROWSTR + 4];
            }
#pragma unroll
            for (int nt = 0; nt < 8; nt++) {
                const int bd = buf + 128 * ROWSTR
                             + (wn * 64 + nt * 8 + g) * ROWSTR + k0 + tg;
                const uint32_t b0 = smu[bd], b1 = smu[bd + 4];
#pragma unroll
                for (int mt = 0; mt < 4; mt++)
                    mma8(acc[mt][nt], a[mt], b0, b1);
            }
        }
    }

    // epilogue: direct register -> global (float2), bias/relu/round
#pragma unroll
    for (int mt = 0; mt < 4; mt++) {
        const int r0 = bRow + wm * 64 + mt * 16 + g;
#pragma unroll
        for (int nt = 0; nt < 8; nt++) {
            const int col = bCol + wn * 64 + nt * 8 + tg * 2;
            const float bi0 = bias[col], bi1 = bias[col + 1];
            float v0 = acc[mt][nt][0] + bi0, v1 = acc[mt][nt][1] + bi1;
            float v2 = acc[mt][nt][2] + bi0, v3 = acc[mt][nt][3] + bi1;
            if (relu) {
                v0 = fmaxf(v0, 0.f); v1 = fmaxf(v1, 0.f);
                v2 = fmaxf(v2, 0.f); v3 = fmaxf(v3, 0.f);
            }
            if (rnd) {
                v0 = rna_tf32(v0); v1 = rna_tf32(v1);
                v2 = rna_tf32(v2); v3 = rna_tf32(v3);
            }
            *(float2*)(C + (size_t)r0 * N + col)       = make_float2(v0, v1);
            *(float2*)(C + (size_t)(r0 + 8) * N + col) = make_float2(v2, v3);
        }
    }
}

// ---------------- weight transposes (to K-major, tf32-rounded) --------------
__global__ __launch_bounds__(256) void transpose_flat(
    const float* __restrict__ W, float* __restrict__ Wt, int K, int N)
{
    __shared__ float t[32][33];
    const int k0 = blockIdx.x * 32, n0 = blockIdx.y * 32;
    const int x = threadIdx.x, y = threadIdx.y;
#pragma unroll
    for (int j = 0; j < 32; j += 8) t[y + j][x] = W[(size_t)(k0 + y + j) * N + n0 + x];
    __syncthreads();
#pragma unroll
    for (int j = 0; j < 32; j += 8)
        Wt[(size_t)(n0 + y + j) * K + k0 + x] = rna_tf32(t[x][y + j]);
}

__global__ __launch_bounds__(256) void transpose_head(
    const float* __restrict__ W, float* __restrict__ Wt, int K)
{
    __shared__ float t[32][33];
    const int h = blockIdx.z;
    const int k0 = blockIdx.x * 32, d0 = blockIdx.y * 32;
    const float* Wh = W  + (size_t)h * K * 64;
    float*       Wo = Wt + (size_t)h * 64 * K;
    const int x = threadIdx.x, y = threadIdx.y;
#pragma unroll
    for (int j = 0; j < 32; j += 8) t[y + j][x] = Wh[(size_t)(k0 + y + j) * 64 + d0 + x];
    __syncthreads();
#pragma unroll
    for (int j = 0; j < 32; j += 8)
        Wo[(size_t)(d0 + y + j) * K + k0 + x] = rna_tf32(t[x][y + j]);
}

// ---------------- tf32 round-copy (for dec/enc activations) -----------------
__global__ __launch_bounds__(256) void round_copy(
    const float* __restrict__ in, float* __restrict__ out, int n4)
{
    const int i = blockIdx.x * blockDim.x + threadIdx.x;
    if (i < n4) {
        float4 v = ((const float4*)in)[i];
        v.x = rna_tf32(v.x); v.y = rna_tf32(v.y);
        v.z = rna_tf32(v.z); v.w = rna_tf32(v.w);
        ((float4*)out)[i] = v;
    }
}

// ---------------- attention (flash-style, one thread per query row) ---------
template<bool CAUSAL>
__global__ __launch_bounds__(128) void attn_kernel(
    const float* __restrict__ Q, const float* __restrict__ K,
    const float* __restrict__ V, float* __restrict__ O, int T)
{
    __shared__ float4 Ks[64][16];
    __shared__ float4 Vs[64][16];

    const int h = blockIdx.y;
    const int b = blockIdx.z;
    const int t = blockIdx.x * 128 + threadIdx.x;

    const float* qp = Q + ((size_t)(b * T + t) * N_HEADS + h) * DKH;
    float4 q[16];
#pragma unroll
    for (int i = 0; i < 16; i++) q[i] = ((const float4*)qp)[i];

    float4 acc[16];
#pragma unroll
    for (int i = 0; i < 16; i++) acc[i] = make_float4(0.f, 0.f, 0.f, 0.f);
    float mval = -1e30f, lsum = 0.f;

    const int sEnd = CAUSAL ? (blockIdx.x * 128 + 128) : T;
    for (int s0 = 0; s0 < sEnd; s0 += 64) {
        for (int i = threadIdx.x; i < 64 * 16; i += 128) {
            const int r = i >> 4, c = i & 15;
            const size_t gg = ((size_t)(b * T + s0 + r) * N_HEADS + h) * DKH;
            Ks[r][c] = ((const float4*)(K + gg))[c];
            Vs[r][c] = ((const float4*)(V + gg))[c];
        }
        __syncthreads();

        const int sMax = CAUSAL ? min(64, t - s0 + 1) : 64;
        for (int s = 0; s < sMax; s++) {
            float sc0 = 0.f, sc1 = 0.f, sc2 = 0.f, sc3 = 0.f;
#pragma unroll
            for (int i = 0; i < 16; i += 4) {
                float4 k0 = Ks[s][i + 0], k1 = Ks[s][i + 1];
                float4 k2 = Ks[s][i + 2], k3 = Ks[s][i + 3];
                sc0 = fmaf(q[i+0].x, k0.x, fmaf(q[i+0].y, k0.y,
                      fmaf(q[i+0].z, k0.z, fmaf(q[i+0].w, k0.w, sc0))));
                sc1 = fmaf(q[i+1].x, k1.x, fmaf(q[i+1].y, k1.y,
                      fmaf(q[i+1].z, k1.z, fmaf(q[i+1].w, k1.w, sc1))));
                sc2 = fmaf(q[i+2].x, k2.x, fmaf(q[i+2].y, k2.y,
                      fmaf(q[i+2].z, k2.z, fmaf(q[i+2].w, k2.w, sc2))));
                sc3 = fmaf(q[i+3].x, k3.x, fmaf(q[i+3].y, k3.y,
                      fmaf(q[i+3].z, k3.z, fmaf(q[i+3].w, k3.w, sc3))));
            }
            float sc = ((sc0 + sc1) + (sc2 + sc3)) * 0.125f;

            if (sc > mval) {
                const float cr = __expf(mval - sc);
                mval = sc;
                lsum *= cr;
#pragma unroll
                for (int i = 0; i < 16; i++) {
                    acc[i].x *= cr; acc[i].y *= cr;
                    acc[i].z *= cr; acc[i].w *= cr;
                }
            }
            const float p = __expf(sc - mval);
            lsum += p;
#pragma unroll
            for (int i = 0; i < 16; i++) {
                float4 vv = Vs[s][i];
                acc[i].x = fmaf(p, vv.x, acc[i].x);
                acc[i].y = fmaf(p, vv.y, acc[i].y);
                acc[i].z = fmaf(p, vv.z, acc[i].z);
                acc[i].w = fmaf(p, vv.w, acc[i].w);
            }
        }
        __syncthreads();
    }

    // output feeds a tf32 GEMM -> round here
    const float inv = 1.f / lsum;
    float4* op = (float4*)(O + ((size_t)(b * T + t) * N_HEADS + h) * DKH);
#pragma unroll
    for (int i = 0; i < 16; i++) {
        float4 o;
        o.x = rna_tf32(acc[i].x * inv); o.y = rna_tf32(acc[i].y * inv);
        o.z = rna_tf32(acc[i].z * inv); o.w = rna_tf32(acc[i].w * inv);
        op[i] = o;
    }
}

// ---------------- residual add + LayerNorm (row-wise, D=1024) ---------------
__inline__ __device__ float warpSum(float v) {
#pragma unroll
    for (int o = 16; o > 0; o >>= 1) v += __shfl_xor_sync(0xffffffffu, v, o);
    return v;
}

__global__ __launch_bounds__(256) void add_ln_kernel(
    const float* __restrict__ res, const float* __restrict__ y,
    const float* __restrict__ gamma, const float* __restrict__ beta,
    float* __restrict__ out, int rnd)
{
    const int row = blockIdx.x;
    const int i = threadIdx.x;
    const float4 a  = ((const float4*)(res + (size_t)row * D_MODEL))[i];
    const float4 b4 = ((const float4*)(y   + (size_t)row * D_MODEL))[i];
    const float x0 = a.x + b4.x, x1 = a.y + b4.y, x2 = a.z + b4.z, x3 = a.w + b4.w;

    float s  = x0 + x1 + x2 + x3;
    float sq = x0 * x0 + x1 * x1 + x2 * x2 + x3 * x3;
    s = warpSum(s); sq = warpSum(sq);

    __shared__ float sh[2][8];
    const int w = threadIdx.x >> 5, l = threadIdx.x & 31;
    if (l == 0) { sh[0][w] = s; sh[1][w] = sq; }
    __syncthreads();
    if (threadIdx.x < 32) {
        float aa = (l < 8) ? sh[0][l] : 0.f;
        float bb = (l < 8) ? sh[1][l] : 0.f;
        aa = warpSum(aa); bb = warpSum(bb);
        if (l == 0) { sh[0][0] = aa; sh[1][0] = bb; }
    }
    __syncthreads();
    const float mean = sh[0][0] * (1.f / D_MODEL);
    const float var  = sh[1][0] * (1.f / D_MODEL) - mean * mean;
    const float rinv = rsqrtf(var + 1e-5f);

    const float4 gm = ((const float4*)gamma)[i];
    const float4 be = ((const float4*)beta)[i];
    float4 o;
    o.x = (x0 - mean) * rinv * gm.x + be.x;
    o.y = (x1 - mean) * rinv * gm.y + be.y;
    o.z = (x2 - mean) * rinv * gm.z + be.z;
    o.w = (x3 - mean) * rinv * gm.w + be.w;
    if (rnd) {
        o.x = rna_tf32(o.x); o.y = rna_tf32(o.y);
        o.z = rna_tf32(o.z); o.w = rna_tf32(o.w);
    }
    ((float4*)(out + (size_t)row * D_MODEL))[i] = o;
}

// ---------------- launch ----------------------------------------------------
extern "C" void kernel_launch(void* const* d_in, const int* in_sizes, int n_in,
                              void* d_out, int out_size)
{
    const float* dec  = (const float*)d_in[0];
    const float* enc  = (const float*)d_in[1];
    const float* Wq_s = (const float*)d_in[2];
    const float* bq_s = (const float*)d_in[3];
    const float* Wk_s = (const float*)d_in[4];
    const float* bk_s = (const float*)d_in[5];
    const float* Wv_s = (const float*)d_in[6];
    const float* bv_s = (const float*)d_in[7];
    const float* Wo_s = (const float*)d_in[8];
    const float* bo_s = (const float*)d_in[9];
    const float* Wq_c = (const float*)d_in[10];
    const float* bq_c = (const float*)d_in[11];
    const float* Wk_c = (const float*)d_in[12];
    const float* bk_c = (const float*)d_in[13];
    const float* Wv_c = (const float*)d_in[14];
    const float* bv_c = (const float*)d_in[15];
    const float* Wo_c = (const float*)d_in[16];
    const float* bo_c = (const float*)d_in[17];
    const float* W1   = (const float*)d_in[18];
    const float* b1   = (const float*)d_in[19];
    const float* W2   = (const float*)d_in[20];
    const float* b2   = (const float*)d_in[21];
    const float* g1   = (const float*)d_in[22];
    const float* be1  = (const float*)d_in[23];
    const float* g2   = (const float*)d_in[24];
    const float* be2  = (const float*)d_in[25];
    const float* g3   = (const float*)d_in[26];
    const float* be3  = (const float*)d_in[27];

    float *Qb, *Kb, *Vb, *At, *X1, *X2, *Tm, *Ff, *Wt;
    cudaGetSymbolAddress((void**)&Qb, g_Q);
    cudaGetSymbolAddress((void**)&Kb, g_K);
    cudaGetSymbolAddress((void**)&Vb, g_V);
    cudaGetSymbolAddress((void**)&At, g_attn);
    cudaGetSymbolAddress((void**)&X1, g_x1);
    cudaGetSymbolAddress((void**)&X2, g_x2);
    cudaGetSymbolAddress((void**)&Tm, g_tmp);
    cudaGetSymbolAddress((void**)&Ff, g_ffn);
    cudaGetSymbolAddress((void**)&Wt, g_Wt);
    float* dec_r = Ff;                       // rounded dec (g_ffn scratch, front)
    float* enc_r = Ff + (size_t)MROWS * D_MODEL;  // rounded enc (g_ffn scratch, back)

    cudaFuncSetAttribute(gemm_tc, cudaFuncAttributeMaxDynamicSharedMemorySize, GSMEMB);

    const dim3 tb(32, 8);
    const dim3 gHead(D_MODEL / 32, DKH / 32, N_HEADS);
    const dim3 gFlatDD(D_MODEL / 32, D_MODEL / 32);
    const dim3 gD(D_MODEL / 128, MROWS / 128);   // (8, 32)
    const dim3 gF(D_FF / 128,   MROWS / 128);    // (32, 32)
    const dim3 gA(TT / 128, N_HEADS, BB);
    const int NC4 = MROWS * D_MODEL / 4;

    // pre-round activations entering GEMMs
    round_copy<<<(NC4 + 255) / 256, 256>>>(dec, dec_r, NC4);
    round_copy<<<(NC4 + 255) / 256, 256>>>(enc, enc_r, NC4);

    // ---- self-attention block ----
    transpose_head<<<gHead, tb>>>(Wq_s, Wt, D_MODEL);
    gemm_tc<<<gD, 128, GSMEMB>>>(MROWS, D_MODEL, D_MODEL, dec_r, Wt, bq_s, Qb, 0, 0);
    transpose_head<<<gHead, tb>>>(Wk_s, Wt, D_MODEL);
    gemm_tc<<<gD, 128, GSMEMB>>>(MROWS, D_MODEL, D_MODEL, dec_r, Wt, bk_s, Kb, 0, 0);
    transpose_head<<<gHead, tb>>>(Wv_s, Wt, D_MODEL);
    gemm_tc<<<gD, 128, GSMEMB>>>(MROWS, D_MODEL, D_MODEL, dec_r, Wt, bv_s, Vb, 0, 0);
    attn_kernel<true><<<gA, 128>>>(Qb, Kb, Vb, At, TT);
    transpose_flat<<<gFlatDD, tb>>>(Wo_s, Wt, D_MODEL, D_MODEL);
    gemm_tc<<<gD, 128, GSMEMB>>>(MROWS, D_MODEL, D_MODEL, At, Wt, bo_s, Tm, 0, 0);
    add_ln_kernel<<<MROWS, 256>>>(dec, Tm, g1, be1, X1, 1);   // X1 rounded (feeds GEMM)

    // ---- cross-attention block ----
    transpose_head<<<gHead, tb>>>(Wq_c, Wt, D_MODEL);
    gemm_tc<<<gD, 128, GSMEMB>>>(MROWS, D_MODEL, D_MODEL, X1, Wt, bq_c, Qb, 0, 0);
    transpose_head<<<gHead, tb>>>(Wk_c, Wt, D_MODEL);
    gemm_tc<<<gD, 128, GSMEMB>>>(MROWS, D_MODEL, D_MODEL, enc_r, Wt, bk_c, Kb, 0, 0);
    transpose_head<<<gHead, tb>>>(Wv_c, Wt, D_MODEL);
    gemm_tc<<<gD, 128, GSMEMB>>>(MROWS, D_MODEL, D_MODEL, enc_r, Wt, bv_c, Vb, 0, 0);
    attn_kernel<false><<<gA, 128>>>(Qb, Kb, Vb, At, TT);
    transpose_flat<<<gFlatDD, tb>>>(Wo_c, Wt, D_MODEL, D_MODEL);
    gemm_tc<<<gD, 128, GSMEMB>>>(MROWS, D_MODEL, D_MODEL, At, Wt, bo_c, Tm, 0, 0);
    add_ln_kernel<<<MROWS, 256>>>(X1, Tm, g2, be2, X2, 1);    // X2 rounded (feeds GEMM)

    // ---- FFN block ----
    transpose_flat<<<dim3(D_MODEL / 32, D_FF / 32), tb>>>(W1, Wt, D_MODEL, D_FF);
    gemm_tc<<<gF, 128, GSMEMB>>>(MROWS, D_FF, D_MODEL, X2, Wt, b1, Ff, 1, 1);  // relu+round
    transpose_flat<<<dim3(D_FF / 32, D_MODEL / 32), tb>>>(W2, Wt, D_FF, D_MODEL);
    gemm_tc<<<gD, 128, GSMEMB>>>(MROWS, D_MODEL, D_FF, Ff, Wt, b2, Tm, 0, 0);
    add_ln_kernel<<<MROWS, 256>>>(X2, Tm, g3, be3, (float*)d_out, 0);          // final: full fp32
}

// round 8
// speedup vs baseline: 1.7022x; 1.6198x over previous
#include <cuda_runtime.h>
#include <cuda_bf16.h>
#include <cuda_fp16.h>
#include <cstdint>
#include <cstddef>
#include <math.h>

#define D_MODEL 1024
#define N_HEADS 16
#define DKH     64
#define D_FF    4096
#define BB      2
#define TT      2048
#define MROWS   (BB * TT)   // 4096

// ---------------- scratch (device globals; no runtime allocation) -----------
__device__ float g_Q   [MROWS * D_MODEL];
__device__ float g_K   [MROWS * D_MODEL];
__device__ float g_V   [MROWS * D_MODEL];
__device__ float g_attn[MROWS * D_MODEL];
__device__ float g_x1  [MROWS * D_MODEL];
__device__ float g_x2  [MROWS * D_MODEL];
__device__ float g_tmp [MROWS * D_MODEL];
__device__ float g_ffn [MROWS * D_FF];     // also holds rounded dec/enc early
__device__ float g_Wt  [D_FF * D_MODEL];   // transposed (K-major) weights

// ======================= helpers ============================================
__device__ __forceinline__ float rna_tf32(float x) {
    uint32_t u;
    asm("cvt.rna.tf32.f32 %0, %1;" : "=r"(u) : "f"(x));
    return __uint_as_float(u);
}

__device__ __forceinline__ uint32_t h2_as_u32(__half2 h) {
    union { __half2 h; uint32_t u; } cvt;
    cvt.h = h;
    return cvt.u;
}

__device__ __forceinline__ void cpa8(uint32_t dst, const void* src) {
    asm volatile("cp.async.ca.shared.global [%0], [%1], 8;\n"
                 :: "r"(dst), "l"(src) : "memory");
}
#define CP_COMMIT() asm volatile("cp.async.commit_group;\n" ::: "memory")
#define CP_WAIT(n)  asm volatile("cp.async.wait_group %0;\n" :: "n"(n) : "memory")

__device__ __forceinline__ uint32_t smem_u32(const void* p) {
    uint32_t a;
    asm("{ .reg .u64 t; cvta.to.shared.u64 t, %1; cvt.u32.u64 %0, t; }"
        : "=r"(a) : "l"(p));
    return a;
}

__device__ __forceinline__ void mma8(float* c, const uint32_t* a,
                                     uint32_t b0, uint32_t b1) {
    asm volatile(
        "mma.sync.aligned.m16n8k8.row.col.f32.tf32.tf32.f32 "
        "{%0,%1,%2,%3}, {%4,%5,%6,%7}, {%8,%9}, {%0,%1,%2,%3};"
        : "+f"(c[0]), "+f"(c[1]), "+f"(c[2]), "+f"(c[3])
        : "r"(a[0]), "r"(a[1]), "r"(a[2]), "r"(a[3]), "r"(b0), "r"(b1));
}

__device__ __forceinline__ void mma16h(float* c, uint32_t a0, uint32_t a1,
                                       uint32_t a2, uint32_t a3,
                                       uint32_t b0, uint32_t b1) {
    asm volatile(
        "mma.sync.aligned.m16n8k16.row.col.f32.f16.f16.f32 "
        "{%0,%1,%2,%3}, {%4,%5,%6,%7}, {%8,%9}, {%0,%1,%2,%3};"
        : "+f"(c[0]), "+f"(c[1]), "+f"(c[2]), "+f"(c[3])
        : "r"(a0), "r"(a1), "r"(a2), "r"(a3), "r"(b0), "r"(b1));
}

// =============== tf32 mma.sync GEMM: C = A[M,K] @ Wt^T + bias ===============
#define ROWSTR 20
#define STAGEF (2 * 128 * ROWSTR)
#define NSTAGE 3
#define GSMEMB (NSTAGE * STAGEF * 4)

__global__ __launch_bounds__(128, 1)
void gemm_tc(int M, int N, int K,
             const float* __restrict__ A, const float* __restrict__ Wt,
             const float* __restrict__ bias, float* __restrict__ C,
             int relu, int rnd)
{
    extern __shared__ float sm[];
    const uint32_t* smu = (const uint32_t*)sm;
    const uint32_t sb = smem_u32(sm);

    const int tid = threadIdx.x;
    const int wid = tid >> 5, lid = tid & 31;
    const int g = lid >> 2, tg = lid & 3;
    const int wm = wid >> 1, wn = wid & 1;

    const int bRow = blockIdx.y * 128, bCol = blockIdx.x * 128;
    const float* Ap = A  + (size_t)(bRow + tid) * K;
    const float* Bp = Wt + (size_t)(bCol + tid) * K;
    const int NT = K >> 4;

    float acc[4][8][4];
#pragma unroll
    for (int m = 0; m < 4; m++)
#pragma unroll
        for (int n = 0; n < 8; n++)
#pragma unroll
            for (int x = 0; x < 4; x++) acc[m][n][x] = 0.f;

    auto load_stage = [&](int it, int s) {
        const uint32_t ad = sb + (s * STAGEF + tid * ROWSTR) * 4;
        const uint32_t bd = ad + 128 * ROWSTR * 4;
        const float* as = Ap + it * 16;
        const float* bs = Bp + it * 16;
#pragma unroll
        for (int j = 0; j < 8; j++) {
            cpa8(ad + j * 8, as + j * 2);
            cpa8(bd + j * 8, bs + j * 2);
        }
    };

    load_stage(0, 0); CP_COMMIT();
    load_stage(1, 1); CP_COMMIT();

    for (int i = 0; i < NT; i++) {
        CP_WAIT(1);
        __syncthreads();
        const int pre = i + 2;
        if (pre < NT) load_stage(pre, pre % NSTAGE);
        CP_COMMIT();

        const int buf = (i % NSTAGE) * STAGEF;
#pragma unroll
        for (int ks = 0; ks < 2; ks++) {
            const int k0 = ks * 8;
            uint32_t a[4][4];
#pragma unroll
            for (int mt = 0; mt < 4; mt++) {
                const int ad = buf + (wm * 64 + mt * 16 + g) * ROWSTR + k0 + tg;
                a[mt][0] = smu[ad];
                a[mt][1] = smu[ad + 8 * ROWSTR];
                a[mt][2] = smu[ad + 4];
                a[mt][3] = smu[ad + 8 * ROWSTR + 4];
            }
#pragma unroll
            for (int nt = 0; nt < 8; nt++) {
                const int bd = buf + 128 * ROWSTR
                             + (wn * 64 + nt * 8 + g) * ROWSTR + k0 + tg;
                const uint32_t b0 = smu[bd], b1 = smu[bd + 4];
#pragma unroll
                for (int mt = 0; mt < 4; mt++)
                    mma8(acc[mt][nt], a[mt], b0, b1);
            }
        }
    }

#pragma unroll
    for (int mt = 0; mt < 4; mt++) {
        const int r0 = bRow + wm * 64 + mt * 16 + g;
#pragma unroll
        for (int nt = 0; nt < 8; nt++) {
            const int col = bCol + wn * 64 + nt * 8 + tg * 2;
            const float bi0 = bias[col], bi1 = bias[col + 1];
            float v0 = acc[mt][nt][0] + bi0, v1 = acc[mt][nt][1] + bi1;
            float v2 = acc[mt][nt][2] + bi0, v3 = acc[mt][nt][3] + bi1;
            if (relu) {
                v0 = fmaxf(v0, 0.f); v1 = fmaxf(v1, 0.f);
                v2 = fmaxf(v2, 0.f); v3 = fmaxf(v3, 0.f);
            }
            if (rnd) {
                v0 = rna_tf32(v0); v1 = rna_tf32(v1);
                v2 = rna_tf32(v2); v3 = rna_tf32(v3);
            }
            *(float2*)(C + (size_t)r0 * N + col)       = make_float2(v0, v1);
            *(float2*)(C + (size_t)(r0 + 8) * N + col) = make_float2(v2, v3);
        }
    }
}

// ---------------- weight transposes (to K-major, tf32-rounded) --------------
__global__ __launch_bounds__(256) void transpose_flat(
    const float* __restrict__ W, float* __restrict__ Wt, int K, int N)
{
    __shared__ float t[32][33];
    const int k0 = blockIdx.x * 32, n0 = blockIdx.y * 32;
    const int x = threadIdx.x, y = threadIdx.y;
#pragma unroll
    for (int j = 0; j < 32; j += 8) t[y + j][x] = W[(size_t)(k0 + y + j) * N + n0 + x];
    __syncthreads();
#pragma unroll
    for (int j = 0; j < 32; j += 8)
        Wt[(size_t)(n0 + y + j) * K + k0 + x] = rna_tf32(t[x][y + j]);
}

__global__ __launch_bounds__(256) void transpose_head(
    const float* __restrict__ W, float* __restrict__ Wt, int K)
{
    __shared__ float t[32][33];
    const int h = blockIdx.z;
    const int k0 = blockIdx.x * 32, d0 = blockIdx.y * 32;
    const float* Wh = W  + (size_t)h * K * 64;
    float*       Wo = Wt + (size_t)h * 64 * K;
    const int x = threadIdx.x, y = threadIdx.y;
#pragma unroll
    for (int j = 0; j < 32; j += 8) t[y + j][x] = Wh[(size_t)(k0 + y + j) * 64 + d0 + x];
    __syncthreads();
#pragma unroll
    for (int j = 0; j < 32; j += 8)
        Wo[(size_t)(d0 + y + j) * K + k0 + x] = rna_tf32(t[x][y + j]);
}

// ---------------- tf32 round-copy -------------------------------------------
__global__ __launch_bounds__(256) void round_copy(
    const float* __restrict__ in, float* __restrict__ out, int n4)
{
    const int i = blockIdx.x * blockDim.x + threadIdx.x;
    if (i < n4) {
        float4 v = ((const float4*)in)[i];
        v.x = rna_tf32(v.x); v.y = rna_tf32(v.y);
        v.z = rna_tf32(v.z); v.w = rna_tf32(v.w);
        ((float4*)out)[i] = v;
    }
}

// ========== flash attention, fp16 mma.sync (FA2 layout) =====================
// Block: 64 query rows, 4 warps (16 rows each). K/V streamed in 64-key tiles.
// Q,K,V,O: [B,T,H*64] f32. SMEM rows padded to 72 halves (36 b32) -> the
// fragment-load bank index is (4g+tg) mod 32: conflict-free.
#define AROW 36   // b32 words per smem row

template<bool CAUSAL>
__global__ __launch_bounds__(128) void attn_mma(
    const float* __restrict__ Q, const float* __restrict__ K,
    const float* __restrict__ V, float* __restrict__ O, int T)
{
    __shared__ __align__(16) __half Qs[64 * 72];
    __shared__ __align__(16) __half Ks[64 * 72];
    __shared__ __align__(16) __half Vt[64 * 72];

    const int tid = threadIdx.x, wid = tid >> 5, lid = tid & 31;
    const int g = lid >> 2, tg = lid & 3;
    const int h = blockIdx.y, b = blockIdx.z;
    const int q0 = blockIdx.x * 64;
    const size_t base = (size_t)b * T * D_MODEL + h * DKH;

    // ---- stage Q (pre-scaled by 1/sqrt(dk)) ----
    for (int idx = tid; idx < 64 * 16; idx += 128) {
        const int r = idx >> 4, c4 = idx & 15;
        float4 v = *(const float4*)(Q + base + (size_t)(q0 + r) * D_MODEL + c4 * 4);
        __half2* dst = (__half2*)&Qs[r * 72 + c4 * 4];
        dst[0] = __floats2half2_rn(v.x * 0.125f, v.y * 0.125f);
        dst[1] = __floats2half2_rn(v.z * 0.125f, v.w * 0.125f);
    }
    __syncthreads();

    // ---- Q fragments (A of m16n8k16): qf[kc][0..3] ----
    uint32_t qf[4][4];
    {
        const uint32_t* Qu = (const uint32_t*)Qs;
        const int r0 = wid * 16 + g;
#pragma unroll
        for (int kc = 0; kc < 4; kc++) {
            const int c = 8 * kc + tg;
            qf[kc][0] = Qu[r0 * AROW + c];
            qf[kc][1] = Qu[(r0 + 8) * AROW + c];
            qf[kc][2] = Qu[r0 * AROW + c + 4];
            qf[kc][3] = Qu[(r0 + 8) * AROW + c + 4];
        }
    }

    float oacc[8][4];
#pragma unroll
    for (int j = 0; j < 8; j++)
#pragma unroll
        for (int x = 0; x < 4; x++) oacc[j][x] = 0.f;
    float m0 = -1e30f, m1 = -1e30f, l0 = 0.f, l1 = 0.f;

    const int nkt = CAUSAL ? (blockIdx.x + 1) : (T / 64);
    for (int kt = 0; kt < nkt; kt++) {
        const int s0 = kt * 64;
        __syncthreads();
        // stage K tile [key][dk] and V^T tile [dk][key]
        for (int idx = tid; idx < 64 * 16; idx += 128) {
            const int r = idx >> 4, c4 = idx & 15;
            const size_t gaddr = base + (size_t)(s0 + r) * D_MODEL + c4 * 4;
            float4 kv = *(const float4*)(K + gaddr);
            __half2* kd = (__half2*)&Ks[r * 72 + c4 * 4];
            kd[0] = __floats2half2_rn(kv.x, kv.y);
            kd[1] = __floats2half2_rn(kv.z, kv.w);
            float4 vv = *(const float4*)(V + gaddr);
            Vt[(c4 * 4 + 0) * 72 + r] = __float2half_rn(vv.x);
            Vt[(c4 * 4 + 1) * 72 + r] = __float2half_rn(vv.y);
            Vt[(c4 * 4 + 2) * 72 + r] = __float2half_rn(vv.z);
            Vt[(c4 * 4 + 3) * 72 + r] = __float2half_rn(vv.w);
        }
        __syncthreads();

        // ---- S = Q @ K^T (f32 accum) ----
        float sacc[8][4];
#pragma unroll
        for (int j = 0; j < 8; j++)
#pragma unroll
            for (int x = 0; x < 4; x++) sacc[j][x] = 0.f;
        {
            const uint32_t* Ku = (const uint32_t*)Ks;
#pragma unroll
            for (int j = 0; j < 8; j++) {
                const int rb = (8 * j + g) * AROW + tg;
#pragma unroll
                for (int kc = 0; kc < 4; kc++) {
                    const uint32_t b0 = Ku[rb + 8 * kc];
                    const uint32_t b1 = Ku[rb + 8 * kc + 4];
                    mma16h(sacc[j], qf[kc][0], qf[kc][1], qf[kc][2], qf[kc][3],
                           b0, b1);
                }
            }
        }

        // ---- causal mask (diagonal tile only) ----
        if (CAUSAL && kt == blockIdx.x) {
            const int r0 = q0 + wid * 16 + g, r1 = r0 + 8;
#pragma unroll
            for (int j = 0; j < 8; j++) {
                const int c0 = s0 + 8 * j + 2 * tg, c1 = c0 + 1;
                if (c0 > r0) sacc[j][0] = -INFINITY;
                if (c1 > r0) sacc[j][1] = -INFINITY;
                if (c0 > r1) sacc[j][2] = -INFINITY;
                if (c1 > r1) sacc[j][3] = -INFINITY;
            }
        }

        // ---- online softmax (rows g and g+8) ----
        float tm0 = -1e30f, tm1 = -1e30f;
#pragma unroll
        for (int j = 0; j < 8; j++) {
            tm0 = fmaxf(tm0, fmaxf(sacc[j][0], sacc[j][1]));
            tm1 = fmaxf(tm1, fmaxf(sacc[j][2], sacc[j][3]));
        }
        tm0 = fmaxf(tm0, __shfl_xor_sync(0xffffffffu, tm0, 1));
        tm0 = fmaxf(tm0, __shfl_xor_sync(0xffffffffu, tm0, 2));
        tm1 = fmaxf(tm1, __shfl_xor_sync(0xffffffffu, tm1, 1));
        tm1 = fmaxf(tm1, __shfl_xor_sync(0xffffffffu, tm1, 2));

        const float mn0 = fmaxf(m0, tm0), mn1 = fmaxf(m1, tm1);
        const float cr0 = __expf(m0 - mn0), cr1 = __expf(m1 - mn1);
        m0 = mn0; m1 = mn1;

        uint32_t ph[8][2];
        float ts0 = 0.f, ts1 = 0.f;
#pragma unroll
        for (int j = 0; j < 8; j++) {
            const float p0 = __expf(sacc[j][0] - mn0);
            const float p1 = __expf(sacc[j][1] - mn0);
            const float p2 = __expf(sacc[j][2] - mn1);
            const float p3 = __expf(sacc[j][3] - mn1);
            ts0 += p0 + p1; ts1 += p2 + p3;
            ph[j][0] = h2_as_u32(__floats2half2_rn(p0, p1));
            ph[j][1] = h2_as_u32(__floats2half2_rn(p2, p3));
        }
        ts0 += __shfl_xor_sync(0xffffffffu, ts0, 1);
        ts0 += __shfl_xor_sync(0xffffffffu, ts0, 2);
        ts1 += __shfl_xor_sync(0xffffffffu, ts1, 1);
        ts1 += __shfl_xor_sync(0xffffffffu, ts1, 2);
        l0 = l0 * cr0 + ts0;
        l1 = l1 * cr1 + ts1;

#pragma unroll
        for (int j = 0; j < 8; j++) {
            oacc[j][0] *= cr0; oacc[j][1] *= cr0;
            oacc[j][2] *= cr1; oacc[j][3] *= cr1;
        }

        // ---- O += P @ V ----
        {
            const uint32_t* Vu = (const uint32_t*)Vt;
#pragma unroll
            for (int j = 0; j < 8; j++) {      // dk n-tiles
                const int rb = (8 * j + g) * AROW + tg;
#pragma unroll
                for (int kc = 0; kc < 4; kc++) {
                    const uint32_t b0 = Vu[rb + 8 * kc];
                    const uint32_t b1 = Vu[rb + 8 * kc + 4];
                    mma16h(oacc[j], ph[2 * kc][0], ph[2 * kc][1],
                           ph[2 * kc + 1][0], ph[2 * kc + 1][1], b0, b1);
                }
            }
        }
    }

    // ---- epilogue (round to tf32: feeds a tf32 GEMM) ----
    const float inv0 = 1.f / l0, inv1 = 1.f / l1;
    const int r0 = q0 + wid * 16 + g;
#pragma unroll
    for (int j = 0; j < 8; j++) {
        const int col = 8 * j + 2 * tg;
        float2 a = make_float2(rna_tf32(oacc[j][0] * inv0),
                               rna_tf32(oacc[j][1] * inv0));
        float2 c = make_float2(rna_tf32(oacc[j][2] * inv1),
                               rna_tf32(oacc[j][3] * inv1));
        *(float2*)(O + base + (size_t)r0 * D_MODEL + col)       = a;
        *(float2*)(O + base + (size_t)(r0 + 8) * D_MODEL + col) = c;
    }
}

// ---------------- residual add + LayerNorm (row-wise, D=1024) ---------------
__inline__ __device__ float warpSum(float v) {
#pragma unroll
    for (int o = 16; o > 0; o >>= 1) v += __shfl_xor_sync(0xffffffffu, v, o);
    return v;
}

__global__ __launch_bounds__(256) void add_ln_kernel(
    const float* __restrict__ res, const float* __restrict__ y,
    const float* __restrict__ gamma, const float* __restrict__ beta,
    float* __restrict__ out, int rnd)
{
    const int row = blockIdx.x;
    const int i = threadIdx.x;
    const float4 a  = ((const float4*)(res + (size_t)row * D_MODEL))[i];
    const float4 b4 = ((const float4*)(y   + (size_t)row * D_MODEL))[i];
    const float x0 = a.x + b4.x, x1 = a.y + b4.y, x2 = a.z + b4.z, x3 = a.w + b4.w;

    float s  = x0 + x1 + x2 + x3;
    float sq = x0 * x0 + x1 * x1 + x2 * x2 + x3 * x3;
    s = warpSum(s); sq = warpSum(sq);

    __shared__ float sh[2][8];
    const int w = threadIdx.x >> 5, l = threadIdx.x & 31;
    if (l == 0) { sh[0][w] = s; sh[1][w] = sq; }
    __syncthreads();
    if (threadIdx.x < 32) {
        float aa = (l < 8) ? sh[0][l] : 0.f;
        float bb = (l < 8) ? sh[1][l] : 0.f;
        aa = warpSum(aa); bb = warpSum(bb);
        if (l == 0) { sh[0][0] = aa; sh[1][0] = bb; }
    }
    __syncthreads();
    const float mean = sh[0][0] * (1.f / D_MODEL);
    const float var  = sh[1][0] * (1.f / D_MODEL) - mean * mean;
    const float rinv = rsqrtf(var + 1e-5f);

    const float4 gm = ((const float4*)gamma)[i];
    const float4 be = ((const float4*)beta)[i];
    float4 o;
    o.x = (x0 - mean) * rinv * gm.x + be.x;
    o.y = (x1 - mean) * rinv * gm.y + be.y;
    o.z = (x2 - mean) * rinv * gm.z + be.z;
    o.w = (x3 - mean) * rinv * gm.w + be.w;
    if (rnd) {
        o.x = rna_tf32(o.x); o.y = rna_tf32(o.y);
        o.z = rna_tf32(o.z); o.w = rna_tf32(o.w);
    }
    ((float4*)(out + (size_t)row * D_MODEL))[i] = o;
}

// ---------------- launch ----------------------------------------------------
extern "C" void kernel_launch(void* const* d_in, const int* in_sizes, int n_in,
                              void* d_out, int out_size)
{
    const float* dec  = (const float*)d_in[0];
    const float* enc  = (const float*)d_in[1];
    const float* Wq_s = (const float*)d_in[2];
    const float* bq_s = (const float*)d_in[3];
    const float* Wk_s = (const float*)d_in[4];
    const float* bk_s = (const float*)d_in[5];
    const float* Wv_s = (const float*)d_in[6];
    const float* bv_s = (const float*)d_in[7];
    const float* Wo_s = (const float*)d_in[8];
    const float* bo_s = (const float*)d_in[9];
    const float* Wq_c = (const float*)d_in[10];
    const float* bq_c = (const float*)d_in[11];
    const float* Wk_c = (const float*)d_in[12];
    const float* bk_c = (const float*)d_in[13];
    const float* Wv_c = (const float*)d_in[14];
    const float* bv_c = (const float*)d_in[15];
    const float* Wo_c = (const float*)d_in[16];
    const float* bo_c = (const float*)d_in[17];
    const float* W1   = (const float*)d_in[18];
    const float* b1   = (const float*)d_in[19];
    const float* W2   = (const float*)d_in[20];
    const float* b2   = (const float*)d_in[21];
    const float* g1   = (const float*)d_in[22];
    const float* be1  = (const float*)d_in[23];
    const float* g2   = (const float*)d_in[24];
    const float* be2  = (const float*)d_in[25];
    const float* g3   = (const float*)d_in[26];
    const float* be3  = (const float*)d_in[27];

    float *Qb, *Kb, *Vb, *At, *X1, *X2, *Tm, *Ff, *Wt;
    cudaGetSymbolAddress((void**)&Qb, g_Q);
    cudaGetSymbolAddress((void**)&Kb, g_K);
    cudaGetSymbolAddress((void**)&Vb, g_V);
    cudaGetSymbolAddress((void**)&At, g_attn);
    cudaGetSymbolAddress((void**)&X1, g_x1);
    cudaGetSymbolAddress((void**)&X2, g_x2);
    cudaGetSymbolAddress((void**)&Tm, g_tmp);
    cudaGetSymbolAddress((void**)&Ff, g_ffn);
    cudaGetSymbolAddress((void**)&Wt, g_Wt);
    float* dec_r = Ff;
    float* enc_r = Ff + (size_t)MROWS * D_MODEL;

    cudaFuncSetAttribute(gemm_tc, cudaFuncAttributeMaxDynamicSharedMemorySize, GSMEMB);

    const dim3 tb(32, 8);
    const dim3 gHead(D_MODEL / 32, DKH / 32, N_HEADS);
    const dim3 gFlatDD(D_MODEL / 32, D_MODEL / 32);
    const dim3 gD(D_MODEL / 128, MROWS / 128);   // (8, 32)
    const dim3 gF(D_FF / 128,   MROWS / 128);    // (32, 32)
    const dim3 gA(TT / 64, N_HEADS, BB);         // (32, 16, 2)
    const int NC4 = MROWS * D_MODEL / 4;

    round_copy<<<(NC4 + 255) / 256, 256>>>(dec, dec_r, NC4);
    round_copy<<<(NC4 + 255) / 256, 256>>>(enc, enc_r, NC4);

    // ---- self-attention block ----
    transpose_head<<<gHead, tb>>>(Wq_s, Wt, D_MODEL);
    gemm_tc<<<gD, 128, GSMEMB>>>(MROWS, D_MODEL, D_MODEL, dec_r, Wt, bq_s, Qb, 0, 0);
    transpose_head<<<gHead, tb>>>(Wk_s, Wt, D_MODEL);
    gemm_tc<<<gD, 128, GSMEMB>>>(MROWS, D_MODEL, D_MODEL, dec_r, Wt, bk_s, Kb, 0, 0);
    transpose_head<<<gHead, tb>>>(Wv_s, Wt, D_MODEL);
    gemm_tc<<<gD, 128, GSMEMB>>>(MROWS, D_MODEL, D_MODEL, dec_r, Wt, bv_s, Vb, 0, 0);
    attn_mma<true><<<gA, 128>>>(Qb, Kb, Vb, At, TT);
    transpose_flat<<<gFlatDD, tb>>>(Wo_s, Wt, D_MODEL, D_MODEL);
    gemm_tc<<<gD, 128, GSMEMB>>>(MROWS, D_MODEL, D_MODEL, At, Wt, bo_s, Tm, 0, 0);
    add_ln_kernel<<<MROWS, 256>>>(dec, Tm, g1, be1, X1, 1);

    // ---- cross-attention block ----
    transpose_head<<<gHead, tb>>>(Wq_c, Wt, D_MODEL);
    gemm_tc<<<gD, 128, GSMEMB>>>(MROWS, D_MODEL, D_MODEL, X1, Wt, bq_c, Qb, 0, 0);
    transpose_head<<<gHead, tb>>>(Wk_c, Wt, D_MODEL);
    gemm_tc<<<gD, 128, GSMEMB>>>(MROWS, D_MODEL, D_MODEL, enc_r, Wt, bk_c, Kb, 0, 0);
    transpose_head<<<gHead, tb>>>(Wv_c, Wt, D_MODEL);
    gemm_tc<<<gD, 128, GSMEMB>>>(MROWS, D_MODEL, D_MODEL, enc_r, Wt, bv_c, Vb, 0, 0);
    attn_mma<false><<<gA, 128>>>(Qb, Kb, Vb, At, TT);
    transpose_flat<<<gFlatDD, tb>>>(Wo_c, Wt, D_MODEL, D_MODEL);
    gemm_tc<<<gD, 128, GSMEMB>>>(MROWS, D_MODEL, D_MODEL, At, Wt, bo_c, Tm, 0, 0);
    add_ln_kernel<<<MROWS, 256>>>(X1, Tm, g2, be2, X2, 1);

    // ---- FFN block ----
    transpose_flat<<<dim3(D_MODEL / 32, D_FF / 32), tb>>>(W1, Wt, D_MODEL, D_FF);
    gemm_tc<<<gF, 128, GSMEMB>>>(MROWS, D_FF, D_MODEL, X2, Wt, b1, Ff, 1, 1);
    transpose_flat<<<dim3(D_FF / 32, D_MODEL / 32), tb>>>(W2, Wt, D_FF, D_MODEL);
    gemm_tc<<<gD, 128, GSMEMB>>>(MROWS, D_MODEL, D_FF, Ff, Wt, b2, Tm, 0, 0);
    add_ln_kernel<<<MROWS, 256>>>(X2, Tm, g3, be3, (float*)d_out, 0);
}

// round 9
// speedup vs baseline: 5.1633x; 3.0333x over previous
#include <cuda_runtime.h>
#include <cuda_bf16.h>
#include <cuda_fp16.h>
#include <cstdint>
#include <cstddef>
#include <math.h>

#define D_MODEL 1024
#define N_HEADS 16
#define DKH     64
#define D_FF    4096
#define BB      2
#define TT      2048
#define MROWS   (BB * TT)   // 4096

// ---------------- scratch (device globals; no runtime allocation) -----------
__device__ float g_Q   [MROWS * D_MODEL];   // used as half (Qh)
__device__ float g_K   [MROWS * D_MODEL];   // Kh
__device__ float g_V   [MROWS * D_MODEL];   // Vh
__device__ float g_attn[MROWS * D_MODEL];   // At_h (half)
__device__ float g_x1  [MROWS * D_MODEL];   // fp32
__device__ float g_x2  [MROWS * D_MODEL];   // fp32
__device__ float g_tmp [MROWS * D_MODEL];   // fp32 GEMM out
__device__ float g_ffn [MROWS * D_FF];      // front: dec_h/enc_h; +8M floats: Ff_h
__device__ float g_Wt  [D_FF * D_MODEL];    // front: Wt half; back: Xh half

// ======================= helpers ============================================
__device__ __forceinline__ uint32_t h2_as_u32(__half2 h) {
    union { __half2 h; uint32_t u; } cvt;
    cvt.h = h;
    return cvt.u;
}

__device__ __forceinline__ void cpa8(uint32_t dst, const void* src) {
    asm volatile("cp.async.ca.shared.global [%0], [%1], 8;\n"
                 :: "r"(dst), "l"(src) : "memory");
}
#define CP_COMMIT() asm volatile("cp.async.commit_group;\n" ::: "memory")
#define CP_WAIT(n)  asm volatile("cp.async.wait_group %0;\n" :: "n"(n) : "memory")

__device__ __forceinline__ uint32_t smem_u32(const void* p) {
    uint32_t a;
    asm("{ .reg .u64 t; cvta.to.shared.u64 t, %1; cvt.u32.u64 %0, t; }"
        : "=r"(a) : "l"(p));
    return a;
}

__device__ __forceinline__ void mma16h(float* c, uint32_t a0, uint32_t a1,
                                       uint32_t a2, uint32_t a3,
                                       uint32_t b0, uint32_t b1) {
    asm volatile(
        "mma.sync.aligned.m16n8k16.row.col.f32.f16.f16.f32 "
        "{%0,%1,%2,%3}, {%4,%5,%6,%7}, {%8,%9}, {%0,%1,%2,%3};"
        : "+f"(c[0]), "+f"(c[1]), "+f"(c[2]), "+f"(c[3])
        : "r"(a0), "r"(a1), "r"(a2), "r"(a3), "r"(b0), "r"(b1));
}

// =============== fp16 mma GEMM: C = A[M,K] @ Wt^T + bias ====================
// A, Wt: half, K-major rows. Block tile 256x128, 256 thr, warp tile 64x64.
// SMEM row stride 80B (40 halves, 20 u32) -> all fragment loads conflict-free.
#define G_STAGEB 30720            // (256+128) rows * 80B
#define G_STAGE32 7680
#define G_BOFF32 5120             // B region offset in u32 (256*80/4)
#define G_NSTG 3
#define G_SMEM (G_NSTG * G_STAGEB)  // 92160

__global__ __launch_bounds__(256, 1)
void gemm_h(int M, int N, int K,
            const __half* __restrict__ A, const __half* __restrict__ Wt,
            const float* __restrict__ bias, void* __restrict__ C,
            int relu, int outHalf)
{
    extern __shared__ char smc[];
    const uint32_t* su = (const uint32_t*)smc;
    const uint32_t sb = smem_u32(smc);

    const int tid = threadIdx.x;
    const int wid = tid >> 5, lid = tid & 31;
    const int g = lid >> 2, tg = lid & 3;
    const int wm = wid >> 1, wn = wid & 1;   // 4 x 2 warp grid

    const int bRow = blockIdx.y * 256, bCol = blockIdx.x * 128;
    const int NT = K >> 5;                    // BK = 32 halves

    float acc[4][8][4];
#pragma unroll
    for (int m = 0; m < 4; m++)
#pragma unroll
        for (int n = 0; n < 8; n++)
#pragma unroll
            for (int x = 0; x < 4; x++) acc[m][n][x] = 0.f;

    const int arow = tid >> 3, ac = (tid & 7) * 4;   // ac in halves

    auto load_stage = [&](int it, int s) {
        const uint32_t base = sb + s * G_STAGEB;
        const __half* as = A  + (size_t)(bRow + arow) * K + it * 32 + ac;
        const __half* bs = Wt + (size_t)(bCol + arow) * K + it * 32 + ac;
#pragma unroll
        for (int j = 0; j < 8; j++)
            cpa8(base + (arow + 32 * j) * 80 + ac * 2, as + (size_t)(32 * j) * K);
#pragma unroll
        for (int j = 0; j < 4; j++)
            cpa8(base + G_BOFF32 * 4 + (arow + 32 * j) * 80 + ac * 2,
                 bs + (size_t)(32 * j) * K);
    };

    load_stage(0, 0); CP_COMMIT();
    load_stage(1, 1); CP_COMMIT();

    for (int i = 0; i < NT; i++) {
        CP_WAIT(1);
        __syncthreads();
        const int pre = i + 2;
        if (pre < NT) load_stage(pre, pre % G_NSTG);
        CP_COMMIT();

        const int buf = (i % G_NSTG) * G_STAGE32;
#pragma unroll
        for (int ks = 0; ks < 2; ks++) {
            const int kb = ks * 8;
            uint32_t a[4][4];
#pragma unroll
            for (int mt = 0; mt < 4; mt++) {
                const int ad = buf + (wm * 64 + mt * 16 + g) * 20 + kb + tg;
                a[mt][0] = su[ad];
                a[mt][1] = su[ad + 160];
                a[mt][2] = su[ad + 4];
                a[mt][3] = su[ad + 164];
            }
#pragma unroll
            for (int nt = 0; nt < 8; nt++) {
                const int bd = buf + G_BOFF32
                             + (wn * 64 + nt * 8 + g) * 20 + kb + tg;
                const uint32_t b0 = su[bd], b1 = su[bd + 4];
#pragma unroll
                for (int mt = 0; mt < 4; mt++)
                    mma16h(acc[mt][nt], a[mt][0], a[mt][1], a[mt][2], a[mt][3],
                           b0, b1);
            }
        }
    }

    // epilogue
    float* Cf = (float*)C;
    __half* Ch = (__half*)C;
#pragma unroll
    for (int mt = 0; mt < 4; mt++) {
        const int r0 = bRow + wm * 64 + mt * 16 + g;
#pragma unroll
        for (int nt = 0; nt < 8; nt++) {
            const int col = bCol + wn * 64 + nt * 8 + 2 * tg;
            const float bi0 = bias[col], bi1 = bias[col + 1];
            float v0 = acc[mt][nt][0] + bi0, v1 = acc[mt][nt][1] + bi1;
            float v2 = acc[mt][nt][2] + bi0, v3 = acc[mt][nt][3] + bi1;
            if (relu) {
                v0 = fmaxf(v0, 0.f); v1 = fmaxf(v1, 0.f);
                v2 = fmaxf(v2, 0.f); v3 = fmaxf(v3, 0.f);
            }
            if (outHalf) {
                *(__half2*)(Ch + (size_t)r0 * N + col) =
                    __floats2half2_rn(v0, v1);
                *(__half2*)(Ch + (size_t)(r0 + 8) * N + col) =
                    __floats2half2_rn(v2, v3);
            } else {
                *(float2*)(Cf + (size_t)r0 * N + col) = make_float2(v0, v1);
                *(float2*)(Cf + (size_t)(r0 + 8) * N + col) = make_float2(v2, v3);
            }
        }
    }
}

// ---------------- weight transposes (to K-major fp16) -----------------------
__global__ __launch_bounds__(256) void transpose_flat(
    const float* __restrict__ W, __half* __restrict__ Wt, int K, int N)
{
    __shared__ float t[32][33];
    const int k0 = blockIdx.x * 32, n0 = blockIdx.y * 32;
    const int x = threadIdx.x, y = threadIdx.y;
#pragma unroll
    for (int j = 0; j < 32; j += 8) t[y + j][x] = W[(size_t)(k0 + y + j) * N + n0 + x];
    __syncthreads();
#pragma unroll
    for (int j = 0; j < 32; j += 8)
        Wt[(size_t)(n0 + y + j) * K + k0 + x] = __float2half_rn(t[x][y + j]);
}

__global__ __launch_bounds__(256) void transpose_head(
    const float* __restrict__ W, __half* __restrict__ Wt, int K)
{
    __shared__ float t[32][33];
    const int h = blockIdx.z;
    const int k0 = blockIdx.x * 32, d0 = blockIdx.y * 32;
    const float* Wh = W  + (size_t)h * K * 64;
    __half*      Wo = Wt + (size_t)h * 64 * K;
    const int x = threadIdx.x, y = threadIdx.y;
#pragma unroll
    for (int j = 0; j < 32; j += 8) t[y + j][x] = Wh[(size_t)(k0 + y + j) * 64 + d0 + x];
    __syncthreads();
#pragma unroll
    for (int j = 0; j < 32; j += 8)
        Wo[(size_t)(d0 + y + j) * K + k0 + x] = __float2half_rn(t[x][y + j]);
}

// ---------------- fp32 -> fp16 copy -----------------------------------------
__global__ __launch_bounds__(256) void h_copy(
    const float* __restrict__ in, __half* __restrict__ out, int n4)
{
    const int i = blockIdx.x * blockDim.x + threadIdx.x;
    if (i < n4) {
        float4 v = ((const float4*)in)[i];
        uint2 o;
        o.x = h2_as_u32(__floats2half2_rn(v.x, v.y));
        o.y = h2_as_u32(__floats2half2_rn(v.z, v.w));
        ((uint2*)out)[i] = o;
    }
}

// ========== flash attention, fp16 I/O, fp16 mma.sync ========================
#define AROW 36   // b32 words per smem row (72 halves)

template<bool CAUSAL>
__global__ __launch_bounds__(128) void attn_mma(
    const __half* __restrict__ Q, const __half* __restrict__ K,
    const __half* __restrict__ V, __half* __restrict__ O, int T)
{
    __shared__ __align__(16) __half Qs[64 * 72];
    __shared__ __align__(16) __half Ks[64 * 72];
    __shared__ __align__(16) __half Vt[64 * 72];

    const int tid = threadIdx.x, wid = tid >> 5, lid = tid & 31;
    const int g = lid >> 2, tg = lid & 3;
    const int h = blockIdx.y, b = blockIdx.z;
    const int q0 = blockIdx.x * 64;
    const size_t base = (size_t)b * T * D_MODEL + h * DKH;

    // ---- stage Q ----
    for (int idx = tid; idx < 64 * 8; idx += 128) {
        const int r = idx >> 3, c8 = idx & 7;
        *(uint4*)&Qs[r * 72 + c8 * 8] =
            *(const uint4*)(Q + base + (size_t)(q0 + r) * D_MODEL + c8 * 8);
    }
    __syncthreads();

    uint32_t qf[4][4];
    {
        const uint32_t* Qu = (const uint32_t*)Qs;
        const int r0 = wid * 16 + g;
#pragma unroll
        for (int kc = 0; kc < 4; kc++) {
            const int c = 8 * kc + tg;
            qf[kc][0] = Qu[r0 * AROW + c];
            qf[kc][1] = Qu[(r0 + 8) * AROW + c];
            qf[kc][2] = Qu[r0 * AROW + c + 4];
            qf[kc][3] = Qu[(r0 + 8) * AROW + c + 4];
        }
    }

    float oacc[8][4];
#pragma unroll
    for (int j = 0; j < 8; j++)
#pragma unroll
        for (int x = 0; x < 4; x++) oacc[j][x] = 0.f;
    float m0 = -1e30f, m1 = -1e30f, l0 = 0.f, l1 = 0.f;

    const int nkt = CAUSAL ? (blockIdx.x + 1) : (T / 64);
    for (int kt = 0; kt < nkt; kt++) {
        const int s0 = kt * 64;
        __syncthreads();
        for (int idx = tid; idx < 64 * 8; idx += 128) {
            const int r = idx >> 3, c8 = idx & 7;
            const size_t gaddr = base + (size_t)(s0 + r) * D_MODEL + c8 * 8;
            *(uint4*)&Ks[r * 72 + c8 * 8] = *(const uint4*)(K + gaddr);
            uint4 vv = *(const uint4*)(V + gaddr);
            const __half* hv = (const __half*)&vv;
#pragma unroll
            for (int q = 0; q < 8; q++)
                Vt[(c8 * 8 + q) * 72 + r] = hv[q];
        }
        __syncthreads();

        // ---- S = Q @ K^T ----
        float sacc[8][4];
#pragma unroll
        for (int j = 0; j < 8; j++)
#pragma unroll
            for (int x = 0; x < 4; x++) sacc[j][x] = 0.f;
        {
            const uint32_t* Ku = (const uint32_t*)Ks;
#pragma unroll
            for (int j = 0; j < 8; j++) {
                const int rb = (8 * j + g) * AROW + tg;
#pragma unroll
                for (int kc = 0; kc < 4; kc++) {
                    const uint32_t b0 = Ku[rb + 8 * kc];
                    const uint32_t b1 = Ku[rb + 8 * kc + 4];
                    mma16h(sacc[j], qf[kc][0], qf[kc][1], qf[kc][2], qf[kc][3],
                           b0, b1);
                }
            }
        }
        // scale 1/sqrt(64)
#pragma unroll
        for (int j = 0; j < 8; j++) {
            sacc[j][0] *= 0.125f; sacc[j][1] *= 0.125f;
            sacc[j][2] *= 0.125f; sacc[j][3] *= 0.125f;
        }

        if (CAUSAL && kt == blockIdx.x) {
            const int r0 = q0 + wid * 16 + g, r1 = r0 + 8;
#pragma unroll
            for (int j = 0; j < 8; j++) {
                const int c0 = s0 + 8 * j + 2 * tg, c1 = c0 + 1;
                if (c0 > r0) sacc[j][0] = -INFINITY;
                if (c1 > r0) sacc[j][1] = -INFINITY;
                if (c0 > r1) sacc[j][2] = -INFINITY;
                if (c1 > r1) sacc[j][3] = -INFINITY;
            }
        }

        float tm0 = -1e30f, tm1 = -1e30f;
#pragma unroll
        for (int j = 0; j < 8; j++) {
            tm0 = fmaxf(tm0, fmaxf(sacc[j][0], sacc[j][1]));
            tm1 = fmaxf(tm1, fmaxf(sacc[j][2], sacc[j][3]));
        }
        tm0 = fmaxf(tm0, __shfl_xor_sync(0xffffffffu, tm0, 1));
        tm0 = fmaxf(tm0, __shfl_xor_sync(0xffffffffu, tm0, 2));
        tm1 = fmaxf(tm1, __shfl_xor_sync(0xffffffffu, tm1, 1));
        tm1 = fmaxf(tm1, __shfl_xor_sync(0xffffffffu, tm1, 2));

        const float mn0 = fmaxf(m0, tm0), mn1 = fmaxf(m1, tm1);
        const float cr0 = __expf(m0 - mn0), cr1 = __expf(m1 - mn1);
        m0 = mn0; m1 = mn1;

        uint32_t ph[8][2];
        float ts0 = 0.f, ts1 = 0.f;
#pragma unroll
        for (int j = 0; j < 8; j++) {
            const float p0 = __expf(sacc[j][0] - mn0);
            const float p1 = __expf(sacc[j][1] - mn0);
            const float p2 = __expf(sacc[j][2] - mn1);
            const float p3 = __expf(sacc[j][3] - mn1);
            ts0 += p0 + p1; ts1 += p2 + p3;
            ph[j][0] = h2_as_u32(__floats2half2_rn(p0, p1));
            ph[j][1] = h2_as_u32(__floats2half2_rn(p2, p3));
        }
        ts0 += __shfl_xor_sync(0xffffffffu, ts0, 1);
        ts0 += __shfl_xor_sync(0xffffffffu, ts0, 2);
        ts1 += __shfl_xor_sync(0xffffffffu, ts1, 1);
        ts1 += __shfl_xor_sync(0xffffffffu, ts1, 2);
        l0 = l0 * cr0 + ts0;
        l1 = l1 * cr1 + ts1;

#pragma unroll
        for (int j = 0; j < 8; j++) {
            oacc[j][0] *= cr0; oacc[j][1] *= cr0;
            oacc[j][2] *= cr1; oacc[j][3] *= cr1;
        }

        // ---- O += P @ V ----
        {
            const uint32_t* Vu = (const uint32_t*)Vt;
#pragma unroll
            for (int j = 0; j < 8; j++) {
                const int rb = (8 * j + g) * AROW + tg;
#pragma unroll
                for (int kc = 0; kc < 4; kc++) {
                    const uint32_t b0 = Vu[rb + 8 * kc];
                    const uint32_t b1 = Vu[rb + 8 * kc + 4];
                    mma16h(oacc[j], ph[2 * kc][0], ph[2 * kc][1],
                           ph[2 * kc + 1][0], ph[2 * kc + 1][1], b0, b1);
                }
            }
        }
    }

    const float inv0 = 1.f / l0, inv1 = 1.f / l1;
    const int r0 = q0 + wid * 16 + g;
#pragma unroll
    for (int j = 0; j < 8; j++) {
        const int col = 8 * j + 2 * tg;
        *(__half2*)(O + base + (size_t)r0 * D_MODEL + col) =
            __floats2half2_rn(oacc[j][0] * inv0, oacc[j][1] * inv0);
        *(__half2*)(O + base + (size_t)(r0 + 8) * D_MODEL + col) =
            __floats2half2_rn(oacc[j][2] * inv1, oacc[j][3] * inv1);
    }
}

// ---------------- residual add + LayerNorm (fp32, optional fp16 mirror) -----
__inline__ __device__ float warpSum(float v) {
#pragma unroll
    for (int o = 16; o > 0; o >>= 1) v += __shfl_xor_sync(0xffffffffu, v, o);
    return v;
}

__global__ __launch_bounds__(256) void add_ln_kernel(
    const float* __restrict__ res, const float* __restrict__ y,
    const float* __restrict__ gamma, const float* __restrict__ beta,
    float* __restrict__ out, __half* __restrict__ outh)
{
    const int row = blockIdx.x;
    const int i = threadIdx.x;
    const float4 a  = ((const float4*)(res + (size_t)row * D_MODEL))[i];
    const float4 b4 = ((const float4*)(y   + (size_t)row * D_MODEL))[i];
    const float x0 = a.x + b4.x, x1 = a.y + b4.y, x2 = a.z + b4.z, x3 = a.w + b4.w;

    float s  = x0 + x1 + x2 + x3;
    float sq = x0 * x0 + x1 * x1 + x2 * x2 + x3 * x3;
    s = warpSum(s); sq = warpSum(sq);

    __shared__ float sh[2][8];
    const int w = threadIdx.x >> 5, l = threadIdx.x & 31;
    if (l == 0) { sh[0][w] = s; sh[1][w] = sq; }
    __syncthreads();
    if (threadIdx.x < 32) {
        float aa = (l < 8) ? sh[0][l] : 0.f;
        float bb = (l < 8) ? sh[1][l] : 0.f;
        aa = warpSum(aa); bb = warpSum(bb);
        if (l == 0) { sh[0][0] = aa; sh[1][0] = bb; }
    }
    __syncthreads();
    const float mean = sh[0][0] * (1.f / D_MODEL);
    const float var  = sh[1][0] * (1.f / D_MODEL) - mean * mean;
    const float rinv = rsqrtf(var + 1e-5f);

    const float4 gm = ((const float4*)gamma)[i];
    const float4 be = ((const float4*)beta)[i];
    float4 o;
    o.x = (x0 - mean) * rinv * gm.x + be.x;
    o.y = (x1 - mean) * rinv * gm.y + be.y;
    o.z = (x2 - mean) * rinv * gm.z + be.z;
    o.w = (x3 - mean) * rinv * gm.w + be.w;
    ((float4*)(out + (size_t)row * D_MODEL))[i] = o;
    if (outh) {
        uint2 oh;
        oh.x = h2_as_u32(__floats2half2_rn(o.x, o.y));
        oh.y = h2_as_u32(__floats2half2_rn(o.z, o.w));
        ((uint2*)(outh + (size_t)row * D_MODEL))[i] = oh;
    }
}

// ---------------- launch ----------------------------------------------------
extern "C" void kernel_launch(void* const* d_in, const int* in_sizes, int n_in,
                              void* d_out, int out_size)
{
    const float* dec  = (const float*)d_in[0];
    const float* enc  = (const float*)d_in[1];
    const float* Wq_s = (const float*)d_in[2];
    const float* bq_s = (const float*)d_in[3];
    const float* Wk_s = (const float*)d_in[4];
    const float* bk_s = (const float*)d_in[5];
    const float* Wv_s = (const float*)d_in[6];
    const float* bv_s = (const float*)d_in[7];
    const float* Wo_s = (const float*)d_in[8];
    const float* bo_s = (const float*)d_in[9];
    const float* Wq_c = (const float*)d_in[10];
    const float* bq_c = (const float*)d_in[11];
    const float* Wk_c = (const float*)d_in[12];
    const float* bk_c = (const float*)d_in[13];
    const float* Wv_c = (const float*)d_in[14];
    const float* bv_c = (const float*)d_in[15];
    const float* Wo_c = (const float*)d_in[16];
    const float* bo_c = (const float*)d_in[17];
    const float* W1   = (const float*)d_in[18];
    const float* b1   = (const float*)d_in[19];
    const float* W2   = (const float*)d_in[20];
    const float* b2   = (const float*)d_in[21];
    const float* g1   = (const float*)d_in[22];
    const float* be1  = (const float*)d_in[23];
    const float* g2   = (const float*)d_in[24];
    const float* be2  = (const float*)d_in[25];
    const float* g3   = (const float*)d_in[26];
    const float* be3  = (const float*)d_in[27];

    float *Qf, *Kf, *Vf, *Af, *X1, *X2, *Tm, *Fbuf, *Wbuf;
    cudaGetSymbolAddress((void**)&Qf, g_Q);
    cudaGetSymbolAddress((void**)&Kf, g_K);
    cudaGetSymbolAddress((void**)&Vf, g_V);
    cudaGetSymbolAddress((void**)&Af, g_attn);
    cudaGetSymbolAddress((void**)&X1, g_x1);
    cudaGetSymbolAddress((void**)&X2, g_x2);
    cudaGetSymbolAddress((void**)&Tm, g_tmp);
    cudaGetSymbolAddress((void**)&Fbuf, g_ffn);
    cudaGetSymbolAddress((void**)&Wbuf, g_Wt);

    __half* Qh    = (__half*)Qf;
    __half* Kh    = (__half*)Kf;
    __half* Vh    = (__half*)Vf;
    __half* Ath   = (__half*)Af;
    __half* dec_h = (__half*)Fbuf;                                   // 8MB
    __half* enc_h = (__half*)(Fbuf + (size_t)2 * 1024 * 1024);       // next 8MB
    __half* Ffh   = (__half*)(Fbuf + (size_t)8 * 1024 * 1024);       // 32MB region
    __half* Wth   = (__half*)Wbuf;                                   // 8.4MB
    __half* Xh    = (__half*)(Wbuf + (size_t)(D_FF / 2) * D_MODEL);  // back half

    cudaFuncSetAttribute(gemm_h, cudaFuncAttributeMaxDynamicSharedMemorySize, G_SMEM);

    const dim3 tb(32, 8);
    const dim3 gHead(D_MODEL / 32, DKH / 32, N_HEADS);
    const dim3 gFlatDD(D_MODEL / 32, D_MODEL / 32);
    const dim3 gD(D_MODEL / 128, MROWS / 256);   // (8, 16) = 128 CTAs
    const dim3 gF(D_FF / 128,   MROWS / 256);    // (32, 16)
    const dim3 gA(TT / 64, N_HEADS, BB);
    const int NC4 = MROWS * D_MODEL / 4;

    h_copy<<<(NC4 + 255) / 256, 256>>>(dec, dec_h, NC4);
    h_copy<<<(NC4 + 255) / 256, 256>>>(enc, enc_h, NC4);

    // ---- self-attention block ----
    transpose_head<<<gHead, tb>>>(Wq_s, Wth, D_MODEL);
    gemm_h<<<gD, 256, G_SMEM>>>(MROWS, D_MODEL, D_MODEL, dec_h, Wth, bq_s, Qh, 0, 1);
    transpose_head<<<gHead, tb>>>(Wk_s, Wth, D_MODEL);
    gemm_h<<<gD, 256, G_SMEM>>>(MROWS, D_MODEL, D_MODEL, dec_h, Wth, bk_s, Kh, 0, 1);
    transpose_head<<<gHead, tb>>>(Wv_s, Wth, D_MODEL);
    gemm_h<<<gD, 256, G_SMEM>>>(MROWS, D_MODEL, D_MODEL, dec_h, Wth, bv_s, Vh, 0, 1);
    attn_mma<true><<<gA, 128>>>(Qh, Kh, Vh, Ath, TT);
    transpose_flat<<<gFlatDD, tb>>>(Wo_s, Wth, D_MODEL, D_MODEL);
    gemm_h<<<gD, 256, G_SMEM>>>(MROWS, D_MODEL, D_MODEL, Ath, Wth, bo_s, Tm, 0, 0);
    add_ln_kernel<<<MROWS, 256>>>(dec, Tm, g1, be1, X1, Xh);

    // ---- cross-attention block ----
    transpose_head<<<gHead, tb>>>(Wq_c, Wth, D_MODEL);
    gemm_h<<<gD, 256, G_SMEM>>>(MROWS, D_MODEL, D_MODEL, Xh, Wth, bq_c, Qh, 0, 1);
    transpose_head<<<gHead, tb>>>(Wk_c, Wth, D_MODEL);
    gemm_h<<<gD, 256, G_SMEM>>>(MROWS, D_MODEL, D_MODEL, enc_h, Wth, bk_c, Kh, 0, 1);
    transpose_head<<<gHead, tb>>>(Wv_c, Wth, D_MODEL);
    gemm_h<<<gD, 256, G_SMEM>>>(MROWS, D_MODEL, D_MODEL, enc_h, Wth, bv_c, Vh, 0, 1);
    attn_mma<false><<<gA, 128>>>(Qh, Kh, Vh, Ath, TT);
    transpose_flat<<<gFlatDD, tb>>>(Wo_c, Wth, D_MODEL, D_MODEL);
    gemm_h<<<gD, 256, G_SMEM>>>(MROWS, D_MODEL, D_MODEL, Ath, Wth, bo_c, Tm, 0, 0);
    add_ln_kernel<<<MROWS, 256>>>(X1, Tm, g2, be2, X2, Xh);

    // ---- FFN block ----
    transpose_flat<<<dim3(D_MODEL / 32, D_FF / 32), tb>>>(W1, Wth, D_MODEL, D_FF);
    gemm_h<<<gF, 256, G_SMEM>>>(MROWS, D_FF, D_MODEL, Xh, Wth, b1, Ffh, 1, 1);
    transpose_flat<<<dim3(D_FF / 32, D_MODEL / 32), tb>>>(W2, Wth, D_FF, D_MODEL);
    gemm_h<<<gD, 256, G_SMEM>>>(MROWS, D_MODEL, D_FF, Ffh, Wth, b2, Tm, 0, 0);
    add_ln_kernel<<<MROWS, 256>>>(X2, Tm, g3, be3, (float*)d_out, (__half*)nullptr);
}

// round 10
// speedup vs baseline: 5.2864x; 1.0238x over previous
#include <cuda_runtime.h>
#include <cuda_bf16.h>
#include <cuda_fp16.h>
#include <cstdint>
#include <cstddef>
#include <math.h>

#define D_MODEL 1024
#define N_HEADS 16
#define DKH     64
#define D_FF    4096
#define BB      2
#define TT      2048
#define MROWS   (BB * TT)   // 4096

// ---------------- scratch (device globals; no runtime allocation) -----------
// layout (as halves unless noted):
// g_Q   : dec_h (4M) | enc_h (4M)
// g_K   : Qh_cross (4M) | free
// g_V   : KVbuf_cross (8M halves, ld 2048)
// g_attn: Ath (4M) | biasQKV (3072 f32) | biasKV (2048 f32)
// g_x1/g_x2/g_tmp : fp32 activations
// g_ffn : QKVbuf_self (12M halves, ld 3072) | Ffh (16M halves)
// g_Wt  : Wth (<=4M halves) | Xh (4M halves)
__device__ float g_Q   [MROWS * D_MODEL];
__device__ float g_K   [MROWS * D_MODEL];
__device__ float g_V   [MROWS * D_MODEL];
__device__ float g_attn[MROWS * D_MODEL];
__device__ float g_x1  [MROWS * D_MODEL];
__device__ float g_x2  [MROWS * D_MODEL];
__device__ float g_tmp [MROWS * D_MODEL];
__device__ float g_ffn [MROWS * D_FF];
__device__ float g_Wt  [D_FF * D_MODEL];

// ======================= helpers ============================================
__device__ __forceinline__ uint32_t h2_as_u32(__half2 h) {
    union { __half2 h; uint32_t u; } cvt;
    cvt.h = h;
    return cvt.u;
}

__device__ __forceinline__ void cpa8(uint32_t dst, const void* src) {
    asm volatile("cp.async.ca.shared.global [%0], [%1], 8;\n"
                 :: "r"(dst), "l"(src) : "memory");
}
#define CP_COMMIT() asm volatile("cp.async.commit_group;\n" ::: "memory")
#define CP_WAIT(n)  asm volatile("cp.async.wait_group %0;\n" :: "n"(n) : "memory")

__device__ __forceinline__ uint32_t smem_u32(const void* p) {
    uint32_t a;
    asm("{ .reg .u64 t; cvta.to.shared.u64 t, %1; cvt.u32.u64 %0, t; }"
        : "=r"(a) : "l"(p));
    return a;
}

__device__ __forceinline__ void mma16h(float* c, uint32_t a0, uint32_t a1,
                                       uint32_t a2, uint32_t a3,
                                       uint32_t b0, uint32_t b1) {
    asm volatile(
        "mma.sync.aligned.m16n8k16.row.col.f32.f16.f16.f32 "
        "{%0,%1,%2,%3}, {%4,%5,%6,%7}, {%8,%9}, {%0,%1,%2,%3};"
        : "+f"(c[0]), "+f"(c[1]), "+f"(c[2]), "+f"(c[3])
        : "r"(a0), "r"(a1), "r"(a2), "r"(a3), "r"(b0), "r"(b1));
}

__device__ __forceinline__ void lsm4(uint32_t* r, uint32_t addr) {
    asm volatile("ldmatrix.sync.aligned.m8n8.x4.shared.b16 {%0,%1,%2,%3}, [%4];"
                 : "=r"(r[0]), "=r"(r[1]), "=r"(r[2]), "=r"(r[3]) : "r"(addr));
}

// =============== fp16 mma GEMM: C = A[M,K] @ Wt^T + bias ====================
// A, Wt: half, K-major rows. Block tile 256x128, 256 thr, warp tile 64x64.
// SMEM row stride 80B; ldmatrix row-starts at banks 20r mod 32: conflict-free.
#define G_STAGEB 30720            // (256+128) rows * 80B
#define G_BOFF  20480             // B region byte offset (256*80)
#define G_NSTG 3
#define G_SMEM (G_NSTG * G_STAGEB)  // 92160

__global__ __launch_bounds__(256, 1)
void gemm_h(int M, int N, int K,
            const __half* __restrict__ A, const __half* __restrict__ Wt,
            const float* __restrict__ bias, void* __restrict__ C,
            int relu, int outHalf)
{
    extern __shared__ char smc[];
    const uint32_t sb = smem_u32(smc);

    const int tid = threadIdx.x;
    const int wid = tid >> 5, lid = tid & 31;
    const int g = lid >> 2, tg = lid & 3;
    const int wm = wid >> 1, wn = wid & 1;   // 4 x 2 warp grid

    const int bRow = blockIdx.y * 256, bCol = blockIdx.x * 128;
    const int NT = K >> 5;                    // BK = 32 halves

    float acc[4][8][4];
#pragma unroll
    for (int m = 0; m < 4; m++)
#pragma unroll
        for (int n = 0; n < 8; n++)
#pragma unroll
            for (int x = 0; x < 4; x++) acc[m][n][x] = 0.f;

    const int arow = tid >> 3, ac = (tid & 7) * 4;   // loader indices (halves)

    auto load_stage = [&](int it, int s) {
        const uint32_t base = sb + s * G_STAGEB;
        const __half* as = A  + (size_t)(bRow + arow) * K + it * 32 + ac;
        const __half* bs = Wt + (size_t)(bCol + arow) * K + it * 32 + ac;
#pragma unroll
        for (int j = 0; j < 8; j++)
            cpa8(base + (arow + 32 * j) * 80 + ac * 2, as + (size_t)(32 * j) * K);
#pragma unroll
        for (int j = 0; j < 4; j++)
            cpa8(base + G_BOFF + (arow + 32 * j) * 80 + ac * 2,
                 bs + (size_t)(32 * j) * K);
    };

    // per-lane ldmatrix base offsets (bytes within a stage)
    const uint32_t aoff = (uint32_t)((wm * 64 + (lid & 7) + ((lid >> 3) & 1) * 8) * 80
                                     + (lid >> 4) * 16);
    const uint32_t boff = (uint32_t)(G_BOFF
                                     + (wn * 64 + (lid & 7) + (lid >> 4) * 8) * 80
                                     + ((lid >> 3) & 1) * 16);

    load_stage(0, 0); CP_COMMIT();
    load_stage(1, 1); CP_COMMIT();

    for (int i = 0; i < NT; i++) {
        CP_WAIT(1);
        __syncthreads();
        const int pre = i + 2;
        if (pre < NT) load_stage(pre, pre % G_NSTG);
        CP_COMMIT();

        const uint32_t buf = sb + (i % G_NSTG) * G_STAGEB;
#pragma unroll
        for (int ks = 0; ks < 2; ks++) {
            uint32_t a[4][4];
#pragma unroll
            for (int mt = 0; mt < 4; mt++)
                lsm4(a[mt], buf + aoff + mt * 16 * 80 + ks * 32);
#pragma unroll
            for (int p = 0; p < 4; p++) {
                uint32_t b[4];
                lsm4(b, buf + boff + p * 16 * 80 + ks * 32);
#pragma unroll
                for (int mt = 0; mt < 4; mt++) {
                    mma16h(acc[mt][2 * p],     a[mt][0], a[mt][1], a[mt][2],
                           a[mt][3], b[0], b[1]);
                    mma16h(acc[mt][2 * p + 1], a[mt][0], a[mt][1], a[mt][2],
                           a[mt][3], b[2], b[3]);
                }
            }
        }
    }

    // epilogue
    float* Cf = (float*)C;
    __half* Ch = (__half*)C;
#pragma unroll
    for (int mt = 0; mt < 4; mt++) {
        const int r0 = bRow + wm * 64 + mt * 16 + g;
#pragma unroll
        for (int nt = 0; nt < 8; nt++) {
            const int col = bCol + wn * 64 + nt * 8 + 2 * tg;
            const float bi0 = bias[col], bi1 = bias[col + 1];
            float v0 = acc[mt][nt][0] + bi0, v1 = acc[mt][nt][1] + bi1;
            float v2 = acc[mt][nt][2] + bi0, v3 = acc[mt][nt][3] + bi1;
            if (relu) {
                v0 = fmaxf(v0, 0.f); v1 = fmaxf(v1, 0.f);
                v2 = fmaxf(v2, 0.f); v3 = fmaxf(v3, 0.f);
            }
            if (outHalf) {
                *(__half2*)(Ch + (size_t)r0 * N + col) =
                    __floats2half2_rn(v0, v1);
                *(__half2*)(Ch + (size_t)(r0 + 8) * N + col) =
                    __floats2half2_rn(v2, v3);
            } else {
                *(float2*)(Cf + (size_t)r0 * N + col) = make_float2(v0, v1);
                *(float2*)(Cf + (size_t)(r0 + 8) * N + col) = make_float2(v2, v3);
            }
        }
    }
}

// ---------------- weight transposes (to K-major fp16) -----------------------
__global__ __launch_bounds__(256) void transpose_flat(
    const float* __restrict__ W, __half* __restrict__ Wt, int K, int N)
{
    __shared__ float t[32][33];
    const int k0 = blockIdx.x * 32, n0 = blockIdx.y * 32;
    const int x = threadIdx.x, y = threadIdx.y;
#pragma unroll
    for (int j = 0; j < 32; j += 8) t[y + j][x] = W[(size_t)(k0 + y + j) * N + n0 + x];
    __syncthreads();
#pragma unroll
    for (int j = 0; j < 32; j += 8)
        Wt[(size_t)(n0 + y + j) * K + k0 + x] = __float2half_rn(t[x][y + j]);
}

__global__ __launch_bounds__(256) void transpose_head(
    const float* __restrict__ W, __half* __restrict__ Wt, int K)
{
    __shared__ float t[32][33];
    const int h = blockIdx.z;
    const int k0 = blockIdx.x * 32, d0 = blockIdx.y * 32;
    const float* Wh = W  + (size_t)h * K * 64;
    __half*      Wo = Wt + (size_t)h * 64 * K;
    const int x = threadIdx.x, y = threadIdx.y;
#pragma unroll
    for (int j = 0; j < 32; j += 8) t[y + j][x] = Wh[(size_t)(k0 + y + j) * 64 + d0 + x];
    __syncthreads();
#pragma unroll
    for (int j = 0; j < 32; j += 8)
        Wo[(size_t)(d0 + y + j) * K + k0 + x] = __float2half_rn(t[x][y + j]);
}

// ---------------- small utils ----------------------------------------------
__global__ __launch_bounds__(256) void h_copy(
    const float* __restrict__ in, __half* __restrict__ out, int n4)
{
    const int i = blockIdx.x * blockDim.x + threadIdx.x;
    if (i < n4) {
        float4 v = ((const float4*)in)[i];
        uint2 o;
        o.x = h2_as_u32(__floats2half2_rn(v.x, v.y));
        o.y = h2_as_u32(__floats2half2_rn(v.z, v.w));
        ((uint2*)out)[i] = o;
    }
}

__global__ void cat_bias3(const float* a, const float* b, const float* c,
                          float* o)
{
    const int i = blockIdx.x * blockDim.x + threadIdx.x;
    if (i < 1024) o[i] = a[i];
    else if (i < 2048) o[i] = b[i - 1024];
    else if (i < 3072) o[i] = c[i - 2048];
}

__global__ void cat_bias2(const float* a, const float* b, float* o)
{
    const int i = blockIdx.x * blockDim.x + threadIdx.x;
    if (i < 1024) o[i] = a[i];
    else if (i < 2048) o[i] = b[i - 1024];
}

// ========== flash attention, fp16 I/O, fp16 mma.sync ========================
#define AROW 36   // b32 words per smem row (72 halves)

template<bool CAUSAL>
__global__ __launch_bounds__(128) void attn_mma(
    const __half* __restrict__ Q, const __half* __restrict__ K,
    const __half* __restrict__ V, __half* __restrict__ O,
    int T, int ldq, int ldkv)
{
    __shared__ __align__(16) __half Qs[64 * 72];
    __shared__ __align__(16) __half Ks[64 * 72];
    __shared__ __align__(16) __half Vt[64 * 72];

    const int tid = threadIdx.x, wid = tid >> 5, lid = tid & 31;
    const int g = lid >> 2, tg = lid & 3;
    const int h = blockIdx.y, b = blockIdx.z;
    const int q0 = blockIdx.x * 64;
    const size_t qbase  = (size_t)b * T * ldq  + h * DKH;
    const size_t kvbase = (size_t)b * T * ldkv + h * DKH;
    const size_t obase  = (size_t)b * T * D_MODEL + h * DKH;

    // ---- stage Q ----
    for (int idx = tid; idx < 64 * 8; idx += 128) {
        const int r = idx >> 3, c8 = idx & 7;
        *(uint4*)&Qs[r * 72 + c8 * 8] =
            *(const uint4*)(Q + qbase + (size_t)(q0 + r) * ldq + c8 * 8);
    }
    __syncthreads();

    uint32_t qf[4][4];
    {
        const uint32_t* Qu = (const uint32_t*)Qs;
        const int r0 = wid * 16 + g;
#pragma unroll
        for (int kc = 0; kc < 4; kc++) {
            const int c = 8 * kc + tg;
            qf[kc][0] = Qu[r0 * AROW + c];
            qf[kc][1] = Qu[(r0 + 8) * AROW + c];
            qf[kc][2] = Qu[r0 * AROW + c + 4];
            qf[kc][3] = Qu[(r0 + 8) * AROW + c + 4];
        }
    }

    float oacc[8][4];
#pragma unroll
    for (int j = 0; j < 8; j++)
#pragma unroll
        for (int x = 0; x < 4; x++) oacc[j][x] = 0.f;
    float m0 = -1e30f, m1 = -1e30f, l0 = 0.f, l1 = 0.f;

    const int nkt = CAUSAL ? (blockIdx.x + 1) : (T / 64);
    for (int kt = 0; kt < nkt; kt++) {
        const int s0 = kt * 64;
        __syncthreads();
        for (int idx = tid; idx < 64 * 8; idx += 128) {
            const int r = idx >> 3, c8 = idx & 7;
            const size_t gaddr = kvbase + (size_t)(s0 + r) * ldkv + c8 * 8;
            *(uint4*)&Ks[r * 72 + c8 * 8] = *(const uint4*)(K + gaddr);
            uint4 vv = *(const uint4*)(V + gaddr);
            const __half* hv = (const __half*)&vv;
#pragma unroll
            for (int q = 0; q < 8; q++)
                Vt[(c8 * 8 + q) * 72 + r] = hv[q];
        }
        __syncthreads();

        // ---- S = Q @ K^T ----
        float sacc[8][4];
#pragma unroll
        for (int j = 0; j < 8; j++)
#pragma unroll
            for (int x = 0; x < 4; x++) sacc[j][x] = 0.f;
        {
            const uint32_t* Ku = (const uint32_t*)Ks;
#pragma unroll
            for (int j = 0; j < 8; j++) {
                const int rb = (8 * j + g) * AROW + tg;
#pragma unroll
                for (int kc = 0; kc < 4; kc++) {
                    const uint32_t b0 = Ku[rb + 8 * kc];
                    const uint32_t b1 = Ku[rb + 8 * kc + 4];
                    mma16h(sacc[j], qf[kc][0], qf[kc][1], qf[kc][2], qf[kc][3],
                           b0, b1);
                }
            }
        }
#pragma unroll
        for (int j = 0; j < 8; j++) {
            sacc[j][0] *= 0.125f; sacc[j][1] *= 0.125f;
            sacc[j][2] *= 0.125f; sacc[j][3] *= 0.125f;
        }

        if (CAUSAL && kt == blockIdx.x) {
            const int r0 = q0 + wid * 16 + g, r1 = r0 + 8;
#pragma unroll
            for (int j = 0; j < 8; j++) {
                const int c0 = s0 + 8 * j + 2 * tg, c1 = c0 + 1;
                if (c0 > r0) sacc[j][0] = -INFINITY;
                if (c1 > r0) sacc[j][1] = -INFINITY;
                if (c0 > r1) sacc[j][2] = -INFINITY;
                if (c1 > r1) sacc[j][3] = -INFINITY;
            }
        }

        float tm0 = -1e30f, tm1 = -1e30f;
#pragma unroll
        for (int j = 0; j < 8; j++) {
            tm0 = fmaxf(tm0, fmaxf(sacc[j][0], sacc[j][1]));
            tm1 = fmaxf(tm1, fmaxf(sacc[j][2], sacc[j][3]));
        }
        tm0 = fmaxf(tm0, __shfl_xor_sync(0xffffffffu, tm0, 1));
        tm0 = fmaxf(tm0, __shfl_xor_sync(0xffffffffu, tm0, 2));
        tm1 = fmaxf(tm1, __shfl_xor_sync(0xffffffffu, tm1, 1));
        tm1 = fmaxf(tm1, __shfl_xor_sync(0xffffffffu, tm1, 2));

        const float mn0 = fmaxf(m0, tm0), mn1 = fmaxf(m1, tm1);
        const float cr0 = __expf(m0 - mn0), cr1 = __expf(m1 - mn1);
        m0 = mn0; m1 = mn1;

        uint32_t ph[8][2];
        float ts0 = 0.f, ts1 = 0.f;
#pragma unroll
        for (int j = 0; j < 8; j++) {
            const float p0 = __expf(sacc[j][0] - mn0);
            const float p1 = __expf(sacc[j][1] - mn0);
            const float p2 = __expf(sacc[j][2] - mn1);
            const float p3 = __expf(sacc[j][3] - mn1);
            ts0 += p0 + p1; ts1 += p2 + p3;
            ph[j][0] = h2_as_u32(__floats2half2_rn(p0, p1));
            ph[j][1] = h2_as_u32(__floats2half2_rn(p2, p3));
        }
        ts0 += __shfl_xor_sync(0xffffffffu, ts0, 1);
        ts0 += __shfl_xor_sync(0xffffffffu, ts0, 2);
        ts1 += __shfl_xor_sync(0xffffffffu, ts1, 1);
        ts1 += __shfl_xor_sync(0xffffffffu, ts1, 2);
        l0 = l0 * cr0 + ts0;
        l1 = l1 * cr1 + ts1;

#pragma unroll
        for (int j = 0; j < 8; j++) {
            oacc[j][0] *= cr0; oacc[j][1] *= cr0;
            oacc[j][2] *= cr1; oacc[j][3] *= cr1;
        }

        // ---- O += P @ V ----
        {
            const uint32_t* Vu = (const uint32_t*)Vt;
#pragma unroll
            for (int j = 0; j < 8; j++) {
                const int rb = (8 * j + g) * AROW + tg;
#pragma unroll
                for (int kc = 0; kc < 4; kc++) {
                    const uint32_t b0 = Vu[rb + 8 * kc];
                    const uint32_t b1 = Vu[rb + 8 * kc + 4];
                    mma16h(oacc[j], ph[2 * kc][0], ph[2 * kc][1],
                           ph[2 * kc + 1][0], ph[2 * kc + 1][1], b0, b1);
                }
            }
        }
    }

    const float inv0 = 1.f / l0, inv1 = 1.f / l1;
    const int r0 = q0 + wid * 16 + g;
#pragma unroll
    for (int j = 0; j < 8; j++) {
        const int col = 8 * j + 2 * tg;
        *(__half2*)(O + obase + (size_t)r0 * D_MODEL + col) =
            __floats2half2_rn(oacc[j][0] * inv0, oacc[j][1] * inv0);
        *(__half2*)(O + obase + (size_t)(r0 + 8) * D_MODEL + col) =
            __floats2half2_rn(oacc[j][2] * inv1, oacc[j][3] * inv1);
    }
}

// ---------------- residual add + LayerNorm (fp32, optional fp16 mirror) -----
__inline__ __device__ float warpSum(float v) {
#pragma unroll
    for (int o = 16; o > 0; o >>= 1) v += __shfl_xor_sync(0xffffffffu, v, o);
    return v;
}

__global__ __launch_bounds__(256) void add_ln_kernel(
    const float* __restrict__ res, const float* __restrict__ y,
    const float* __restrict__ gamma, const float* __restrict__ beta,
    float* __restrict__ out, __half* __restrict__ outh)
{
    const int row = blockIdx.x;
    const int i = threadIdx.x;
    const float4 a  = ((const float4*)(res + (size_t)row * D_MODEL))[i];
    const float4 b4 = ((const float4*)(y   + (size_t)row * D_MODEL))[i];
    const float x0 = a.x + b4.x, x1 = a.y + b4.y, x2 = a.z + b4.z, x3 = a.w + b4.w;

    float s  = x0 + x1 + x2 + x3;
    float sq = x0 * x0 + x1 * x1 + x2 * x2 + x3 * x3;
    s = warpSum(s); sq = warpSum(sq);

    __shared__ float sh[2][8];
    const int w = threadIdx.x >> 5, l = threadIdx.x & 31;
    if (l == 0) { sh[0][w] = s; sh[1][w] = sq; }
    __syncthreads();
    if (threadIdx.x < 32) {
        float aa = (l < 8) ? sh[0][l] : 0.f;
        float bb = (l < 8) ? sh[1][l] : 0.f;
        aa = warpSum(aa); bb = warpSum(bb);
        if (l == 0) { sh[0][0] = aa; sh[1][0] = bb; }
    }
    __syncthreads();
    const float mean = sh[0][0] * (1.f / D_MODEL);
    const float var  = sh[1][0] * (1.f / D_MODEL) - mean * mean;
    const float rinv = rsqrtf(var + 1e-5f);

    const float4 gm = ((const float4*)gamma)[i];
    const float4 be = ((const float4*)beta)[i];
    float4 o;
    o.x = (x0 - mean) * rinv * gm.x + be.x;
    o.y = (x1 - mean) * rinv * gm.y + be.y;
    o.z = (x2 - mean) * rinv * gm.z + be.z;
    o.w = (x3 - mean) * rinv * gm.w + be.w;
    ((float4*)(out + (size_t)row * D_MODEL))[i] = o;
    if (outh) {
        uint2 oh;
        oh.x = h2_as_u32(__floats2half2_rn(o.x, o.y));
        oh.y = h2_as_u32(__floats2half2_rn(o.z, o.w));
        ((uint2*)(outh + (size_t)row * D_MODEL))[i] = oh;
    }
}

// ---------------- launch ----------------------------------------------------
extern "C" void kernel_launch(void* const* d_in, const int* in_sizes, int n_in,
                              void* d_out, int out_size)
{
    const float* dec  = (const float*)d_in[0];
    const float* enc  = (const float*)d_in[1];
    const float* Wq_s = (const float*)d_in[2];
    const float* bq_s = (const float*)d_in[3];
    const float* Wk_s = (const float*)d_in[4];
    const float* bk_s = (const float*)d_in[5];
    const float* Wv_s = (const float*)d_in[6];
    const float* bv_s = (const float*)d_in[7];
    const float* Wo_s = (const float*)d_in[8];
    const float* bo_s = (const float*)d_in[9];
    const float* Wq_c = (const float*)d_in[10];
    const float* bq_c = (const float*)d_in[11];
    const float* Wk_c = (const float*)d_in[12];
    const float* bk_c = (const float*)d_in[13];
    const float* Wv_c = (const float*)d_in[14];
    const float* bv_c = (const float*)d_in[15];
    const float* Wo_c = (const float*)d_in[16];
    const float* bo_c = (const float*)d_in[17];
    const float* W1   = (const float*)d_in[18];
    const float* b1   = (const float*)d_in[19];
    const float* W2   = (const float*)d_in[20];
    const float* b2   = (const float*)d_in[21];
    const float* g1   = (const float*)d_in[22];
    const float* be1  = (const float*)d_in[23];
    const float* g2   = (const float*)d_in[24];
    const float* be2  = (const float*)d_in[25];
    const float* g3   = (const float*)d_in[26];
    const float* be3  = (const float*)d_in[27];

    float *Qf, *Kf, *Vf, *Af, *X1, *X2, *Tm, *Fbuf, *Wbuf;
    cudaGetSymbolAddress((void**)&Qf, g_Q);
    cudaGetSymbolAddress((void**)&Kf, g_K);
    cudaGetSymbolAddress((void**)&Vf, g_V);
    cudaGetSymbolAddress((void**)&Af, g_attn);
    cudaGetSymbolAddress((void**)&X1, g_x1);
    cudaGetSymbolAddress((void**)&X2, g_x2);
    cudaGetSymbolAddress((void**)&Tm, g_tmp);
    cudaGetSymbolAddress((void**)&Fbuf, g_ffn);
    cudaGetSymbolAddress((void**)&Wbuf, g_Wt);

    const size_t NE = (size_t)MROWS * D_MODEL;        // 4M
    __half* dec_h = (__half*)Qf;                      // 4M halves
    __half* enc_h = dec_h + NE;                       // 4M halves
    __half* Qhc   = (__half*)Kf;                      // cross-Q, 4M halves
    __half* KVc   = (__half*)Vf;                      // cross-KV, 8M halves (ld 2048)
    __half* Ath   = (__half*)Af;                      // 4M halves
    float*  biasQ = (float*)(Ath + NE);               // 3072 f32
    float*  biasK = biasQ + 4096;                     // 2048 f32
    __half* QKV   = (__half*)Fbuf;                    // 12M halves (ld 3072)
    __half* Ffh   = QKV + (size_t)MROWS * 3072;       // 16M halves
    __half* Wth   = (__half*)Wbuf;                    // up to 4M halves
    __half* Xh    = Wth + (size_t)D_FF * D_MODEL;     // 4M halves

    cudaFuncSetAttribute(gemm_h, cudaFuncAttributeMaxDynamicSharedMemorySize, G_SMEM);

    const dim3 tb(32, 8);
    const dim3 gHead(D_MODEL / 32, DKH / 32, N_HEADS);
    const dim3 gFlatDD(D_MODEL / 32, D_MODEL / 32);
    const dim3 gD (D_MODEL / 128, MROWS / 256);   // (8, 16)
    const dim3 gD3(3 * D_MODEL / 128, MROWS / 256); // (24, 16)
    const dim3 gD2(2 * D_MODEL / 128, MROWS / 256); // (16, 16)
    const dim3 gF (D_FF / 128,   MROWS / 256);    // (32, 16)
    const dim3 gA(TT / 64, N_HEADS, BB);
    const int NC4 = MROWS * D_MODEL / 4;

    h_copy<<<(NC4 + 255) / 256, 256>>>(dec, dec_h, NC4);
    h_copy<<<(NC4 + 255) / 256, 256>>>(enc, enc_h, NC4);
    cat_bias3<<<12, 256>>>(bq_s, bk_s, bv_s, biasQ);
    cat_bias2<<<8, 256>>>(bk_c, bv_c, biasK);

    // ---- self-attention block ----
    transpose_head<<<gHead, tb>>>(Wq_s, Wth, D_MODEL);
    transpose_head<<<gHead, tb>>>(Wk_s, Wth + (size_t)D_MODEL * D_MODEL, D_MODEL);
    transpose_head<<<gHead, tb>>>(Wv_s, Wth + (size_t)2 * D_MODEL * D_MODEL, D_MODEL);
    gemm_h<<<gD3, 256, G_SMEM>>>(MROWS, 3 * D_MODEL, D_MODEL, dec_h, Wth, biasQ, QKV, 0, 1);
    attn_mma<true><<<gA, 128>>>(QKV, QKV + 1024, QKV + 2048, Ath, TT, 3072, 3072);
    transpose_flat<<<gFlatDD, tb>>>(Wo_s, Wth, D_MODEL, D_MODEL);
    gemm_h<<<gD, 256, G_SMEM>>>(MROWS, D_MODEL, D_MODEL, Ath, Wth, bo_s, Tm, 0, 0);
    add_ln_kernel<<<MROWS, 256>>>(dec, Tm, g1, be1, X1, Xh);

    // ---- cross-attention block ----
    transpose_head<<<gHead, tb>>>(Wq_c, Wth, D_MODEL);
    transpose_head<<<gHead, tb>>>(Wk_c, Wth + (size_t)D_MODEL * D_MODEL, D_MODEL);
    transpose_head<<<gHead, tb>>>(Wv_c, Wth + (size_t)2 * D_MODEL * D_MODEL, D_MODEL);
    gemm_h<<<gD, 256, G_SMEM>>>(MROWS, D_MODEL, D_MODEL, Xh, Wth, bq_c, Qhc, 0, 1);
    gemm_h<<<gD2, 256, G_SMEM>>>(MROWS, 2 * D_MODEL, D_MODEL, enc_h,
                                 Wth + (size_t)D_MODEL * D_MODEL, biasK, KVc, 0, 1);
    attn_mma<false><<<gA, 128>>>(Qhc, KVc, KVc + 1024, Ath, TT, 1024, 2048);
    transpose_flat<<<gFlatDD, tb>>>(Wo_c, Wth, D_MODEL, D_MODEL);
    gemm_h<<<gD, 256, G_SMEM>>>(MROWS, D_MODEL, D_MODEL, Ath, Wth, bo_c, Tm, 0, 0);
    add_ln_kernel<<<MROWS, 256>>>(X1, Tm, g2, be2, X2, Xh);

    // ---- FFN block ----
    transpose_flat<<<dim3(D_MODEL / 32, D_FF / 32), tb>>>(W1, Wth, D_MODEL, D_FF);
    gemm_h<<<gF, 256, G_SMEM>>>(MROWS, D_FF, D_MODEL, Xh, Wth, b1, Ffh, 1, 1);
    transpose_flat<<<dim3(D_FF / 32, D_MODEL / 32), tb>>>(W2, Wth, D_FF, D_MODEL);
    gemm_h<<<gD, 256, G_SMEM>>>(MROWS, D_MODEL, D_FF, Ffh, Wth, b2, Tm, 0, 0);
    add_ln_kernel<<<MROWS, 256>>>(X2, Tm, g3, be3, (float*)d_out, (__half*)nullptr);
}

// round 12
// speedup vs baseline: 5.7594x; 1.0895x over previous
#include <cuda_runtime.h>
#include <cuda_bf16.h>
#include <cuda_fp16.h>
#include <cstdint>
#include <cstddef>
#include <math.h>

#define D_MODEL 1024
#define N_HEADS 16
#define DKH     64
#define D_FF    4096
#define BB      2
#define TT      2048
#define MROWS   (BB * TT)   // 4096

__device__ float  g_Q   [MROWS * D_MODEL];
__device__ float  g_K   [MROWS * D_MODEL];
__device__ float  g_V   [MROWS * D_MODEL];
__device__ float  g_attn[MROWS * D_MODEL];
__device__ float  g_x1  [MROWS * D_MODEL];
__device__ float  g_x2  [MROWS * D_MODEL];
__device__ float  g_tmp [MROWS * D_MODEL];
__device__ float  g_ffn [MROWS * D_FF];
__device__ float  g_Wt  [D_FF * D_MODEL];          // holds Xh (fp16) + spare
__device__ __half g_wh  [16 * 1024 * 1024];        // 32MB: all transposed weights

// ======================= helpers ============================================
__device__ __forceinline__ uint32_t h2_as_u32(__half2 h) {
    union { __half2 h; uint32_t u; } cvt;
    cvt.h = h;
    return cvt.u;
}

__device__ __forceinline__ void cpa16(uint32_t dst, const void* src) {
    asm volatile("cp.async.cg.shared.global [%0], [%1], 16;\n"
                 :: "r"(dst), "l"(src) : "memory");
}
#define CP_COMMIT() asm volatile("cp.async.commit_group;\n" ::: "memory")
#define CP_WAIT(n)  asm volatile("cp.async.wait_group %0;\n" :: "n"(n) : "memory")

__device__ __forceinline__ uint32_t smem_u32(const void* p) {
    uint32_t a;
    asm("{ .reg .u64 t; cvta.to.shared.u64 t, %1; cvt.u32.u64 %0, t; }"
        : "=r"(a) : "l"(p));
    return a;
}

__device__ __forceinline__ void mma16h(float* c, uint32_t a0, uint32_t a1,
                                       uint32_t a2, uint32_t a3,
                                       uint32_t b0, uint32_t b1) {
    asm volatile(
        "mma.sync.aligned.m16n8k16.row.col.f32.f16.f16.f32 "
        "{%0,%1,%2,%3}, {%4,%5,%6,%7}, {%8,%9}, {%0,%1,%2,%3};"
        : "+f"(c[0]), "+f"(c[1]), "+f"(c[2]), "+f"(c[3])
        : "r"(a0), "r"(a1), "r"(a2), "r"(a3), "r"(b0), "r"(b1));
}

__device__ __forceinline__ void lsm4(uint32_t* r, uint32_t addr) {
    asm volatile("ldmatrix.sync.aligned.m8n8.x4.shared.b16 {%0,%1,%2,%3}, [%4];"
                 : "=r"(r[0]), "=r"(r[1]), "=r"(r[2]), "=r"(r[3]) : "r"(addr));
}

// =============== fp16 mma GEMM: C = A[M,K] @ Wt^T + bias ====================
#define G_STAGEB 30720
#define G_BOFF  20480
#define G_NSTG 3
#define G_SMEM (G_NSTG * G_STAGEB)

__global__ __launch_bounds__(256, 1)
void gemm_h(int M, int N, int K,
            const __half* __restrict__ A, const __half* __restrict__ Wt,
            const float* __restrict__ bias, void* __restrict__ C,
            int relu, int outHalf)
{
    extern __shared__ char smc[];
    const uint32_t sb = smem_u32(smc);

    const int tid = threadIdx.x;
    const int wid = tid >> 5, lid = tid & 31;
    const int g = lid >> 2, tg = lid & 3;
    const int wm = wid >> 1, wn = wid & 1;

    const int bRow = blockIdx.y * 256, bCol = blockIdx.x * 128;
    const int NT = K >> 5;

    float acc[4][8][4];
#pragma unroll
    for (int m = 0; m < 4; m++)
#pragma unroll
        for (int n = 0; n < 8; n++)
#pragma unroll
            for (int x = 0; x < 4; x++) acc[m][n][x] = 0.f;

    auto load_stage = [&](int it, int s) {
        const uint32_t base = sb + s * G_STAGEB;
#pragma unroll
        for (int j = 0; j < 4; j++) {            // A: 1024 16B chunks
            const int idx = tid + 256 * j;
            const int row = idx >> 2, c16 = idx & 3;
            cpa16(base + row * 80 + c16 * 16,
                  A + (size_t)(bRow + row) * K + it * 32 + c16 * 8);
        }
#pragma unroll
        for (int j = 0; j < 2; j++) {            // B: 512 16B chunks
            const int idx = tid + 256 * j;
            const int row = idx >> 2, c16 = idx & 3;
            cpa16(base + G_BOFF + row * 80 + c16 * 16,
                  Wt + (size_t)(bCol + row) * K + it * 32 + c16 * 8);
        }
    };

    const uint32_t aoff = (uint32_t)((wm * 64 + (lid & 7) + ((lid >> 3) & 1) * 8) * 80
                                     + (lid >> 4) * 16);
    const uint32_t boff = (uint32_t)(G_BOFF
                                     + (wn * 64 + (lid & 7) + (lid >> 4) * 8) * 80
                                     + ((lid >> 3) & 1) * 16);

    load_stage(0, 0); CP_COMMIT();
    load_stage(1, 1); CP_COMMIT();

    for (int i = 0; i < NT; i++) {
        CP_WAIT(1);
        __syncthreads();
        const int pre = i + 2;
        if (pre < NT) load_stage(pre, pre % G_NSTG);
        CP_COMMIT();

        const uint32_t buf = sb + (i % G_NSTG) * G_STAGEB;
#pragma unroll
        for (int ks = 0; ks < 2; ks++) {
            uint32_t a[4][4];
#pragma unroll
            for (int mt = 0; mt < 4; mt++)
                lsm4(a[mt], buf + aoff + mt * 16 * 80 + ks * 32);
#pragma unroll
            for (int p = 0; p < 4; p++) {
                uint32_t b[4];
                lsm4(b, buf + boff + p * 16 * 80 + ks * 32);
#pragma unroll
                for (int mt = 0; mt < 4; mt++) {
                    mma16h(acc[mt][2 * p],     a[mt][0], a[mt][1], a[mt][2],
                           a[mt][3], b[0], b[1]);
                    mma16h(acc[mt][2 * p + 1], a[mt][0], a[mt][1], a[mt][2],
                           a[mt][3], b[2], b[3]);
                }
            }
        }
    }

    float* Cf = (float*)C;
    __half* Ch = (__half*)C;
#pragma unroll
    for (int mt = 0; mt < 4; mt++) {
        const int r0 = bRow + wm * 64 + mt * 16 + g;
#pragma unroll
        for (int nt = 0; nt < 8; nt++) {
            const int col = bCol + wn * 64 + nt * 8 + 2 * tg;
            const float bi0 = bias[col], bi1 = bias[col + 1];
            float v0 = acc[mt][nt][0] + bi0, v1 = acc[mt][nt][1] + bi1;
            float v2 = acc[mt][nt][2] + bi0, v3 = acc[mt][nt][3] + bi1;
            if (relu) {
                v0 = fmaxf(v0, 0.f); v1 = fmaxf(v1, 0.f);
                v2 = fmaxf(v2, 0.f); v3 = fmaxf(v3, 0.f);
            }
            if (outHalf) {
                *(__half2*)(Ch + (size_t)r0 * N + col) = __floats2half2_rn(v0, v1);
                *(__half2*)(Ch + (size_t)(r0 + 8) * N + col) = __floats2half2_rn(v2, v3);
            } else {
                *(float2*)(Cf + (size_t)r0 * N + col) = make_float2(v0, v1);
                *(float2*)(Cf + (size_t)(r0 + 8) * N + col) = make_float2(v2, v3);
            }
        }
    }
}

// ---------------- fused weight prep (all transposes, one launch) ------------
struct PrepJob { const float* src; __half* dst; int K, R, isHead, blk0; };
struct PrepArgs { PrepJob j[12]; };

__global__ __launch_bounds__(256) void prep_weights(PrepArgs pa)
{
    __shared__ float t[32][33];
    int ji = 0;
#pragma unroll
    for (int q = 1; q < 12; q++)
        if ((int)blockIdx.x >= pa.j[q].blk0) ji = q;
    const PrepJob& J = pa.j[ji];
    const int b = blockIdx.x - J.blk0;
    const int kt = J.K >> 5;
    const int kx = b % kt, rx = b / kt;
    const int k0 = kx * 32, r0 = rx * 32;
    const int x = threadIdx.x & 31, y = threadIdx.x >> 5;

    if (J.isHead) {
#pragma unroll
        for (int jj = 0; jj < 32; jj += 8) {
            const int n = r0 + x;                 // output row = head*64+d
            const int hh = n >> 6, d = n & 63;
            t[y + jj][x] = J.src[((size_t)hh * J.K + (k0 + y + jj)) * 64 + d];
        }
    } else {
#pragma unroll
        for (int jj = 0; jj < 32; jj += 8)
            t[y + jj][x] = J.src[(size_t)(k0 + y + jj) * J.R + r0 + x];
    }
    __syncthreads();
#pragma unroll
    for (int jj = 0; jj < 32; jj += 8)
        J.dst[(size_t)(r0 + y + jj) * J.K + k0 + x] = __float2half_rn(t[x][y + jj]);
}

// ---------------- small utils ----------------------------------------------
__global__ __launch_bounds__(256) void h_copy(
    const float* __restrict__ in, __half* __restrict__ out, int n4)
{
    const int i = blockIdx.x * blockDim.x + threadIdx.x;
    if (i < n4) {
        float4 v = ((const float4*)in)[i];
        uint2 o;
        o.x = h2_as_u32(__floats2half2_rn(v.x, v.y));
        o.y = h2_as_u32(__floats2half2_rn(v.z, v.w));
        ((uint2*)out)[i] = o;
    }
}

__global__ void prep_bias(const float* a, const float* b, const float* c,
                          const float* d, const float* e,
                          float* o3, float* o2)
{
    const int i = blockIdx.x * blockDim.x + threadIdx.x;
    if (i < 1024) o3[i] = a[i];
    else if (i < 2048) o3[i] = b[i - 1024];
    else if (i < 3072) o3[i] = c[i - 2048];
    else if (i < 4096) o2[i - 3072] = d[i - 3072];
    else if (i < 5120) o2[i - 3072] = e[i - 4096];
}

// ========== flash attention: 128-query blocks, 256 thr, fp16 mma ============
#define AROW 36   // b32 words per smem row (72 halves)

template<bool CAUSAL>
__global__ __launch_bounds__(256) void attn_mma(
    const __half* __restrict__ Q, const __half* __restrict__ K,
    const __half* __restrict__ V, __half* __restrict__ O,
    int T, int ldq, int ldkv)
{
    __shared__ __align__(16) __half Qs[128 * 72];
    __shared__ __align__(16) __half Ks[64 * 72];
    __shared__ __align__(16) __half Vt[64 * 72];

    const int tid = threadIdx.x, wid = tid >> 5, lid = tid & 31;
    const int g = lid >> 2, tg = lid & 3;
    const int h = blockIdx.y, b = blockIdx.z;
    const int q0 = blockIdx.x * 128;
    const size_t qbase  = (size_t)b * T * ldq  + h * DKH;
    const size_t kvbase = (size_t)b * T * ldkv + h * DKH;
    const size_t obase  = (size_t)b * T * D_MODEL + h * DKH;

    // ---- stage Q (128 rows) ----
    for (int idx = tid; idx < 128 * 8; idx += 256) {
        const int r = idx >> 3, c8 = idx & 7;
        *(uint4*)&Qs[r * 72 + c8 * 8] =
            *(const uint4*)(Q + qbase + (size_t)(q0 + r) * ldq + c8 * 8);
    }
    __syncthreads();

    uint32_t qf[4][4];
    {
        const uint32_t* Qu = (const uint32_t*)Qs;
        const int r0 = wid * 16 + g;
#pragma unroll
        for (int kc = 0; kc < 4; kc++) {
            const int c = 8 * kc + tg;
            qf[kc][0] = Qu[r0 * AROW + c];
            qf[kc][1] = Qu[(r0 + 8) * AROW + c];
            qf[kc][2] = Qu[r0 * AROW + c + 4];
            qf[kc][3] = Qu[(r0 + 8) * AROW + c + 4];
        }
    }

    float oacc[8][4];
#pragma unroll
    for (int j = 0; j < 8; j++)
#pragma unroll
        for (int x = 0; x < 4; x++) oacc[j][x] = 0.f;
    float m0 = -1e30f, m1 = -1e30f, l0 = 0.f, l1 = 0.f;

    const int nkt = CAUSAL ? 2 * (blockIdx.x + 1) : (T / 64);
    for (int kt = 0; kt < nkt; kt++) {
        const int s0 = kt * 64;
        __syncthreads();
        for (int idx = tid; idx < 64 * 8; idx += 256) {
            const int r = idx >> 3, c8 = idx & 7;
            const size_t gaddr = kvbase + (size_t)(s0 + r) * ldkv + c8 * 8;
            *(uint4*)&Ks[r * 72 + c8 * 8] = *(const uint4*)(K + gaddr);
            uint4 vv = *(const uint4*)(V + gaddr);
            const __half* hv = (const __half*)&vv;
#pragma unroll
            for (int q = 0; q < 8; q++)
                Vt[(c8 * 8 + q) * 72 + r] = hv[q];
        }
        __syncthreads();

        // warps fully above the diagonal skip this tile's compute
        if (CAUSAL && s0 >= q0 + wid * 16 + 16) continue;

        // ---- S = Q @ K^T ----
        float sacc[8][4];
#pragma unroll
        for (int j = 0; j < 8; j++)
#pragma unroll
            for (int x = 0; x < 4; x++) sacc[j][x] = 0.f;
        {
            const uint32_t* Ku = (const uint32_t*)Ks;
#pragma unroll
            for (int j = 0; j < 8; j++) {
                const int rb = (8 * j + g) * AROW + tg;
#pragma unroll
                for (int kc = 0; kc < 4; kc++) {
                    const uint32_t b0 = Ku[rb + 8 * kc];
                    const uint32_t b1 = Ku[rb + 8 * kc + 4];
                    mma16h(sacc[j], qf[kc][0], qf[kc][1], qf[kc][2], qf[kc][3],
                           b0, b1);
                }
            }
        }
#pragma unroll
        for (int j = 0; j < 8; j++) {
            sacc[j][0] *= 0.125f; sacc[j][1] *= 0.125f;
            sacc[j][2] *= 0.125f; sacc[j][3] *= 0.125f;
        }

        if (CAUSAL && s0 + 63 >= q0 + wid * 16) {   // diagonal tile for this warp
            const int r0 = q0 + wid * 16 + g, r1 = r0 + 8;
#pragma unroll
            for (int j = 0; j < 8; j++) {
                const int c0 = s0 + 8 * j + 2 * tg, c1 = c0 + 1;
                if (c0 > r0) sacc[j][0] = -INFINITY;
                if (c1 > r0) sacc[j][1] = -INFINITY;
                if (c0 > r1) sacc[j][2] = -INFINITY;
                if (c1 > r1) sacc[j][3] = -INFINITY;
            }
        }

        float tm0 = -1e30f, tm1 = -1e30f;
#pragma unroll
        for (int j = 0; j < 8; j++) {
            tm0 = fmaxf(tm0, fmaxf(sacc[j][0], sacc[j][1]));
            tm1 = fmaxf(tm1, fmaxf(sacc[j][2], sacc[j][3]));
        }
        tm0 = fmaxf(tm0, __shfl_xor_sync(0xffffffffu, tm0, 1));
        tm0 = fmaxf(tm0, __shfl_xor_sync(0xffffffffu, tm0, 2));
        tm1 = fmaxf(tm1, __shfl_xor_sync(0xffffffffu, tm1, 1));
        tm1 = fmaxf(tm1, __shfl_xor_sync(0xffffffffu, tm1, 2));

        const float mn0 = fmaxf(m0, tm0), mn1 = fmaxf(m1, tm1);
        const float cr0 = __expf(m0 - mn0), cr1 = __expf(m1 - mn1);
        m0 = mn0; m1 = mn1;

        uint32_t ph[8][2];
        float ts0 = 0.f, ts1 = 0.f;
#pragma unroll
        for (int j = 0; j < 8; j++) {
            const float p0 = __expf(sacc[j][0] - mn0);
            const float p1 = __expf(sacc[j][1] - mn0);
            const float p2 = __expf(sacc[j][2] - mn1);
            const float p3 = __expf(sacc[j][3] - mn1);
            ts0 += p0 + p1; ts1 += p2 + p3;
            ph[j][0] = h2_as_u32(__floats2half2_rn(p0, p1));
            ph[j][1] = h2_as_u32(__floats2half2_rn(p2, p3));
        }
        ts0 += __shfl_xor_sync(0xffffffffu, ts0, 1);
        ts0 += __shfl_xor_sync(0xffffffffu, ts0, 2);
        ts1 += __shfl_xor_sync(0xffffffffu, ts1, 1);
        ts1 += __shfl_xor_sync(0xffffffffu, ts1, 2);
        l0 = l0 * cr0 + ts0;
        l1 = l1 * cr1 + ts1;

#pragma unroll
        for (int j = 0; j < 8; j++) {
            oacc[j][0] *= cr0; oacc[j][1] *= cr0;
            oacc[j][2] *= cr1; oacc[j][3] *= cr1;
        }

        // ---- O += P @ V ----
        {
            const uint32_t* Vu = (const uint32_t*)Vt;
#pragma unroll
            for (int j = 0; j < 8; j++) {
                const int rb = (8 * j + g) * AROW + tg;
#pragma unroll
                for (int kc = 0; kc < 4; kc++) {
                    const uint32_t b0 = Vu[rb + 8 * kc];
                    const uint32_t b1 = Vu[rb + 8 * kc + 4];
                    mma16h(oacc[j], ph[2 * kc][0], ph[2 * kc][1],
                           ph[2 * kc + 1][0], ph[2 * kc + 1][1], b0, b1);
                }
            }
        }
    }

    const float inv0 = 1.f / l0, inv1 = 1.f / l1;
    const int r0 = q0 + wid * 16 + g;
#pragma unroll
    for (int j = 0; j < 8; j++) {
        const int col = 8 * j + 2 * tg;
        *(__half2*)(O + obase + (size_t)r0 * D_MODEL + col) =
            __floats2half2_rn(oacc[j][0] * inv0, oacc[j][1] * inv0);
        *(__half2*)(O + obase + (size_t)(r0 + 8) * D_MODEL + col) =
            __floats2half2_rn(oacc[j][2] * inv1, oacc[j][3] * inv1);
    }
}

// ---------------- residual add + LayerNorm ----------------------------------
__inline__ __device__ float warpSum(float v) {
#pragma unroll
    for (int o = 16; o > 0; o >>= 1) v += __shfl_xor_sync(0xffffffffu, v, o);
    return v;
}

__global__ __launch_bounds__(256) void add_ln_kernel(
    const float* __restrict__ res, const float* __restrict__ y,
    const float* __restrict__ gamma, const float* __restrict__ beta,
    float* __restrict__ out, __half* __restrict__ outh)
{
    const int row = blockIdx.x;
    const int i = threadIdx.x;
    const float4 a  = ((const float4*)(res + (size_t)row * D_MODEL))[i];
    const float4 b4 = ((const float4*)(y   + (size_t)row * D_MODEL))[i];
    const float x0 = a.x + b4.x, x1 = a.y + b4.y, x2 = a.z + b4.z, x3 = a.w + b4.w;

    float s  = x0 + x1 + x2 + x3;
    float sq = x0 * x0 + x1 * x1 + x2 * x2 + x3 * x3;
    s = warpSum(s); sq = warpSum(sq);

    __shared__ float sh[2][8];
    const int w = threadIdx.x >> 5, l = threadIdx.x & 31;
    if (l == 0) { sh[0][w] = s; sh[1][w] = sq; }
    __syncthreads();
    if (threadIdx.x < 32) {
        float aa = (l < 8) ? sh[0][l] : 0.f;
        float bb = (l < 8) ? sh[1][l] : 0.f;
        aa = warpSum(aa); bb = warpSum(bb);
        if (l == 0) { sh[0][0] = aa; sh[1][0] = bb; }
    }
    __syncthreads();
    const float mean = sh[0][0] * (1.f / D_MODEL);
    const float var  = sh[1][0] * (1.f / D_MODEL) - mean * mean;
    const float rinv = rsqrtf(var + 1e-5f);

    const float4 gm = ((const float4*)gamma)[i];
    const float4 be = ((const float4*)beta)[i];
    float4 o;
    o.x = (x0 - mean) * rinv * gm.x + be.x;
    o.y = (x1 - mean) * rinv * gm.y + be.y;
    o.z = (x2 - mean) * rinv * gm.z + be.z;
    o.w = (x3 - mean) * rinv * gm.w + be.w;
    ((float4*)(out + (size_t)row * D_MODEL))[i] = o;
    if (outh) {
        uint2 oh;
        oh.x = h2_as_u32(__floats2half2_rn(o.x, o.y));
        oh.y = h2_as_u32(__floats2half2_rn(o.z, o.w));
        ((uint2*)(outh + (size_t)row * D_MODEL))[i] = oh;
    }
}

// ---------------- launch ----------------------------------------------------
extern "C" void kernel_launch(void* const* d_in, const int* in_sizes, int n_in,
                              void* d_out, int out_size)
{
    const float* dec  = (const float*)d_in[0];
    const float* enc  = (const float*)d_in[1];
    const float* Wq_s = (const float*)d_in[2];
    const float* bq_s = (const float*)d_in[3];
    const float* Wk_s = (const float*)d_in[4];
    const float* bk_s = (const float*)d_in[5];
    const float* Wv_s = (const float*)d_in[6];
    const float* bv_s = (const float*)d_in[7];
    const float* Wo_s = (const float*)d_in[8];
    const float* bo_s = (const float*)d_in[9];
    const float* Wq_c = (const float*)d_in[10];
    const float* bq_c = (const float*)d_in[11];
    const float* Wk_c = (const float*)d_in[12];
    const float* bk_c = (const float*)d_in[13];
    const float* Wv_c = (const float*)d_in[14];
    const float* bv_c = (const float*)d_in[15];
    const float* Wo_c = (const float*)d_in[16];
    const float* bo_c = (const float*)d_in[17];
    const float* W1   = (const float*)d_in[18];
    const float* b1   = (const float*)d_in[19];
    const float* W2   = (const float*)d_in[20];
    const float* b2   = (const float*)d_in[21];
    const float* g1   = (const float*)d_in[22];
    const float* be1  = (const float*)d_in[23];
    const float* g2   = (const float*)d_in[24];
    const float* be2  = (const float*)d_in[25];
    const float* g3   = (const float*)d_in[26];
    const float* be3  = (const float*)d_in[27];

    float *Qf, *Kf, *Vf, *Af, *X1, *X2, *Tm, *Fbuf, *Wtb;
    __half* Wh;
    cudaGetSymbolAddress((void**)&Qf, g_Q);
    cudaGetSymbolAddress((void**)&Kf, g_K);
    cudaGetSymbolAddress((void**)&Vf, g_V);
    cudaGetSymbolAddress((void**)&Af, g_attn);
    cudaGetSymbolAddress((void**)&X1, g_x1);
    cudaGetSymbolAddress((void**)&X2, g_x2);
    cudaGetSymbolAddress((void**)&Tm, g_tmp);
    cudaGetSymbolAddress((void**)&Fbuf, g_ffn);
    cudaGetSymbolAddress((void**)&Wtb, g_Wt);
    cudaGetSymbolAddress((void**)&Wh, g_wh);

    const size_t NE = (size_t)MROWS * D_MODEL;        // 4M
    const size_t MM = (size_t)D_MODEL * D_MODEL;      // 1M
    __half* dec_h = (__half*)Qf;
    __half* enc_h = dec_h + NE;
    __half* Qhc   = (__half*)Kf;
    __half* KVc   = (__half*)Vf;                      // ld 2048
    __half* Ath   = (__half*)Af;
    float*  biasQ = (float*)(Ath + NE);               // upper half of g_attn
    float*  biasK = biasQ + 4096;
    __half* QKV   = (__half*)Fbuf;                    // ld 3072 (24MB)
    __half* Ffh   = QKV + (size_t)MROWS * 3072;       // 16M halves -> total 28M/32M
    // weights live in g_wh (16M halves = 32MB total)
    __half* w_qkv_s = Wh;                             // 3 MM
    __half* w_o_s   = Wh + 3 * MM;                    // 1 MM
    __half* w_qkv_c = Wh + 4 * MM;                    // 3 MM
    __half* w_o_c   = Wh + 7 * MM;                    // 1 MM
    __half* w_1     = Wh + 8 * MM;                    // 4 MM
    __half* w_2     = Wh + 12 * MM;                   // 4 MM
    __half* Xh      = (__half*)Wtb;                   // 4M halves (g_Wt holds 8M)

    cudaFuncSetAttribute(gemm_h, cudaFuncAttributeMaxDynamicSharedMemorySize, G_SMEM);

    PrepArgs pa;
    auto setj = [&](int i, const float* s, __half* d, int K, int R, int ih, int b0) {
        pa.j[i] = PrepJob{s, d, K, R, ih, b0};
    };
    setj(0,  Wq_s, w_qkv_s,            1024, 1024, 1, 0);
    setj(1,  Wk_s, w_qkv_s + MM,       1024, 1024, 1, 1024);
    setj(2,  Wv_s, w_qkv_s + 2 * MM,   1024, 1024, 1, 2048);
    setj(3,  Wo_s, w_o_s,              1024, 1024, 0, 3072);
    setj(4,  Wq_c, w_qkv_c,            1024, 1024, 1, 4096);
    setj(5,  Wk_c, w_qkv_c + MM,       1024, 1024, 1, 5120);
    setj(6,  Wv_c, w_qkv_c + 2 * MM,   1024, 1024, 1, 6144);
    setj(7,  Wo_c, w_o_c,              1024, 1024, 0, 7168);
    setj(8,  W1,   w_1,                1024, 4096, 0, 8192);
    setj(9,  W2,   w_2,                4096, 1024, 0, 12288);
    setj(10, W2,   w_2,                4096, 1024, 0, 0x7fffffff);
    setj(11, W2,   w_2,                4096, 1024, 0, 0x7fffffff);

    const dim3 gD (D_MODEL / 128, MROWS / 256);
    const dim3 gD3(3 * D_MODEL / 128, MROWS / 256);
    const dim3 gD2(2 * D_MODEL / 128, MROWS / 256);
    const dim3 gF (D_FF / 128,   MROWS / 256);
    const dim3 gA(TT / 128, N_HEADS, BB);
    const int NC4 = MROWS * D_MODEL / 4;

    prep_weights<<<16384, 256>>>(pa);
    h_copy<<<(NC4 + 255) / 256, 256>>>(dec, dec_h, NC4);
    h_copy<<<(NC4 + 255) / 256, 256>>>(enc, enc_h, NC4);
    prep_bias<<<20, 256>>>(bq_s, bk_s, bv_s, bk_c, bv_c, biasQ, biasK);

    // ---- self-attention block ----
    gemm_h<<<gD3, 256, G_SMEM>>>(MROWS, 3 * D_MODEL, D_MODEL, dec_h, w_qkv_s, biasQ, QKV, 0, 1);
    attn_mma<true><<<gA, 256>>>(QKV, QKV + 1024, QKV + 2048, Ath, TT, 3072, 3072);
    gemm_h<<<gD, 256, G_SMEM>>>(MROWS, D_MODEL, D_MODEL, Ath, w_o_s, bo_s, Tm, 0, 0);
    add_ln_kernel<<<MROWS, 256>>>(dec, Tm, g1, be1, X1, Xh);

    // ---- cross-attention block ----
    gemm_h<<<gD, 256, G_SMEM>>>(MROWS, D_MODEL, D_MODEL, Xh, w_qkv_c, bq_c, Qhc, 0, 1);
    gemm_h<<<gD2, 256, G_SMEM>>>(MROWS, 2 * D_MODEL, D_MODEL, enc_h,
                                 w_qkv_c + MM, biasK, KVc, 0, 1);
    attn_mma<false><<<gA, 256>>>(Qhc, KVc, KVc + 1024, Ath, TT, 1024, 2048);
    gemm_h<<<gD, 256, G_SMEM>>>(MROWS, D_MODEL, D_MODEL, Ath, w_o_c, bo_c, Tm, 0, 0);
    add_ln_kernel<<<MROWS, 256>>>(X1, Tm, g2, be2, X2, Xh);

    // ---- FFN block ----
    gemm_h<<<gF, 256, G_SMEM>>>(MROWS, D_FF, D_MODEL, Xh, w_1, b1, Ffh, 1, 1);
    gemm_h<<<gD, 256, G_SMEM>>>(MROWS, D_MODEL, D_FF, Ffh, w_2, b2, Tm, 0, 0);
    add_ln_kernel<<<MROWS, 256>>>(X2, Tm, g3, be3, (float*)d_out, (__half*)nullptr);
}

// round 13
// speedup vs baseline: 6.1975x; 1.0761x over previous
#include <cuda_runtime.h>
#include <cuda_bf16.h>
#include <cuda_fp16.h>
#include <cstdint>
#include <cstddef>
#include <math.h>

#define D_MODEL 1024
#define N_HEADS 16
#define DKH     64
#define D_FF    4096
#define BB      2
#define TT      2048
#define MROWS   (BB * TT)   // 4096

__device__ float  g_Q   [MROWS * D_MODEL];
__device__ float  g_K   [MROWS * D_MODEL];
__device__ float  g_V   [MROWS * D_MODEL];
__device__ float  g_attn[MROWS * D_MODEL];
__device__ float  g_x1  [MROWS * D_MODEL];
__device__ float  g_x2  [MROWS * D_MODEL];
__device__ float  g_tmp [MROWS * D_MODEL];
__device__ float  g_ffn [MROWS * D_FF];
__device__ float  g_Wt  [D_FF * D_MODEL];          // holds Xh (fp16) + spare
__device__ __half g_wh  [16 * 1024 * 1024];        // 32MB: all transposed weights

// ======================= helpers ============================================
__device__ __forceinline__ uint32_t h2_as_u32(__half2 h) {
    union { __half2 h; uint32_t u; } cvt;
    cvt.h = h;
    return cvt.u;
}

__device__ __forceinline__ void cpa16(uint32_t dst, const void* src) {
    asm volatile("cp.async.cg.shared.global [%0], [%1], 16;\n"
                 :: "r"(dst), "l"(src) : "memory");
}
#define CP_COMMIT() asm volatile("cp.async.commit_group;\n" ::: "memory")
#define CP_WAIT(n)  asm volatile("cp.async.wait_group %0;\n" :: "n"(n) : "memory")

__device__ __forceinline__ uint32_t smem_u32(const void* p) {
    uint32_t a;
    asm("{ .reg .u64 t; cvta.to.shared.u64 t, %1; cvt.u32.u64 %0, t; }"
        : "=r"(a) : "l"(p));
    return a;
}

__device__ __forceinline__ void mma16h(float* c, uint32_t a0, uint32_t a1,
                                       uint32_t a2, uint32_t a3,
                                       uint32_t b0, uint32_t b1) {
    asm volatile(
        "mma.sync.aligned.m16n8k16.row.col.f32.f16.f16.f32 "
        "{%0,%1,%2,%3}, {%4,%5,%6,%7}, {%8,%9}, {%0,%1,%2,%3};"
        : "+f"(c[0]), "+f"(c[1]), "+f"(c[2]), "+f"(c[3])
        : "r"(a0), "r"(a1), "r"(a2), "r"(a3), "r"(b0), "r"(b1));
}

__device__ __forceinline__ void lsm4(uint32_t* r, uint32_t addr) {
    asm volatile("ldmatrix.sync.aligned.m8n8.x4.shared.b16 {%0,%1,%2,%3}, [%4];"
                 : "=r"(r[0]), "=r"(r[1]), "=r"(r[2]), "=r"(r[3]) : "r"(addr));
}

// =============== fp16 mma GEMM: C = A[M,K] @ Wt^T + bias ====================
// Block tile 256x128, 256 thr, warp tile 64x64. BK = 64 halves (128B rows),
// row stride 144B (conflict-free per ldmatrix phase). 3-stage cp.async.
#define G_ROWB   144
#define G_STAGEB (384 * G_ROWB)            // 55296
#define G_BOFF   (256 * G_ROWB)            // 36864
#define G_NSTG   3
#define G_SMEM   (G_NSTG * G_STAGEB)       // 165888

__global__ __launch_bounds__(256, 1)
void gemm_h(int M, int N, int K,
            const __half* __restrict__ A, const __half* __restrict__ Wt,
            const float* __restrict__ bias, void* __restrict__ C,
            int relu, int outHalf)
{
    extern __shared__ char smc[];
    const uint32_t sb = smem_u32(smc);

    const int tid = threadIdx.x;
    const int wid = tid >> 5, lid = tid & 31;
    const int g = lid >> 2, tg = lid & 3;
    const int wm = wid >> 1, wn = wid & 1;

    const int bRow = blockIdx.y * 256, bCol = blockIdx.x * 128;
    const int NT = K >> 6;                 // BK = 64 halves

    float acc[4][8][4];
#pragma unroll
    for (int m = 0; m < 4; m++)
#pragma unroll
        for (int n = 0; n < 8; n++)
#pragma unroll
            for (int x = 0; x < 4; x++) acc[m][n][x] = 0.f;

    auto load_stage = [&](int it, int s) {
        const uint32_t base = sb + s * G_STAGEB;
#pragma unroll
        for (int j = 0; j < 8; j++) {            // A: 256 rows x 128B = 2048 chunks
            const int idx = tid + 256 * j;
            const int row = idx >> 3, c16 = idx & 7;
            cpa16(base + row * G_ROWB + c16 * 16,
                  A + (size_t)(bRow + row) * K + it * 64 + c16 * 8);
        }
#pragma unroll
        for (int j = 0; j < 4; j++) {            // B: 128 rows x 128B = 1024 chunks
            const int idx = tid + 256 * j;
            const int row = idx >> 3, c16 = idx & 7;
            cpa16(base + G_BOFF + row * G_ROWB + c16 * 16,
                  Wt + (size_t)(bCol + row) * K + it * 64 + c16 * 8);
        }
    };

    const uint32_t aoff = (uint32_t)((wm * 64 + (lid & 7) + ((lid >> 3) & 1) * 8) * G_ROWB
                                     + (lid >> 4) * 16);
    const uint32_t boff = (uint32_t)(G_BOFF
                                     + (wn * 64 + (lid & 7) + (lid >> 4) * 8) * G_ROWB
                                     + ((lid >> 3) & 1) * 16);

    load_stage(0, 0); CP_COMMIT();
    load_stage(1, 1); CP_COMMIT();

    for (int i = 0; i < NT; i++) {
        CP_WAIT(1);
        __syncthreads();
        const int pre = i + 2;
        if (pre < NT) load_stage(pre, pre % G_NSTG);
        CP_COMMIT();

        const uint32_t buf = sb + (i % G_NSTG) * G_STAGEB;
#pragma unroll
        for (int ks = 0; ks < 4; ks++) {          // 4 x k16 per BK64 stage
            uint32_t a[4][4];
#pragma unroll
            for (int mt = 0; mt < 4; mt++)
                lsm4(a[mt], buf + aoff + mt * 16 * G_ROWB + ks * 32);
#pragma unroll
            for (int p = 0; p < 4; p++) {
                uint32_t b[4];
                lsm4(b, buf + boff + p * 16 * G_ROWB + ks * 32);
#pragma unroll
                for (int mt = 0; mt < 4; mt++) {
                    mma16h(acc[mt][2 * p],     a[mt][0], a[mt][1], a[mt][2],
                           a[mt][3], b[0], b[1]);
                    mma16h(acc[mt][2 * p + 1], a[mt][0], a[mt][1], a[mt][2],
                           a[mt][3], b[2], b[3]);
                }
            }
        }
    }

    float* Cf = (float*)C;
    __half* Ch = (__half*)C;
#pragma unroll
    for (int mt = 0; mt < 4; mt++) {
        const int r0 = bRow + wm * 64 + mt * 16 + g;
#pragma unroll
        for (int nt = 0; nt < 8; nt++) {
            const int col = bCol + wn * 64 + nt * 8 + 2 * tg;
            const float bi0 = bias[col], bi1 = bias[col + 1];
            float v0 = acc[mt][nt][0] + bi0, v1 = acc[mt][nt][1] + bi1;
            float v2 = acc[mt][nt][2] + bi0, v3 = acc[mt][nt][3] + bi1;
            if (relu) {
                v0 = fmaxf(v0, 0.f); v1 = fmaxf(v1, 0.f);
                v2 = fmaxf(v2, 0.f); v3 = fmaxf(v3, 0.f);
            }
            if (outHalf) {
                *(__half2*)(Ch + (size_t)r0 * N + col) = __floats2half2_rn(v0, v1);
                *(__half2*)(Ch + (size_t)(r0 + 8) * N + col) = __floats2half2_rn(v2, v3);
            } else {
                *(float2*)(Cf + (size_t)r0 * N + col) = make_float2(v0, v1);
                *(float2*)(Cf + (size_t)(r0 + 8) * N + col) = make_float2(v2, v3);
            }
        }
    }
}

// ---------------- fused weight prep (all transposes, one launch) ------------
struct PrepJob { const float* src; __half* dst; int K, R, isHead, blk0; };
struct PrepArgs { PrepJob j[12]; };

__global__ __launch_bounds__(256) void prep_weights(PrepArgs pa)
{
    __shared__ float t[32][33];
    int ji = 0;
#pragma unroll
    for (int q = 1; q < 12; q++)
        if ((int)blockIdx.x >= pa.j[q].blk0) ji = q;
    const PrepJob& J = pa.j[ji];
    const int b = blockIdx.x - J.blk0;
    const int kt = J.K >> 5;
    const int kx = b % kt, rx = b / kt;
    const int k0 = kx * 32, r0 = rx * 32;
    const int x = threadIdx.x & 31, y = threadIdx.x >> 5;

    if (J.isHead) {
#pragma unroll
        for (int jj = 0; jj < 32; jj += 8) {
            const int n = r0 + x;
            const int hh = n >> 6, d = n & 63;
            t[y + jj][x] = J.src[((size_t)hh * J.K + (k0 + y + jj)) * 64 + d];
        }
    } else {
#pragma unroll
        for (int jj = 0; jj < 32; jj += 8)
            t[y + jj][x] = J.src[(size_t)(k0 + y + jj) * J.R + r0 + x];
    }
    __syncthreads();
#pragma unroll
    for (int jj = 0; jj < 32; jj += 8)
        J.dst[(size_t)(r0 + y + jj) * J.K + k0 + x] = __float2half_rn(t[x][y + jj]);
}

// ---------------- small utils ----------------------------------------------
__global__ __launch_bounds__(256) void h_copy(
    const float* __restrict__ in, __half* __restrict__ out, int n4)
{
    const int i = blockIdx.x * blockDim.x + threadIdx.x;
    if (i < n4) {
        float4 v = ((const float4*)in)[i];
        uint2 o;
        o.x = h2_as_u32(__floats2half2_rn(v.x, v.y));
        o.y = h2_as_u32(__floats2half2_rn(v.z, v.w));
        ((uint2*)out)[i] = o;
    }
}

__global__ void prep_bias(const float* a, const float* b, const float* c,
                          const float* d, const float* e,
                          float* o3, float* o2)
{
    const int i = blockIdx.x * blockDim.x + threadIdx.x;
    if (i < 1024) o3[i] = a[i];
    else if (i < 2048) o3[i] = b[i - 1024];
    else if (i < 3072) o3[i] = c[i - 2048];
    else if (i < 4096) o2[i - 3072] = d[i - 3072];
    else if (i < 5120) o2[i - 3072] = e[i - 4096];
}

// ========== flash attention: 128-query blocks, 256 thr, fp16 mma ============
#define AROW 36   // b32 words per smem row (72 halves)

template<bool CAUSAL>
__global__ __launch_bounds__(256) void attn_mma(
    const __half* __restrict__ Q, const __half* __restrict__ K,
    const __half* __restrict__ V, __half* __restrict__ O,
    int T, int ldq, int ldkv)
{
    __shared__ __align__(16) __half Qs[128 * 72];
    __shared__ __align__(16) __half Ks[64 * 72];
    __shared__ __align__(16) __half Vt[64 * 72];

    const int tid = threadIdx.x, wid = tid >> 5, lid = tid & 31;
    const int g = lid >> 2, tg = lid & 3;
    const int h = blockIdx.y, b = blockIdx.z;
    const int q0 = blockIdx.x * 128;
    const size_t qbase  = (size_t)b * T * ldq  + h * DKH;
    const size_t kvbase = (size_t)b * T * ldkv + h * DKH;
    const size_t obase  = (size_t)b * T * D_MODEL + h * DKH;

    for (int idx = tid; idx < 128 * 8; idx += 256) {
        const int r = idx >> 3, c8 = idx & 7;
        *(uint4*)&Qs[r * 72 + c8 * 8] =
            *(const uint4*)(Q + qbase + (size_t)(q0 + r) * ldq + c8 * 8);
    }
    __syncthreads();

    uint32_t qf[4][4];
    {
        const uint32_t* Qu = (const uint32_t*)Qs;
        const int r0 = wid * 16 + g;
#pragma unroll
        for (int kc = 0; kc < 4; kc++) {
            const int c = 8 * kc + tg;
            qf[kc][0] = Qu[r0 * AROW + c];
            qf[kc][1] = Qu[(r0 + 8) * AROW + c];
            qf[kc][2] = Qu[r0 * AROW + c + 4];
            qf[kc][3] = Qu[(r0 + 8) * AROW + c + 4];
        }
    }

    float oacc[8][4];
#pragma unroll
    for (int j = 0; j < 8; j++)
#pragma unroll
        for (int x = 0; x < 4; x++) oacc[j][x] = 0.f;
    float m0 = -1e30f, m1 = -1e30f, l0 = 0.f, l1 = 0.f;

    const int nkt = CAUSAL ? 2 * (blockIdx.x + 1) : (T / 64);
    for (int kt = 0; kt < nkt; kt++) {
        const int s0 = kt * 64;
        __syncthreads();
        for (int idx = tid; idx < 64 * 8; idx += 256) {
            const int r = idx >> 3, c8 = idx & 7;
            const size_t gaddr = kvbase + (size_t)(s0 + r) * ldkv + c8 * 8;
            *(uint4*)&Ks[r * 72 + c8 * 8] = *(const uint4*)(K + gaddr);
            uint4 vv = *(const uint4*)(V + gaddr);
            const __half* hv = (const __half*)&vv;
#pragma unroll
            for (int q = 0; q < 8; q++)
                Vt[(c8 * 8 + q) * 72 + r] = hv[q];
        }
        __syncthreads();

        if (CAUSAL && s0 >= q0 + wid * 16 + 16) continue;

        float sacc[8][4];
#pragma unroll
        for (int j = 0; j < 8; j++)
#pragma unroll
            for (int x = 0; x < 4; x++) sacc[j][x] = 0.f;
        {
            const uint32_t* Ku = (const uint32_t*)Ks;
#pragma unroll
            for (int j = 0; j < 8; j++) {
                const int rb = (8 * j + g) * AROW + tg;
#pragma unroll
                for (int kc = 0; kc < 4; kc++) {
                    const uint32_t b0 = Ku[rb + 8 * kc];
                    const uint32_t b1 = Ku[rb + 8 * kc + 4];
                    mma16h(sacc[j], qf[kc][0], qf[kc][1], qf[kc][2], qf[kc][3],
                           b0, b1);
                }
            }
        }
#pragma unroll
        for (int j = 0; j < 8; j++) {
            sacc[j][0] *= 0.125f; sacc[j][1] *= 0.125f;
            sacc[j][2] *= 0.125f; sacc[j][3] *= 0.125f;
        }

        if (CAUSAL && s0 + 63 >= q0 + wid * 16) {
            const int r0 = q0 + wid * 16 + g, r1 = r0 + 8;
#pragma unroll
            for (int j = 0; j < 8; j++) {
                const int c0 = s0 + 8 * j + 2 * tg, c1 = c0 + 1;
                if (c0 > r0) sacc[j][0] = -INFINITY;
                if (c1 > r0) sacc[j][1] = -INFINITY;
                if (c0 > r1) sacc[j][2] = -INFINITY;
                if (c1 > r1) sacc[j][3] = -INFINITY;
            }
        }

        float tm0 = -1e30f, tm1 = -1e30f;
#pragma unroll
        for (int j = 0; j < 8; j++) {
            tm0 = fmaxf(tm0, fmaxf(sacc[j][0], sacc[j][1]));
            tm1 = fmaxf(tm1, fmaxf(sacc[j][2], sacc[j][3]));
        }
        tm0 = fmaxf(tm0, __shfl_xor_sync(0xffffffffu, tm0, 1));
        tm0 = fmaxf(tm0, __shfl_xor_sync(0xffffffffu, tm0, 2));
        tm1 = fmaxf(tm1, __shfl_xor_sync(0xffffffffu, tm1, 1));
        tm1 = fmaxf(tm1, __shfl_xor_sync(0xffffffffu, tm1, 2));

        const float mn0 = fmaxf(m0, tm0), mn1 = fmaxf(m1, tm1);
        const float cr0 = __expf(m0 - mn0), cr1 = __expf(m1 - mn1);
        m0 = mn0; m1 = mn1;

        uint32_t ph[8][2];
        float ts0 = 0.f, ts1 = 0.f;
#pragma unroll
        for (int j = 0; j < 8; j++) {
            const float p0 = __expf(sacc[j][0] - mn0);
            const float p1 = __expf(sacc[j][1] - mn0);
            const float p2 = __expf(sacc[j][2] - mn1);
            const float p3 = __expf(sacc[j][3] - mn1);
            ts0 += p0 + p1; ts1 += p2 + p3;
            ph[j][0] = h2_as_u32(__floats2half2_rn(p0, p1));
            ph[j][1] = h2_as_u32(__floats2half2_rn(p2, p3));
        }
        ts0 += __shfl_xor_sync(0xffffffffu, ts0, 1);
        ts0 += __shfl_xor_sync(0xffffffffu, ts0, 2);
        ts1 += __shfl_xor_sync(0xffffffffu, ts1, 1);
        ts1 += __shfl_xor_sync(0xffffffffu, ts1, 2);
        l0 = l0 * cr0 + ts0;
        l1 = l1 * cr1 + ts1;

#pragma unroll
        for (int j = 0; j < 8; j++) {
            oacc[j][0] *= cr0; oacc[j][1] *= cr0;
            oacc[j][2] *= cr1; oacc[j][3] *= cr1;
        }

        {
            const uint32_t* Vu = (const uint32_t*)Vt;
#pragma unroll
            for (int j = 0; j < 8; j++) {
                const int rb = (8 * j + g) * AROW + tg;
#pragma unroll
                for (int kc = 0; kc < 4; kc++) {
                    const uint32_t b0 = Vu[rb + 8 * kc];
                    const uint32_t b1 = Vu[rb + 8 * kc + 4];
                    mma16h(oacc[j], ph[2 * kc][0], ph[2 * kc][1],
                           ph[2 * kc + 1][0], ph[2 * kc + 1][1], b0, b1);
                }
            }
        }
    }

    const float inv0 = 1.f / l0, inv1 = 1.f / l1;
    const int r0 = q0 + wid * 16 + g;
#pragma unroll
    for (int j = 0; j < 8; j++) {
        const int col = 8 * j + 2 * tg;
        *(__half2*)(O + obase + (size_t)r0 * D_MODEL + col) =
            __floats2half2_rn(oacc[j][0] * inv0, oacc[j][1] * inv0);
        *(__half2*)(O + obase + (size_t)(r0 + 8) * D_MODEL + col) =
            __floats2half2_rn(oacc[j][2] * inv1, oacc[j][3] * inv1);
    }
}

// ---------------- residual add + LayerNorm ----------------------------------
__inline__ __device__ float warpSum(float v) {
#pragma unroll
    for (int o = 16; o > 0; o >>= 1) v += __shfl_xor_sync(0xffffffffu, v, o);
    return v;
}

__global__ __launch_bounds__(256) void add_ln_kernel(
    const float* __restrict__ res, const float* __restrict__ y,
    const float* __restrict__ gamma, const float* __restrict__ beta,
    float* __restrict__ out, __half* __restrict__ outh)
{
    const int row = blockIdx.x;
    const int i = threadIdx.x;
    const float4 a  = ((const float4*)(res + (size_t)row * D_MODEL))[i];
    const float4 b4 = ((const float4*)(y   + (size_t)row * D_MODEL))[i];
    const float x0 = a.x + b4.x, x1 = a.y + b4.y, x2 = a.z + b4.z, x3 = a.w + b4.w;

    float s  = x0 + x1 + x2 + x3;
    float sq = x0 * x0 + x1 * x1 + x2 * x2 + x3 * x3;
    s = warpSum(s); sq = warpSum(sq);

    __shared__ float sh[2][8];
    const int w = threadIdx.x >> 5, l = threadIdx.x & 31;
    if (l == 0) { sh[0][w] = s; sh[1][w] = sq; }
    __syncthreads();
    if (threadIdx.x < 32) {
        float aa = (l < 8) ? sh[0][l] : 0.f;
        float bb = (l < 8) ? sh[1][l] : 0.f;
        aa = warpSum(aa); bb = warpSum(bb);
        if (l == 0) { sh[0][0] = aa; sh[1][0] = bb; }
    }
    __syncthreads();
    const float mean = sh[0][0] * (1.f / D_MODEL);
    const float var  = sh[1][0] * (1.f / D_MODEL) - mean * mean;
    const float rinv = rsqrtf(var + 1e-5f);

    const float4 gm = ((const float4*)gamma)[i];
    const float4 be = ((const float4*)beta)[i];
    float4 o;
    o.x = (x0 - mean) * rinv * gm.x + be.x;
    o.y = (x1 - mean) * rinv * gm.y + be.y;
    o.z = (x2 - mean) * rinv * gm.z + be.z;
    o.w = (x3 - mean) * rinv * gm.w + be.w;
    ((float4*)(out + (size_t)row * D_MODEL))[i] = o;
    if (outh) {
        uint2 oh;
        oh.x = h2_as_u32(__floats2half2_rn(o.x, o.y));
        oh.y = h2_as_u32(__floats2half2_rn(o.z, o.w));
        ((uint2*)(outh + (size_t)row * D_MODEL))[i] = oh;
    }
}

// ---------------- launch ----------------------------------------------------
extern "C" void kernel_launch(void* const* d_in, const int* in_sizes, int n_in,
                              void* d_out, int out_size)
{
    const float* dec  = (const float*)d_in[0];
    const float* enc  = (const float*)d_in[1];
    const float* Wq_s = (const float*)d_in[2];
    const float* bq_s = (const float*)d_in[3];
    const float* Wk_s = (const float*)d_in[4];
    const float* bk_s = (const float*)d_in[5];
    const float* Wv_s = (const float*)d_in[6];
    const float* bv_s = (const float*)d_in[7];
    const float* Wo_s = (const float*)d_in[8];
    const float* bo_s = (const float*)d_in[9];
    const float* Wq_c = (const float*)d_in[10];
    const float* bq_c = (const float*)d_in[11];
    const float* Wk_c = (const float*)d_in[12];
    const float* bk_c = (const float*)d_in[13];
    const float* Wv_c = (const float*)d_in[14];
    const float* bv_c = (const float*)d_in[15];
    const float* Wo_c = (const float*)d_in[16];
    const float* bo_c = (const float*)d_in[17];
    const float* W1   = (const float*)d_in[18];
    const float* b1   = (const float*)d_in[19];
    const float* W2   = (const float*)d_in[20];
    const float* b2   = (const float*)d_in[21];
    const float* g1   = (const float*)d_in[22];
    const float* be1  = (const float*)d_in[23];
    const float* g2   = (const float*)d_in[24];
    const float* be2  = (const float*)d_in[25];
    const float* g3   = (const float*)d_in[26];
    const float* be3  = (const float*)d_in[27];

    float *Qf, *Kf, *Vf, *Af, *X1, *X2, *Tm, *Fbuf, *Wtb;
    __half* Wh;
    cudaGetSymbolAddress((void**)&Qf, g_Q);
    cudaGetSymbolAddress((void**)&Kf, g_K);
    cudaGetSymbolAddress((void**)&Vf, g_V);
    cudaGetSymbolAddress((void**)&Af, g_attn);
    cudaGetSymbolAddress((void**)&X1, g_x1);
    cudaGetSymbolAddress((void**)&X2, g_x2);
    cudaGetSymbolAddress((void**)&Tm, g_tmp);
    cudaGetSymbolAddress((void**)&Fbuf, g_ffn);
    cudaGetSymbolAddress((void**)&Wtb, g_Wt);
    cudaGetSymbolAddress((void**)&Wh, g_wh);

    const size_t NE = (size_t)MROWS * D_MODEL;        // 4M
    const size_t MM = (size_t)D_MODEL * D_MODEL;      // 1M
    __half* dec_h = (__half*)Qf;
    __half* enc_h = dec_h + NE;
    __half* Qhc   = (__half*)Kf;
    __half* KVc   = (__half*)Vf;                      // ld 2048
    __half* Ath   = (__half*)Af;
    float*  biasQ = (float*)(Ath + NE);
    float*  biasK = biasQ + 4096;
    __half* QKV   = (__half*)Fbuf;                    // ld 3072
    __half* Ffh   = QKV + (size_t)MROWS * 3072;
    __half* w_qkv_s = Wh;
    __half* w_o_s   = Wh + 3 * MM;
    __half* w_qkv_c = Wh + 4 * MM;
    __half* w_o_c   = Wh + 7 * MM;
    __half* w_1     = Wh + 8 * MM;
    __half* w_2     = Wh + 12 * MM;
    __half* Xh      = (__half*)Wtb;

    cudaFuncSetAttribute(gemm_h, cudaFuncAttributeMaxDynamicSharedMemorySize, G_SMEM);

    PrepArgs pa;
    auto setj = [&](int i, const float* s, __half* d, int K, int R, int ih, int b0) {
        pa.j[i] = PrepJob{s, d, K, R, ih, b0};
    };
    setj(0,  Wq_s, w_qkv_s,            1024, 1024, 1, 0);
    setj(1,  Wk_s, w_qkv_s + MM,       1024, 1024, 1, 1024);
    setj(2,  Wv_s, w_qkv_s + 2 * MM,   1024, 1024, 1, 2048);
    setj(3,  Wo_s, w_o_s,              1024, 1024, 0, 3072);
    setj(4,  Wq_c, w_qkv_c,            1024, 1024, 1, 4096);
    setj(5,  Wk_c, w_qkv_c + MM,       1024, 1024, 1, 5120);
    setj(6,  Wv_c, w_qkv_c + 2 * MM,   1024, 1024, 1, 6144);
    setj(7,  Wo_c, w_o_c,              1024, 1024, 0, 7168);
    setj(8,  W1,   w_1,                1024, 4096, 0, 8192);
    setj(9,  W2,   w_2,                4096, 1024, 0, 12288);
    setj(10, W2,   w_2,                4096, 1024, 0, 0x7fffffff);
    setj(11, W2,   w_2,                4096, 1024, 0, 0x7fffffff);

    const dim3 gD (D_MODEL / 128, MROWS / 256);
    const dim3 gD3(3 * D_MODEL / 128, MROWS / 256);
    const dim3 gD2(2 * D_MODEL / 128, MROWS / 256);
    const dim3 gF (D_FF / 128,   MROWS / 256);
    const dim3 gA(TT / 128, N_HEADS, BB);
    const int NC4 = MROWS * D_MODEL / 4;

    prep_weights<<<16384, 256>>>(pa);
    h_copy<<<(NC4 + 255) / 256, 256>>>(dec, dec_h, NC4);
    h_copy<<<(NC4 + 255) / 256, 256>>>(enc, enc_h, NC4);
    prep_bias<<<20, 256>>>(bq_s, bk_s, bv_s, bk_c, bv_c, biasQ, biasK);

    // ---- self-attention block ----
    gemm_h<<<gD3, 256, G_SMEM>>>(MROWS, 3 * D_MODEL, D_MODEL, dec_h, w_qkv_s, biasQ, QKV, 0, 1);
    attn_mma<true><<<gA, 256>>>(QKV, QKV + 1024, QKV + 2048, Ath, TT, 3072, 3072);
    gemm_h<<<gD, 256, G_SMEM>>>(MROWS, D_MODEL, D_MODEL, Ath, w_o_s, bo_s, Tm, 0, 0);
    add_ln_kernel<<<MROWS, 256>>>(dec, Tm, g1, be1, X1, Xh);

    // ---- cross-attention block ----
    gemm_h<<<gD, 256, G_SMEM>>>(MROWS, D_MODEL, D_MODEL, Xh, w_qkv_c, bq_c, Qhc, 0, 1);
    gemm_h<<<gD2, 256, G_SMEM>>>(MROWS, 2 * D_MODEL, D_MODEL, enc_h,
                                 w_qkv_c + MM, biasK, KVc, 0, 1);
    attn_mma<false><<<gA, 256>>>(Qhc, KVc, KVc + 1024, Ath, TT, 1024, 2048);
    gemm_h<<<gD, 256, G_SMEM>>>(MROWS, D_MODEL, D_MODEL, Ath, w_o_c, bo_c, Tm, 0, 0);
    add_ln_kernel<<<MROWS, 256>>>(X1, Tm, g2, be2, X2, Xh);

    // ---- FFN block ----
    gemm_h<<<gF, 256, G_SMEM>>>(MROWS, D_FF, D_MODEL, Xh, w_1, b1, Ffh, 1, 1);
    gemm_h<<<gD, 256, G_SMEM>>>(MROWS, D_MODEL, D_FF, Ffh, w_2, b2, Tm, 0, 0);
    add_ln_kernel<<<MROWS, 256>>>(X2, Tm, g3, be3, (float*)d_out, (__half*)nullptr);
}

// round 14
// speedup vs baseline: 6.4005x; 1.0328x over previous
#include <cuda_runtime.h>
#include <cuda_bf16.h>
#include <cuda_fp16.h>
#include <cstdint>
#include <cstddef>
#include <math.h>

#define D_MODEL 1024
#define N_HEADS 16
#define DKH     64
#define D_FF    4096
#define BB      2
#define TT      2048
#define MROWS   (BB * TT)   // 4096

__device__ float  g_Q   [MROWS * D_MODEL];
__device__ float  g_K   [MROWS * D_MODEL];
__device__ float  g_V   [MROWS * D_MODEL];
__device__ float  g_attn[MROWS * D_MODEL];
__device__ float  g_x1  [MROWS * D_MODEL];
__device__ float  g_x2  [MROWS * D_MODEL];
__device__ float  g_tmp [MROWS * D_MODEL];
__device__ float  g_ffn [MROWS * D_FF];
__device__ float  g_Wt  [D_FF * D_MODEL];          // holds Xh (fp16) + spare
__device__ __half g_wh  [16 * 1024 * 1024];        // 32MB: all transposed weights

// ======================= helpers ============================================
__device__ __forceinline__ uint32_t h2_as_u32(__half2 h) {
    union { __half2 h; uint32_t u; } cvt;
    cvt.h = h;
    return cvt.u;
}

__device__ __forceinline__ void cpa16(uint32_t dst, const void* src) {
    asm volatile("cp.async.cg.shared.global [%0], [%1], 16;\n"
                 :: "r"(dst), "l"(src) : "memory");
}
#define CP_COMMIT() asm volatile("cp.async.commit_group;\n" ::: "memory")
#define CP_WAIT(n)  asm volatile("cp.async.wait_group %0;\n" :: "n"(n) : "memory")

__device__ __forceinline__ uint32_t smem_u32(const void* p) {
    uint32_t a;
    asm("{ .reg .u64 t; cvta.to.shared.u64 t, %1; cvt.u32.u64 %0, t; }"
        : "=r"(a) : "l"(p));
    return a;
}

__device__ __forceinline__ void mma16h(float* c, uint32_t a0, uint32_t a1,
                                       uint32_t a2, uint32_t a3,
                                       uint32_t b0, uint32_t b1) {
    asm volatile(
        "mma.sync.aligned.m16n8k16.row.col.f32.f16.f16.f32 "
        "{%0,%1,%2,%3}, {%4,%5,%6,%7}, {%8,%9}, {%0,%1,%2,%3};"
        : "+f"(c[0]), "+f"(c[1]), "+f"(c[2]), "+f"(c[3])
        : "r"(a0), "r"(a1), "r"(a2), "r"(a3), "r"(b0), "r"(b1));
}

__device__ __forceinline__ void lsm4(uint32_t* r, uint32_t addr) {
    asm volatile("ldmatrix.sync.aligned.m8n8.x4.shared.b16 {%0,%1,%2,%3}, [%4];"
                 : "=r"(r[0]), "=r"(r[1]), "=r"(r[2]), "=r"(r[3]) : "r"(addr));
}

// =============== fp16 mma GEMM: C = A[M,K] @ Wt^T + bias ====================
// Block tile 128x128, 256 thr (8 warps, warp tile 32x64), BK = 64 halves.
// Row stride 144B (conflict-free per ldmatrix phase). 3-stage cp.async.
// 110.6KB smem + <=128 regs -> 2 CTAs/SM (4 warps/SMSP for latency hiding).
#define G_ROWB   144
#define G_STAGEB (256 * G_ROWB)            // 36864
#define G_BOFF   (128 * G_ROWB)            // 18432
#define G_NSTG   3
#define G_SMEM   (G_NSTG * G_STAGEB)       // 110592

__global__ __launch_bounds__(256, 2)
void gemm_h(int M, int N, int K,
            const __half* __restrict__ A, const __half* __restrict__ Wt,
            const float* __restrict__ bias, void* __restrict__ C,
            int relu, int outHalf)
{
    extern __shared__ char smc[];
    const uint32_t sb = smem_u32(smc);

    const int tid = threadIdx.x;
    const int wid = tid >> 5, lid = tid & 31;
    const int g = lid >> 2, tg = lid & 3;
    const int wm = wid >> 1, wn = wid & 1;   // 4 x 2 warp grid, warp tile 32x64

    const int bRow = blockIdx.y * 128, bCol = blockIdx.x * 128;
    const int NT = K >> 6;                   // BK = 64 halves

    float acc[2][8][4];
#pragma unroll
    for (int m = 0; m < 2; m++)
#pragma unroll
        for (int n = 0; n < 8; n++)
#pragma unroll
            for (int x = 0; x < 4; x++) acc[m][n][x] = 0.f;

    auto load_stage = [&](int it, int s) {
        const uint32_t base = sb + s * G_STAGEB;
#pragma unroll
        for (int j = 0; j < 4; j++) {        // A: 128 rows x 8 chunks = 1024
            const int idx = tid + 256 * j;
            const int row = idx >> 3, c16 = idx & 7;
            cpa16(base + row * G_ROWB + c16 * 16,
                  A + (size_t)(bRow + row) * K + it * 64 + c16 * 8);
        }
#pragma unroll
        for (int j = 0; j < 4; j++) {        // B: 128 rows x 8 chunks = 1024
            const int idx = tid + 256 * j;
            const int row = idx >> 3, c16 = idx & 7;
            cpa16(base + G_BOFF + row * G_ROWB + c16 * 16,
                  Wt + (size_t)(bCol + row) * K + it * 64 + c16 * 8);
        }
    };

    const uint32_t aoff = (uint32_t)((wm * 32 + (lid & 7) + ((lid >> 3) & 1) * 8) * G_ROWB
                                     + (lid >> 4) * 16);
    const uint32_t boff = (uint32_t)(G_BOFF
                                     + (wn * 64 + (lid & 7) + (lid >> 4) * 8) * G_ROWB
                                     + ((lid >> 3) & 1) * 16);

    load_stage(0, 0); CP_COMMIT();
    load_stage(1, 1); CP_COMMIT();

    for (int i = 0; i < NT; i++) {
        CP_WAIT(1);
        __syncthreads();
        const int pre = i + 2;
        if (pre < NT) load_stage(pre, pre % G_NSTG);
        CP_COMMIT();

        const uint32_t buf = sb + (i % G_NSTG) * G_STAGEB;
#pragma unroll
        for (int ks = 0; ks < 4; ks++) {      // 4 x k16 per BK64 stage
            uint32_t a[2][4];
#pragma unroll
            for (int mt = 0; mt < 2; mt++)
                lsm4(a[mt], buf + aoff + mt * 16 * G_ROWB + ks * 32);
#pragma unroll
            for (int p = 0; p < 4; p++) {
                uint32_t b[4];
                lsm4(b, buf + boff + p * 16 * G_ROWB + ks * 32);
#pragma unroll
                for (int mt = 0; mt < 2; mt++) {
                    mma16h(acc[mt][2 * p],     a[mt][0], a[mt][1], a[mt][2],
                           a[mt][3], b[0], b[1]);
                    mma16h(acc[mt][2 * p + 1], a[mt][0], a[mt][1], a[mt][2],
                           a[mt][3], b[2], b[3]);
                }
            }
        }
    }

    float* Cf = (float*)C;
    __half* Ch = (__half*)C;
#pragma unroll
    for (int mt = 0; mt < 2; mt++) {
        const int r0 = bRow + wm * 32 + mt * 16 + g;
#pragma unroll
        for (int nt = 0; nt < 8; nt++) {
            const int col = bCol + wn * 64 + nt * 8 + 2 * tg;
            const float bi0 = bias[col], bi1 = bias[col + 1];
            float v0 = acc[mt][nt][0] + bi0, v1 = acc[mt][nt][1] + bi1;
            float v2 = acc[mt][nt][2] + bi0, v3 = acc[mt][nt][3] + bi1;
            if (relu) {
                v0 = fmaxf(v0, 0.f); v1 = fmaxf(v1, 0.f);
                v2 = fmaxf(v2, 0.f); v3 = fmaxf(v3, 0.f);
            }
            if (outHalf) {
                *(__half2*)(Ch + (size_t)r0 * N + col) = __floats2half2_rn(v0, v1);
                *(__half2*)(Ch + (size_t)(r0 + 8) * N + col) = __floats2half2_rn(v2, v3);
            } else {
                *(float2*)(Cf + (size_t)r0 * N + col) = make_float2(v0, v1);
                *(float2*)(Cf + (size_t)(r0 + 8) * N + col) = make_float2(v2, v3);
            }
        }
    }
}

// ---------------- fused weight prep (all transposes, one launch) ------------
struct PrepJob { const float* src; __half* dst; int K, R, isHead, blk0; };
struct PrepArgs { PrepJob j[12]; };

__global__ __launch_bounds__(256) void prep_weights(PrepArgs pa)
{
    __shared__ float t[32][33];
    int ji = 0;
#pragma unroll
    for (int q = 1; q < 12; q++)
        if ((int)blockIdx.x >= pa.j[q].blk0) ji = q;
    const PrepJob& J = pa.j[ji];
    const int b = blockIdx.x - J.blk0;
    const int kt = J.K >> 5;
    const int kx = b % kt, rx = b / kt;
    const int k0 = kx * 32, r0 = rx * 32;
    const int x = threadIdx.x & 31, y = threadIdx.x >> 5;

    if (J.isHead) {
#pragma unroll
        for (int jj = 0; jj < 32; jj += 8) {
            const int n = r0 + x;
            const int hh = n >> 6, d = n & 63;
            t[y + jj][x] = J.src[((size_t)hh * J.K + (k0 + y + jj)) * 64 + d];
        }
    } else {
#pragma unroll
        for (int jj = 0; jj < 32; jj += 8)
            t[y + jj][x] = J.src[(size_t)(k0 + y + jj) * J.R + r0 + x];
    }
    __syncthreads();
#pragma unroll
    for (int jj = 0; jj < 32; jj += 8)
        J.dst[(size_t)(r0 + y + jj) * J.K + k0 + x] = __float2half_rn(t[x][y + jj]);
}

// ---------------- small utils ----------------------------------------------
__global__ __launch_bounds__(256) void h_copy(
    const float* __restrict__ in, __half* __restrict__ out, int n4)
{
    const int i = blockIdx.x * blockDim.x + threadIdx.x;
    if (i < n4) {
        float4 v = ((const float4*)in)[i];
        uint2 o;
        o.x = h2_as_u32(__floats2half2_rn(v.x, v.y));
        o.y = h2_as_u32(__floats2half2_rn(v.z, v.w));
        ((uint2*)out)[i] = o;
    }
}

__global__ void prep_bias(const float* a, const float* b, const float* c,
                          const float* d, const float* e,
                          float* o3, float* o2)
{
    const int i = blockIdx.x * blockDim.x + threadIdx.x;
    if (i < 1024) o3[i] = a[i];
    else if (i < 2048) o3[i] = b[i - 1024];
    else if (i < 3072) o3[i] = c[i - 2048];
    else if (i < 4096) o2[i - 3072] = d[i - 3072];
    else if (i < 5120) o2[i - 3072] = e[i - 4096];
}

// ========== flash attention: 128-query blocks, 256 thr, fp16 mma ============
#define AROW 36   // b32 words per smem row (72 halves)

template<bool CAUSAL>
__global__ __launch_bounds__(256) void attn_mma(
    const __half* __restrict__ Q, const __half* __restrict__ K,
    const __half* __restrict__ V, __half* __restrict__ O,
    int T, int ldq, int ldkv)
{
    __shared__ __align__(16) __half Qs[128 * 72];
    __shared__ __align__(16) __half Ks[64 * 72];
    __shared__ __align__(16) __half Vt[64 * 72];

    const int tid = threadIdx.x, wid = tid >> 5, lid = tid & 31;
    const int g = lid >> 2, tg = lid & 3;
    const int h = blockIdx.y, b = blockIdx.z;
    const int q0 = blockIdx.x * 128;
    const size_t qbase  = (size_t)b * T * ldq  + h * DKH;
    const size_t kvbase = (size_t)b * T * ldkv + h * DKH;
    const size_t obase  = (size_t)b * T * D_MODEL + h * DKH;

    for (int idx = tid; idx < 128 * 8; idx += 256) {
        const int r = idx >> 3, c8 = idx & 7;
        *(uint4*)&Qs[r * 72 + c8 * 8] =
            *(const uint4*)(Q + qbase + (size_t)(q0 + r) * ldq + c8 * 8);
    }
    __syncthreads();

    uint32_t qf[4][4];
    {
        const uint32_t* Qu = (const uint32_t*)Qs;
        const int r0 = wid * 16 + g;
#pragma unroll
        for (int kc = 0; kc < 4; kc++) {
            const int c = 8 * kc + tg;
            qf[kc][0] = Qu[r0 * AROW + c];
            qf[kc][1] = Qu[(r0 + 8) * AROW + c];
            qf[kc][2] = Qu[r0 * AROW + c + 4];
            qf[kc][3] = Qu[(r0 + 8) * AROW + c + 4];
        }
    }

    float oacc[8][4];
#pragma unroll
    for (int j = 0; j < 8; j++)
#pragma unroll
        for (int x = 0; x < 4; x++) oacc[j][x] = 0.f;
    float m0 = -1e30f, m1 = -1e30f, l0 = 0.f, l1 = 0.f;

    const int nkt = CAUSAL ? 2 * (blockIdx.x + 1) : (T / 64);
    for (int kt = 0; kt < nkt; kt++) {
        const int s0 = kt * 64;
        __syncthreads();
        for (int idx = tid; idx < 64 * 8; idx += 256) {
            const int r = idx >> 3, c8 = idx & 7;
            const size_t gaddr = kvbase + (size_t)(s0 + r) * ldkv + c8 * 8;
            *(uint4*)&Ks[r * 72 + c8 * 8] = *(const uint4*)(K + gaddr);
            uint4 vv = *(const uint4*)(V + gaddr);
            const __half* hv = (const __half*)&vv;
#pragma unroll
            for (int q = 0; q < 8; q++)
                Vt[(c8 * 8 + q) * 72 + r] = hv[q];
        }
        __syncthreads();

        if (CAUSAL && s0 >= q0 + wid * 16 + 16) continue;

        float sacc[8][4];
#pragma unroll
        for (int j = 0; j < 8; j++)
#pragma unroll
            for (int x = 0; x < 4; x++) sacc[j][x] = 0.f;
        {
            const uint32_t* Ku = (const uint32_t*)Ks;
#pragma unroll
            for (int j = 0; j < 8; j++) {
                const int rb = (8 * j + g) * AROW + tg;
#pragma unroll
                for (int kc = 0; kc < 4; kc++) {
                    const uint32_t b0 = Ku[rb + 8 * kc];
                    const uint32_t b1 = Ku[rb + 8 * kc + 4];
                    mma16h(sacc[j], qf[kc][0], qf[kc][1], qf[kc][2], qf[kc][3],
                           b0, b1);
                }
            }
        }
#pragma unroll
        for (int j = 0; j < 8; j++) {
            sacc[j][0] *= 0.125f; sacc[j][1] *= 0.125f;
            sacc[j][2] *= 0.125f; sacc[j][3] *= 0.125f;
        }

        if (CAUSAL && s0 + 63 >= q0 + wid * 16) {
            const int r0 = q0 + wid * 16 + g, r1 = r0 + 8;
#pragma unroll
            for (int j = 0; j < 8; j++) {
                const int c0 = s0 + 8 * j + 2 * tg, c1 = c0 + 1;
                if (c0 > r0) sacc[j][0] = -INFINITY;
                if (c1 > r0) sacc[j][1] = -INFINITY;
                if (c0 > r1) sacc[j][2] = -INFINITY;
                if (c1 > r1) sacc[j][3] = -INFINITY;
            }
        }

        float tm0 = -1e30f, tm1 = -1e30f;
#pragma unroll
        for (int j = 0; j < 8; j++) {
            tm0 = fmaxf(tm0, fmaxf(sacc[j][0], sacc[j][1]));
            tm1 = fmaxf(tm1, fmaxf(sacc[j][2], sacc[j][3]));
        }
        tm0 = fmaxf(tm0, __shfl_xor_sync(0xffffffffu, tm0, 1));
        tm0 = fmaxf(tm0, __shfl_xor_sync(0xffffffffu, tm0, 2));
        tm1 = fmaxf(tm1, __shfl_xor_sync(0xffffffffu, tm1, 1));
        tm1 = fmaxf(tm1, __shfl_xor_sync(0xffffffffu, tm1, 2));

        const float mn0 = fmaxf(m0, tm0), mn1 = fmaxf(m1, tm1);
        const float cr0 = __expf(m0 - mn0), cr1 = __expf(m1 - mn1);
        m0 = mn0; m1 = mn1;

        uint32_t ph[8][2];
        float ts0 = 0.f, ts1 = 0.f;
#pragma unroll
        for (int j = 0; j < 8; j++) {
            const float p0 = __expf(sacc[j][0] - mn0);
            const float p1 = __expf(sacc[j][1] - mn0);
            const float p2 = __expf(sacc[j][2] - mn1);
            const float p3 = __expf(sacc[j][3] - mn1);
            ts0 += p0 + p1; ts1 += p2 + p3;
            ph[j][0] = h2_as_u32(__floats2half2_rn(p0, p1));
            ph[j][1] = h2_as_u32(__floats2half2_rn(p2, p3));
        }
        ts0 += __shfl_xor_sync(0xffffffffu, ts0, 1);
        ts0 += __shfl_xor_sync(0xffffffffu, ts0, 2);
        ts1 += __shfl_xor_sync(0xffffffffu, ts1, 1);
        ts1 += __shfl_xor_sync(0xffffffffu, ts1, 2);
        l0 = l0 * cr0 + ts0;
        l1 = l1 * cr1 + ts1;

#pragma unroll
        for (int j = 0; j < 8; j++) {
            oacc[j][0] *= cr0; oacc[j][1] *= cr0;
            oacc[j][2] *= cr1; oacc[j][3] *= cr1;
        }

        {
            const uint32_t* Vu = (const uint32_t*)Vt;
#pragma unroll
            for (int j = 0; j < 8; j++) {
                const int rb = (8 * j + g) * AROW + tg;
#pragma unroll
                for (int kc = 0; kc < 4; kc++) {
                    const uint32_t b0 = Vu[rb + 8 * kc];
                    const uint32_t b1 = Vu[rb + 8 * kc + 4];
                    mma16h(oacc[j], ph[2 * kc][0], ph[2 * kc][1],
                           ph[2 * kc + 1][0], ph[2 * kc + 1][1], b0, b1);
                }
            }
        }
    }

    const float inv0 = 1.f / l0, inv1 = 1.f / l1;
    const int r0 = q0 + wid * 16 + g;
#pragma unroll
    for (int j = 0; j < 8; j++) {
        const int col = 8 * j + 2 * tg;
        *(__half2*)(O + obase + (size_t)r0 * D_MODEL + col) =
            __floats2half2_rn(oacc[j][0] * inv0, oacc[j][1] * inv0);
        *(__half2*)(O + obase + (size_t)(r0 + 8) * D_MODEL + col) =
            __floats2half2_rn(oacc[j][2] * inv1, oacc[j][3] * inv1);
    }
}

// ---------------- residual add + LayerNorm ----------------------------------
__inline__ __device__ float warpSum(float v) {
#pragma unroll
    for (int o = 16; o > 0; o >>= 1) v += __shfl_xor_sync(0xffffffffu, v, o);
    return v;
}

__global__ __launch_bounds__(256) void add_ln_kernel(
    const float* __restrict__ res, const float* __restrict__ y,
    const float* __restrict__ gamma, const float* __restrict__ beta,
    float* __restrict__ out, __half* __restrict__ outh)
{
    const int row = blockIdx.x;
    const int i = threadIdx.x;
    const float4 a  = ((const float4*)(res + (size_t)row * D_MODEL))[i];
    const float4 b4 = ((const float4*)(y   + (size_t)row * D_MODEL))[i];
    const float x0 = a.x + b4.x, x1 = a.y + b4.y, x2 = a.z + b4.z, x3 = a.w + b4.w;

    float s  = x0 + x1 + x2 + x3;
    float sq = x0 * x0 + x1 * x1 + x2 * x2 + x3 * x3;
    s = warpSum(s); sq = warpSum(sq);

    __shared__ float sh[2][8];
    const int w = threadIdx.x >> 5, l = threadIdx.x & 31;
    if (l == 0) { sh[0][w] = s; sh[1][w] = sq; }
    __syncthreads();
    if (threadIdx.x < 32) {
        float aa = (l < 8) ? sh[0][l] : 0.f;
        float bb = (l < 8) ? sh[1][l] : 0.f;
        aa = warpSum(aa); bb = warpSum(bb);
        if (l == 0) { sh[0][0] = aa; sh[1][0] = bb; }
    }
    __syncthreads();
    const float mean = sh[0][0] * (1.f / D_MODEL);
    const float var  = sh[1][0] * (1.f / D_MODEL) - mean * mean;
    const float rinv = rsqrtf(var + 1e-5f);

    const float4 gm = ((const float4*)gamma)[i];
    const float4 be = ((const float4*)beta)[i];
    float4 o;
    o.x = (x0 - mean) * rinv * gm.x + be.x;
    o.y = (x1 - mean) * rinv * gm.y + be.y;
    o.z = (x2 - mean) * rinv * gm.z + be.z;
    o.w = (x3 - mean) * rinv * gm.w + be.w;
    ((float4*)(out + (size_t)row * D_MODEL))[i] = o;
    if (outh) {
        uint2 oh;
        oh.x = h2_as_u32(__floats2half2_rn(o.x, o.y));
        oh.y = h2_as_u32(__floats2half2_rn(o.z, o.w));
        ((uint2*)(outh + (size_t)row * D_MODEL))[i] = oh;
    }
}

// ---------------- launch ----------------------------------------------------
extern "C" void kernel_launch(void* const* d_in, const int* in_sizes, int n_in,
                              void* d_out, int out_size)
{
    const float* dec  = (const float*)d_in[0];
    const float* enc  = (const float*)d_in[1];
    const float* Wq_s = (const float*)d_in[2];
    const float* bq_s = (const float*)d_in[3];
    const float* Wk_s = (const float*)d_in[4];
    const float* bk_s = (const float*)d_in[5];
    const float* Wv_s = (const float*)d_in[6];
    const float* bv_s = (const float*)d_in[7];
    const float* Wo_s = (const float*)d_in[8];
    const float* bo_s = (const float*)d_in[9];
    const float* Wq_c = (const float*)d_in[10];
    const float* bq_c = (const float*)d_in[11];
    const float* Wk_c = (const float*)d_in[12];
    const float* bk_c = (const float*)d_in[13];
    const float* Wv_c = (const float*)d_in[14];
    const float* bv_c = (const float*)d_in[15];
    const float* Wo_c = (const float*)d_in[16];
    const float* bo_c = (const float*)d_in[17];
    const float* W1   = (const float*)d_in[18];
    const float* b1   = (const float*)d_in[19];
    const float* W2   = (const float*)d_in[20];
    const float* b2   = (const float*)d_in[21];
    const float* g1   = (const float*)d_in[22];
    const float* be1  = (const float*)d_in[23];
    const float* g2   = (const float*)d_in[24];
    const float* be2  = (const float*)d_in[25];
    const float* g3   = (const float*)d_in[26];
    const float* be3  = (const float*)d_in[27];

    float *Qf, *Kf, *Vf, *Af, *X1, *X2, *Tm, *Fbuf, *Wtb;
    __half* Wh;
    cudaGetSymbolAddress((void**)&Qf, g_Q);
    cudaGetSymbolAddress((void**)&Kf, g_K);
    cudaGetSymbolAddress((void**)&Vf, g_V);
    cudaGetSymbolAddress((void**)&Af, g_attn);
    cudaGetSymbolAddress((void**)&X1, g_x1);
    cudaGetSymbolAddress((void**)&X2, g_x2);
    cudaGetSymbolAddress((void**)&Tm, g_tmp);
    cudaGetSymbolAddress((void**)&Fbuf, g_ffn);
    cudaGetSymbolAddress((void**)&Wtb, g_Wt);
    cudaGetSymbolAddress((void**)&Wh, g_wh);

    const size_t NE = (size_t)MROWS * D_MODEL;        // 4M
    const size_t MM = (size_t)D_MODEL * D_MODEL;      // 1M
    __half* dec_h = (__half*)Qf;
    __half* enc_h = dec_h + NE;
    __half* Qhc   = (__half*)Kf;
    __half* KVc   = (__half*)Vf;                      // ld 2048
    __half* Ath   = (__half*)Af;
    float*  biasQ = (float*)(Ath + NE);
    float*  biasK = biasQ + 4096;
    __half* QKV   = (__half*)Fbuf;                    // ld 3072
    __half* Ffh   = QKV + (size_t)MROWS * 3072;
    __half* w_qkv_s = Wh;
    __half* w_o_s   = Wh + 3 * MM;
    __half* w_qkv_c = Wh + 4 * MM;
    __half* w_o_c   = Wh + 7 * MM;
    __half* w_1     = Wh + 8 * MM;
    __half* w_2     = Wh + 12 * MM;
    __half* Xh      = (__half*)Wtb;

    cudaFuncSetAttribute(gemm_h, cudaFuncAttributeMaxDynamicSharedMemorySize, G_SMEM);

    PrepArgs pa;
    auto setj = [&](int i, const float* s, __half* d, int K, int R, int ih, int b0) {
        pa.j[i] = PrepJob{s, d, K, R, ih, b0};
    };
    setj(0,  Wq_s, w_qkv_s,            1024, 1024, 1, 0);
    setj(1,  Wk_s, w_qkv_s + MM,       1024, 1024, 1, 1024);
    setj(2,  Wv_s, w_qkv_s + 2 * MM,   1024, 1024, 1, 2048);
    setj(3,  Wo_s, w_o_s,              1024, 1024, 0, 3072);
    setj(4,  Wq_c, w_qkv_c,            1024, 1024, 1, 4096);
    setj(5,  Wk_c, w_qkv_c + MM,       1024, 1024, 1, 5120);
    setj(6,  Wv_c, w_qkv_c + 2 * MM,   1024, 1024, 1, 6144);
    setj(7,  Wo_c, w_o_c,              1024, 1024, 0, 7168);
    setj(8,  W1,   w_1,                1024, 4096, 0, 8192);
    setj(9,  W2,   w_2,                4096, 1024, 0, 12288);
    setj(10, W2,   w_2,                4096, 1024, 0, 0x7fffffff);
    setj(11, W2,   w_2,                4096, 1024, 0, 0x7fffffff);

    const dim3 gD (D_MODEL / 128, MROWS / 128);        // (8, 32)
    const dim3 gD3(3 * D_MODEL / 128, MROWS / 128);    // (24, 32)
    const dim3 gD2(2 * D_MODEL / 128, MROWS / 128);    // (16, 32)
    const dim3 gF (D_FF / 128,   MROWS / 128);         // (32, 32)
    const dim3 gA(TT / 128, N_HEADS, BB);
    const int NC4 = MROWS * D_MODEL / 4;

    prep_weights<<<16384, 256>>>(pa);
    h_copy<<<(NC4 + 255) / 256, 256>>>(dec, dec_h, NC4);
    h_copy<<<(NC4 + 255) / 256, 256>>>(enc, enc_h, NC4);
    prep_bias<<<20, 256>>>(bq_s, bk_s, bv_s, bk_c, bv_c, biasQ, biasK);

    // ---- self-attention block ----
    gemm_h<<<gD3, 256, G_SMEM>>>(MROWS, 3 * D_MODEL, D_MODEL, dec_h, w_qkv_s, biasQ, QKV, 0, 1);
    attn_mma<true><<<gA, 256>>>(QKV, QKV + 1024, QKV + 2048, Ath, TT, 3072, 3072);
    gemm_h<<<gD, 256, G_SMEM>>>(MROWS, D_MODEL, D_MODEL, Ath, w_o_s, bo_s, Tm, 0, 0);
    add_ln_kernel<<<MROWS, 256>>>(dec, Tm, g1, be1, X1, Xh);

    // ---- cross-attention block ----
    gemm_h<<<gD, 256, G_SMEM>>>(MROWS, D_MODEL, D_MODEL, Xh, w_qkv_c, bq_c, Qhc, 0, 1);
    gemm_h<<<gD2, 256, G_SMEM>>>(MROWS, 2 * D_MODEL, D_MODEL, enc_h,
                                 w_qkv_c + MM, biasK, KVc, 0, 1);
    attn_mma<false><<<gA, 256>>>(Qhc, KVc, KVc + 1024, Ath, TT, 1024, 2048);
    gemm_h<<<gD, 256, G_SMEM>>>(MROWS, D_MODEL, D_MODEL, Ath, w_o_c, bo_c, Tm, 0, 0);
    add_ln_kernel<<<MROWS, 256>>>(X1, Tm, g2, be2, X2, Xh);

    // ---- FFN block ----
    gemm_h<<<gF, 256, G_SMEM>>>(MROWS, D_FF, D_MODEL, Xh, w_1, b1, Ffh, 1, 1);
    gemm_h<<<gD, 256, G_SMEM>>>(MROWS, D_MODEL, D_FF, Ffh, w_2, b2, Tm, 0, 0);
    add_ln_kernel<<<MROWS, 256>>>(X2, Tm, g3, be3, (float*)d_out, (__half*)nullptr);
}